// round 4
// baseline (speedup 1.0000x reference)
#include <cuda_runtime.h>
#include <cuda_bf16.h>
#include <cstdint>
#include <cstddef>

// Problem constants: B=4, T=1024, D=1024, H=16, DH=64
#define MB ((size_t)1 << 20)

// ---------------------------------------------------------------------------
// Static device heap (no runtime allocation). Offsets in bytes.
// ---------------------------------------------------------------------------
#define OFF_XHI   (0 * MB)
#define OFF_XLO   (8 * MB)
#define OFF_WQTHI (16 * MB)
#define OFF_WQTLO (18 * MB)
#define OFF_WKTHI (20 * MB)
#define OFF_WKTLO (22 * MB)
#define OFF_WOTHI (24 * MB)
#define OFF_WOTLO (26 * MB)
#define OFF_WVTHI (28 * MB)
#define OFF_WVTLO (28 * MB + 131072)
#define OFF_QHI   (29 * MB)
#define OFF_QLO   (37 * MB)
#define OFF_KHI   (45 * MB)
#define OFF_KLO   (53 * MB)
#define OFF_VTHI  (61 * MB)
#define OFF_VTLO  (61 * MB + 524288)
#define OFF_CHI   (62 * MB)
#define OFF_CLO   (70 * MB)
#define OFF_S     (78 * MB)          // raw scores fp32 [bh,q,k]  256 MB
#define OFF_PHI   (334 * MB)         // probs bf16 hi             128 MB
#define OFF_PLO   (462 * MB)
#define HEAP_BYTES (590 * MB)

__device__ char g_heap[HEAP_BYTES];

// ---------------------------------------------------------------------------
// PTX helpers (Ampere-compatible: ldmatrix / mma.sync / cp.async)
// ---------------------------------------------------------------------------
__device__ __forceinline__ uint32_t smem_u32(const void* p) {
    uint32_t a;
    asm("{ .reg .u64 t; cvta.to.shared.u64 t, %1; cvt.u32.u64 %0, t; }" : "=r"(a) : "l"(p));
    return a;
}
__device__ __forceinline__ void ldm_x4(uint32_t* r, uint32_t addr) {
    asm volatile("ldmatrix.sync.aligned.m8n8.x4.shared.b16 {%0,%1,%2,%3}, [%4];"
                 : "=r"(r[0]), "=r"(r[1]), "=r"(r[2]), "=r"(r[3]) : "r"(addr));
}
__device__ __forceinline__ void mma16816(float* c, const uint32_t* a,
                                         uint32_t b0, uint32_t b1) {
    asm volatile(
        "mma.sync.aligned.m16n8k16.row.col.f32.bf16.bf16.f32 "
        "{%0,%1,%2,%3}, {%4,%5,%6,%7}, {%8,%9}, {%0,%1,%2,%3};"
        : "+f"(c[0]), "+f"(c[1]), "+f"(c[2]), "+f"(c[3])
        : "r"(a[0]), "r"(a[1]), "r"(a[2]), "r"(a[3]), "r"(b0), "r"(b1));
}
__device__ __forceinline__ void cpa16(uint32_t saddr, const void* g) {
    asm volatile("cp.async.cg.shared.global [%0], [%1], 16;" :: "r"(saddr), "l"(g));
}
#define CP_COMMIT() asm volatile("cp.async.commit_group;" ::: "memory")
#define CP_WAIT(N)  asm volatile("cp.async.wait_group %0;" :: "n"(N) : "memory")

// bf16 split helpers ---------------------------------------------------------
__device__ __forceinline__ void split_bf16(float v, unsigned short& h, unsigned short& l) {
    __nv_bfloat16 bh = __float2bfloat16(v);
    float r = v - __bfloat162float(bh);
    h = __bfloat16_as_ushort(bh);
    l = __bfloat16_as_ushort(__float2bfloat16(r));
}
__device__ __forceinline__ uint32_t pack2u(unsigned short a, unsigned short b) {
    return (uint32_t)a | ((uint32_t)b << 16);
}
__device__ __forceinline__ uint2 pack4u(unsigned short a, unsigned short b,
                                        unsigned short c, unsigned short d) {
    return make_uint2(pack2u(a, b), pack2u(c, d));
}
__device__ __forceinline__ float bf_lo(uint32_t u) {
    return __bfloat162float(__ushort_as_bfloat16((unsigned short)(u & 0xffff)));
}
__device__ __forceinline__ float bf_hi(uint32_t u) {
    return __bfloat162float(__ushort_as_bfloat16((unsigned short)(u >> 16)));
}

// ---------------------------------------------------------------------------
// Conversion kernels
// ---------------------------------------------------------------------------
__global__ void __launch_bounds__(256)
conv_split(const float* __restrict__ x, __nv_bfloat16* __restrict__ hi,
           __nv_bfloat16* __restrict__ lo, int n4)
{
    int i = blockIdx.x * 256 + threadIdx.x;
    if (i >= n4) return;
    float4 v = reinterpret_cast<const float4*>(x)[i];
    unsigned short h0, h1, h2, h3, l0, l1, l2, l3;
    split_bf16(v.x, h0, l0); split_bf16(v.y, h1, l1);
    split_bf16(v.z, h2, l2); split_bf16(v.w, h3, l3);
    reinterpret_cast<uint2*>(hi)[i] = pack4u(h0, h1, h2, h3);
    reinterpret_cast<uint2*>(lo)[i] = pack4u(l0, l1, l2, l3);
}

// W [K,N] row-major -> W^T hi/lo bf16 [N,K]
__global__ void __launch_bounds__(256)
convT_split(const float* __restrict__ W, __nv_bfloat16* __restrict__ Thi,
            __nv_bfloat16* __restrict__ Tlo, int K, int N)
{
    __shared__ float sm[32][33];
    int n0 = blockIdx.x * 32, k0 = blockIdx.y * 32;
    int tx = threadIdx.x, ty = threadIdx.y;       // (32, 8)
#pragma unroll
    for (int i = 0; i < 32; i += 8)
        sm[ty + i][tx] = W[(size_t)(k0 + ty + i) * N + n0 + tx];
    __syncthreads();
#pragma unroll
    for (int i = 0; i < 32; i += 8) {
        float v = sm[tx][ty + i];
        unsigned short h, l;
        split_bf16(v, h, l);
        size_t o = (size_t)(n0 + ty + i) * K + k0 + tx;
        Thi[o] = __ushort_as_bfloat16(h);
        Tlo[o] = __ushort_as_bfloat16(l);
    }
}

// ---------------------------------------------------------------------------
// bf16x3 GEMM via mma.sync (HMMA):  D[m,n] = sum_k A[m,k]*B[n,k]
// Block 128 x NT x 32, 256 threads, 8 warps (4M x 2N), warp tile 32 x NT/2.
// 3-stage cp.async pipeline.
// Epilogue modes:
//   0: fp32 row-major (+bias,*scale)
//   1: head-split bf16 hi/lo (+bias,*scale):  [b,h,t,d]
//   2: V^T bf16 hi/lo (+bias):  [b, col, t]
//   3: ctx bf16 hi/lo:  [(b*1024+row)*1024 + h*64 + col], z = b*16+h
// ---------------------------------------------------------------------------
#define APAD 80                 // 32 bf16 = 64B payload, padded to 80B
#define A_TERM (128 * APAD)     // 10240

template <int NT>
__global__ void __launch_bounds__(256)
gemm_bf16x3(const __nv_bfloat16* __restrict__ Ahi, const __nv_bfloat16* __restrict__ Alo,
            size_t aBS, int lda,
            const __nv_bfloat16* __restrict__ Bhi, const __nv_bfloat16* __restrict__ Blo,
            size_t bBS, int bDiv, int ldb,
            int K,
            const float* __restrict__ bias, float scale,
            float* __restrict__ outF, size_t outBS, int ldOut,
            __nv_bfloat16* __restrict__ outHi, __nv_bfloat16* __restrict__ outLo,
            int mode)
{
    constexpr int B_TERM = NT * APAD;
    constexpr int STAGE  = 2 * A_TERM + 2 * B_TERM;
    constexpr int W      = NT / 2;     // warp n-width
    constexpr int NTB    = W / 16;     // 16-col blocks per warp

    extern __shared__ __align__(16) char smem[];
    const uint32_t sbase = smem_u32(smem);
    const int tid  = threadIdx.x;
    const int lane = tid & 31;
    const int wid  = tid >> 5;
    const int wm   = wid & 3;
    const int wn   = wid >> 2;
    const int m0   = blockIdx.y * 128;
    const int n0   = blockIdx.x * NT;
    const int z    = blockIdx.z;

    const __nv_bfloat16* Ah = Ahi + (size_t)z * aBS;
    const __nv_bfloat16* Al = Alo + (size_t)z * aBS;
    const __nv_bfloat16* Bh = Bhi + (size_t)(z / bDiv) * bBS;
    const __nv_bfloat16* Bl = Blo + (size_t)(z / bDiv) * bBS;

    const int sRow = tid >> 2;           // 0..63
    const int slot = tid & 3;            // 16B slot in 64B row payload

    const uint32_t aLdmOff = (uint32_t)((wm * 32 + (lane & 15)) * APAD + (lane >> 4) * 16);
    const uint32_t bLdmOff = (uint32_t)((wn * W  + (lane & 15)) * APAD + (lane >> 4) * 16);

    float acc[2][NTB][2][4];
#pragma unroll
    for (int i = 0; i < 2; i++)
#pragma unroll
        for (int j = 0; j < NTB; j++)
#pragma unroll
            for (int k = 0; k < 2; k++)
#pragma unroll
                for (int l = 0; l < 4; l++) acc[i][j][k][l] = 0.0f;

    const int nc = K >> 5;   // chunks of 32

    auto stage_chunk = [&](int c) {
        const int k0 = c << 5;
        const uint32_t buf = sbase + (uint32_t)((c % 3) * STAGE);
#pragma unroll
        for (int r = 0; r < 128; r += 64) {
            int row = sRow + r;
            size_t go = (size_t)(m0 + row) * lda + k0 + slot * 8;
            uint32_t so = buf + (uint32_t)(row * APAD + slot * 16);
            cpa16(so, Ah + go);
            cpa16(so + A_TERM, Al + go);
        }
#pragma unroll
        for (int r = 0; r < NT; r += 64) {
            int row = sRow + r;
            size_t go = (size_t)(n0 + row) * ldb + k0 + slot * 8;
            uint32_t so = buf + 2 * A_TERM + (uint32_t)(row * APAD + slot * 16);
            cpa16(so, Bh + go);
            cpa16(so + B_TERM, Bl + go);
        }
        CP_COMMIT();
    };

    stage_chunk(0);
    if (nc > 1) stage_chunk(1);

    for (int c = 0; c < nc; c++) {
        if (c + 2 < nc) { stage_chunk(c + 2); CP_WAIT(2); }
        else if (c + 1 < nc) { CP_WAIT(1); }
        else { CP_WAIT(0); }
        __syncthreads();

        const uint32_t cbuf = sbase + (uint32_t)((c % 3) * STAGE);
        const uint32_t aHiB = cbuf + aLdmOff;
        const uint32_t aLoB = cbuf + A_TERM + aLdmOff;
        const uint32_t bHiB = cbuf + 2 * A_TERM + bLdmOff;
        const uint32_t bLoB = cbuf + 2 * A_TERM + B_TERM + bLdmOff;

#pragma unroll
        for (int ks = 0; ks < 2; ks++) {
            const uint32_t ko = ks * 32;   // 16 bf16 = 32 bytes
            uint32_t ahi[2][4], alo[2][4], bhi[NTB][4], blo[NTB][4];
            ldm_x4(ahi[0], aHiB + ko);
            ldm_x4(ahi[1], aHiB + ko + 16 * APAD);
            ldm_x4(alo[0], aLoB + ko);
            ldm_x4(alo[1], aLoB + ko + 16 * APAD);
#pragma unroll
            for (int nt = 0; nt < NTB; nt++) {
                ldm_x4(bhi[nt], bHiB + ko + nt * 16 * APAD);
                ldm_x4(blo[nt], bLoB + ko + nt * 16 * APAD);
            }
#pragma unroll
            for (int mt = 0; mt < 2; mt++)
#pragma unroll
                for (int nt = 0; nt < NTB; nt++)
#pragma unroll
                    for (int nh = 0; nh < 2; nh++) {
                        float* cc = acc[mt][nt][nh];
                        mma16816(cc, ahi[mt], bhi[nt][nh], bhi[nt][nh + 2]);
                        mma16816(cc, ahi[mt], blo[nt][nh], blo[nt][nh + 2]);
                        mma16816(cc, alo[mt], bhi[nt][nh], bhi[nt][nh + 2]);
                    }
        }
        __syncthreads();
    }

    // ---- epilogue ----
    const int rr = lane >> 2;
    const int cc2 = (lane & 3) << 1;
#pragma unroll
    for (int mt = 0; mt < 2; mt++)
#pragma unroll
        for (int nt = 0; nt < NTB; nt++)
#pragma unroll
            for (int nh = 0; nh < 2; nh++) {
                const float* cv = acc[mt][nt][nh];
                int gc = n0 + wn * W + nt * 16 + nh * 8 + cc2;
                float b0 = 0.f, b1 = 0.f;
                if (bias) { b0 = bias[gc]; b1 = bias[gc + 1]; }
#pragma unroll
                for (int half = 0; half < 2; half++) {
                    int gr = m0 + wm * 32 + mt * 16 + rr + half * 8;
                    float v0 = (cv[half * 2 + 0] + b0) * scale;
                    float v1 = (cv[half * 2 + 1] + b1) * scale;
                    if (mode == 0) {
                        float* p = outF + (size_t)z * outBS + (size_t)gr * ldOut + gc;
                        *reinterpret_cast<float2*>(p) = make_float2(v0, v1);
                    } else if (mode == 1) {
                        int bb = gr >> 10, t = gr & 1023;
                        int h = gc >> 6, d = gc & 63;
                        size_t idx = ((size_t)((bb << 4) + h) << 16) + ((size_t)t << 6) + d;
                        unsigned short h0, h1, l0, l1;
                        split_bf16(v0, h0, l0); split_bf16(v1, h1, l1);
                        *reinterpret_cast<uint32_t*>(outHi + idx) = pack2u(h0, h1);
                        *reinterpret_cast<uint32_t*>(outLo + idx) = pack2u(l0, l1);
                    } else if (mode == 2) {
                        int bb = gr >> 10, t = gr & 1023;
                        unsigned short h0, h1, l0, l1;
                        split_bf16(v0, h0, l0); split_bf16(v1, h1, l1);
                        size_t i0 = ((size_t)bb << 16) + ((size_t)gc << 10) + t;
                        outHi[i0] = __ushort_as_bfloat16(h0);
                        outLo[i0] = __ushort_as_bfloat16(l0);
                        outHi[i0 + 1024] = __ushort_as_bfloat16(h1);
                        outLo[i0 + 1024] = __ushort_as_bfloat16(l1);
                    } else {  // mode 3: ctx
                        int bb = z >> 4, h = z & 15;
                        size_t idx = (((size_t)(bb << 10) + gr) << 10) + (h << 6) + gc;
                        unsigned short h0, h1, l0, l1;
                        split_bf16(v0, h0, l0); split_bf16(v1, h1, l1);
                        *reinterpret_cast<uint32_t*>(outHi + idx) = pack2u(h0, h1);
                        *reinterpret_cast<uint32_t*>(outLo + idx) = pack2u(l0, l1);
                    }
                }
            }
}

#define SMEM64  (3 * (2 * A_TERM + 2 * 64 * APAD))    // 92160
#define SMEM128 (3 * (2 * A_TERM + 2 * 128 * APAD))   // 122880

// ---------------------------------------------------------------------------
// Softmax over 65536 rows of 1024: read S fp32, write P bf16 hi/lo.
// ---------------------------------------------------------------------------
__global__ void __launch_bounds__(256)
softmax_kernel(const float* __restrict__ S, __nv_bfloat16* __restrict__ Phi,
               __nv_bfloat16* __restrict__ Plo)
{
    const int row = blockIdx.x * 8 + (threadIdx.x >> 5);
    const int lane = threadIdx.x & 31;
    const float* sr = S + (size_t)row * 1024;

    float4 v[8];
    float m = -1e30f;
#pragma unroll
    for (int i = 0; i < 8; i++) {
        v[i] = *reinterpret_cast<const float4*>(sr + ((i * 32 + lane) << 2));
        m = fmaxf(m, fmaxf(fmaxf(v[i].x, v[i].y), fmaxf(v[i].z, v[i].w)));
    }
#pragma unroll
    for (int o = 16; o; o >>= 1) m = fmaxf(m, __shfl_xor_sync(0xffffffffu, m, o));

    float s = 0.0f;
#pragma unroll
    for (int i = 0; i < 8; i++) {
        v[i].x = __expf(v[i].x - m); v[i].y = __expf(v[i].y - m);
        v[i].z = __expf(v[i].z - m); v[i].w = __expf(v[i].w - m);
        s += (v[i].x + v[i].y) + (v[i].z + v[i].w);
    }
#pragma unroll
    for (int o = 16; o; o >>= 1) s += __shfl_xor_sync(0xffffffffu, s, o);
    const float inv = 1.0f / s;

#pragma unroll
    for (int i = 0; i < 8; i++) {
        size_t e = (size_t)row * 1024 + ((i * 32 + lane) << 2);
        unsigned short h0, h1, h2, h3, l0, l1, l2, l3;
        split_bf16(v[i].x * inv, h0, l0);
        split_bf16(v[i].y * inv, h1, l1);
        split_bf16(v[i].z * inv, h2, l2);
        split_bf16(v[i].w * inv, h3, l3);
        *reinterpret_cast<uint2*>(Phi + e) = pack4u(h0, h1, h2, h3);
        *reinterpret_cast<uint2*>(Plo + e) = pack4u(l0, l1, l2, l3);
    }
}

// ---------------------------------------------------------------------------
// attn_mean[b,q,k] = (1/16) * sum_h (Phi + Plo)
// ---------------------------------------------------------------------------
__global__ void __launch_bounds__(256)
attn_mean_kernel(const __nv_bfloat16* __restrict__ Phi,
                 const __nv_bfloat16* __restrict__ Plo, float* __restrict__ out)
{
    size_t idx = (size_t)blockIdx.x * 256 + threadIdx.x;
    size_t e0 = idx << 2;
    int b = (int)(e0 >> 20);
    size_t rem = e0 & 1048575;
    float a0 = 0.f, a1 = 0.f, a2 = 0.f, a3 = 0.f;
#pragma unroll
    for (int h = 0; h < 16; h++) {
        size_t base = (((size_t)(b * 16 + h)) << 20) + rem;
        uint2 uh = *reinterpret_cast<const uint2*>(Phi + base);
        uint2 ul = *reinterpret_cast<const uint2*>(Plo + base);
        a0 += bf_lo(uh.x) + bf_lo(ul.x);
        a1 += bf_hi(uh.x) + bf_hi(ul.x);
        a2 += bf_lo(uh.y) + bf_lo(ul.y);
        a3 += bf_hi(uh.y) + bf_hi(ul.y);
    }
    const float s = 1.0f / 16.0f;
    *reinterpret_cast<float4*>(out + e0) = make_float4(a0 * s, a1 * s, a2 * s, a3 * s);
}

// ---------------------------------------------------------------------------
// kernel_launch. Inputs: x, Wq, bq, Wk, bk, Wv, bv, Wo, bo
// Output: out [4,1024,1024] fp32 then attn_mean [4,1024,1024] fp32
// ---------------------------------------------------------------------------
extern "C" void kernel_launch(void* const* d_in, const int* in_sizes, int n_in,
                              void* d_out, int out_size)
{
    (void)in_sizes; (void)n_in; (void)out_size;
    const float* x  = (const float*)d_in[0];
    const float* Wq = (const float*)d_in[1];
    const float* bq = (const float*)d_in[2];
    const float* Wk = (const float*)d_in[3];
    const float* bk = (const float*)d_in[4];
    const float* Wv = (const float*)d_in[5];
    const float* bv = (const float*)d_in[6];
    const float* Wo = (const float*)d_in[7];
    const float* bo = (const float*)d_in[8];
    float* out     = (float*)d_out;
    float* outAttn = out + 4194304;

    char* hp = nullptr;
    cudaGetSymbolAddress((void**)&hp, g_heap);
    __nv_bfloat16* Xhi   = (__nv_bfloat16*)(hp + OFF_XHI);
    __nv_bfloat16* Xlo   = (__nv_bfloat16*)(hp + OFF_XLO);
    __nv_bfloat16* WqThi = (__nv_bfloat16*)(hp + OFF_WQTHI);
    __nv_bfloat16* WqTlo = (__nv_bfloat16*)(hp + OFF_WQTLO);
    __nv_bfloat16* WkThi = (__nv_bfloat16*)(hp + OFF_WKTHI);
    __nv_bfloat16* WkTlo = (__nv_bfloat16*)(hp + OFF_WKTLO);
    __nv_bfloat16* WoThi = (__nv_bfloat16*)(hp + OFF_WOTHI);
    __nv_bfloat16* WoTlo = (__nv_bfloat16*)(hp + OFF_WOTLO);
    __nv_bfloat16* WvThi = (__nv_bfloat16*)(hp + OFF_WVTHI);
    __nv_bfloat16* WvTlo = (__nv_bfloat16*)(hp + OFF_WVTLO);
    __nv_bfloat16* Qhi   = (__nv_bfloat16*)(hp + OFF_QHI);
    __nv_bfloat16* Qlo   = (__nv_bfloat16*)(hp + OFF_QLO);
    __nv_bfloat16* Khi   = (__nv_bfloat16*)(hp + OFF_KHI);
    __nv_bfloat16* Klo   = (__nv_bfloat16*)(hp + OFF_KLO);
    __nv_bfloat16* Vthi  = (__nv_bfloat16*)(hp + OFF_VTHI);
    __nv_bfloat16* Vtlo  = (__nv_bfloat16*)(hp + OFF_VTLO);
    __nv_bfloat16* Chi   = (__nv_bfloat16*)(hp + OFF_CHI);
    __nv_bfloat16* Clo   = (__nv_bfloat16*)(hp + OFF_CLO);
    __nv_bfloat16* Phi   = (__nv_bfloat16*)(hp + OFF_PHI);
    __nv_bfloat16* Plo   = (__nv_bfloat16*)(hp + OFF_PLO);
    float*         Sbuf  = (float*)(hp + OFF_S);

    cudaFuncSetAttribute(gemm_bf16x3<64>,  cudaFuncAttributeMaxDynamicSharedMemorySize, SMEM64);
    cudaFuncSetAttribute(gemm_bf16x3<128>, cudaFuncAttributeMaxDynamicSharedMemorySize, SMEM128);

    // conversions
    conv_split<<<4096, 256>>>(x, Xhi, Xlo, 1048576);
    convT_split<<<dim3(32, 32), dim3(32, 8)>>>(Wq, WqThi, WqTlo, 1024, 1024);
    convT_split<<<dim3(32, 32), dim3(32, 8)>>>(Wk, WkThi, WkTlo, 1024, 1024);
    convT_split<<<dim3(32, 32), dim3(32, 8)>>>(Wo, WoThi, WoTlo, 1024, 1024);
    convT_split<<<dim3(2, 32),  dim3(32, 8)>>>(Wv, WvThi, WvTlo, 1024, 64);

    // Q projection (scale 1/8 folded in) -> head-split bf16 hi/lo
    gemm_bf16x3<128><<<dim3(8, 32, 1), 256, SMEM128>>>(
        Xhi, Xlo, 0, 1024, WqThi, WqTlo, 0, 1, 1024, 1024,
        bq, 0.125f, nullptr, 0, 0, Qhi, Qlo, 1);
    // K projection -> head-split bf16 hi/lo
    gemm_bf16x3<128><<<dim3(8, 32, 1), 256, SMEM128>>>(
        Xhi, Xlo, 0, 1024, WkThi, WkTlo, 0, 1, 1024, 1024,
        bk, 1.0f, nullptr, 0, 0, Khi, Klo, 1);
    // V projection -> V^T [b,d,t] bf16 hi/lo
    gemm_bf16x3<64><<<dim3(1, 32, 1), 256, SMEM64>>>(
        Xhi, Xlo, 0, 1024, WvThi, WvTlo, 0, 1, 1024, 1024,
        bv, 1.0f, nullptr, 0, 0, Vthi, Vtlo, 2);
    // S = Q K^T (64 batches over b,h; K=64) -> fp32
    gemm_bf16x3<128><<<dim3(8, 8, 64), 256, SMEM128>>>(
        Qhi, Qlo, 65536, 64, Khi, Klo, 65536, 1, 64, 64,
        nullptr, 1.0f, Sbuf, 1048576, 1024, nullptr, nullptr, 0);
    // softmax -> P bf16 hi/lo
    softmax_kernel<<<8192, 256>>>(Sbuf, Phi, Plo);
    // ctx = P V (64 batches, V^T shared per b) -> ctx bf16 hi/lo
    gemm_bf16x3<64><<<dim3(1, 8, 64), 256, SMEM64>>>(
        Phi, Plo, 1048576, 1024, Vthi, Vtlo, 65536, 16, 1024, 1024,
        nullptr, 1.0f, nullptr, 0, 0, Chi, Clo, 3);
    // attn_mean
    attn_mean_kernel<<<4096, 256>>>(Phi, Plo, outAttn);
    // out = ctx @ Wo + bo -> fp32 d_out
    gemm_bf16x3<128><<<dim3(8, 32, 1), 256, SMEM128>>>(
        Chi, Clo, 0, 1024, WoThi, WoTlo, 0, 1, 1024, 1024,
        bo, 1.0f, out, 0, 1024, nullptr, nullptr, 0);
}

// round 6
// speedup vs baseline: 1.0758x; 1.0758x over previous
#include <cuda_runtime.h>
#include <cuda_bf16.h>
#include <cuda_fp16.h>
#include <cstdint>
#include <cstddef>

// Problem constants: B=4, T=1024, D=1024, H=16, DH=64
#define MB ((size_t)1 << 20)

// ---------------------------------------------------------------------------
// Static device heap (no runtime allocation). Offsets in bytes.
// ---------------------------------------------------------------------------
#define OFF_XHI   (0 * MB)
#define OFF_XLO   (8 * MB)
#define OFF_WQTHI (16 * MB)
#define OFF_WQTLO (18 * MB)
#define OFF_WKTHI (20 * MB)
#define OFF_WKTLO (22 * MB)
#define OFF_WOTHI (24 * MB)
#define OFF_WOTLO (26 * MB)
#define OFF_WVTHI (28 * MB)
#define OFF_WVTLO (28 * MB + 131072)
#define OFF_QHI   (29 * MB)
#define OFF_QLO   (37 * MB)
#define OFF_KHI   (45 * MB)
#define OFF_KLO   (53 * MB)
#define OFF_VTHI  (61 * MB)
#define OFF_VTLO  (61 * MB + 524288)
#define OFF_CHI   (62 * MB)
#define OFF_CLO   (70 * MB)
#define OFF_P16   (78 * MB)          // probs fp16 [bh,q,k]  128 MB
#define HEAP_BYTES (206 * MB)

__device__ char g_heap[HEAP_BYTES];

// ---------------------------------------------------------------------------
// PTX helpers (Ampere-compatible: ldmatrix / mma.sync / cp.async)
// ---------------------------------------------------------------------------
__device__ __forceinline__ uint32_t smem_u32(const void* p) {
    uint32_t a;
    asm("{ .reg .u64 t; cvta.to.shared.u64 t, %1; cvt.u32.u64 %0, t; }" : "=r"(a) : "l"(p));
    return a;
}
__device__ __forceinline__ void ldm_x4(uint32_t* r, uint32_t addr) {
    asm volatile("ldmatrix.sync.aligned.m8n8.x4.shared.b16 {%0,%1,%2,%3}, [%4];"
                 : "=r"(r[0]), "=r"(r[1]), "=r"(r[2]), "=r"(r[3]) : "r"(addr));
}
__device__ __forceinline__ void mma16816(float* c, const uint32_t* a,
                                         uint32_t b0, uint32_t b1) {
    asm volatile(
        "mma.sync.aligned.m16n8k16.row.col.f32.bf16.bf16.f32 "
        "{%0,%1,%2,%3}, {%4,%5,%6,%7}, {%8,%9}, {%0,%1,%2,%3};"
        : "+f"(c[0]), "+f"(c[1]), "+f"(c[2]), "+f"(c[3])
        : "r"(a[0]), "r"(a[1]), "r"(a[2]), "r"(a[3]), "r"(b0), "r"(b1));
}
__device__ __forceinline__ void cpa16(uint32_t saddr, const void* g) {
    asm volatile("cp.async.cg.shared.global [%0], [%1], 16;" :: "r"(saddr), "l"(g));
}
#define CP_COMMIT() asm volatile("cp.async.commit_group;" ::: "memory")
#define CP_WAIT(N)  asm volatile("cp.async.wait_group %0;" :: "n"(N) : "memory")

// bf16 split helpers ---------------------------------------------------------
__device__ __forceinline__ void split_bf16(float v, unsigned short& h, unsigned short& l) {
    __nv_bfloat16 bh = __float2bfloat16(v);
    float r = v - __bfloat162float(bh);
    h = __bfloat16_as_ushort(bh);
    l = __bfloat16_as_ushort(__float2bfloat16(r));
}
__device__ __forceinline__ uint32_t pack2u(unsigned short a, unsigned short b) {
    return (uint32_t)a | ((uint32_t)b << 16);
}
__device__ __forceinline__ uint2 pack4u(unsigned short a, unsigned short b,
                                        unsigned short c, unsigned short d) {
    return make_uint2(pack2u(a, b), pack2u(c, d));
}

// ---------------------------------------------------------------------------
// Conversion kernels
// ---------------------------------------------------------------------------
__global__ void __launch_bounds__(256)
conv_split(const float* __restrict__ x, __nv_bfloat16* __restrict__ hi,
           __nv_bfloat16* __restrict__ lo, int n4)
{
    int i = blockIdx.x * 256 + threadIdx.x;
    if (i >= n4) return;
    float4 v = reinterpret_cast<const float4*>(x)[i];
    unsigned short h0, h1, h2, h3, l0, l1, l2, l3;
    split_bf16(v.x, h0, l0); split_bf16(v.y, h1, l1);
    split_bf16(v.z, h2, l2); split_bf16(v.w, h3, l3);
    reinterpret_cast<uint2*>(hi)[i] = pack4u(h0, h1, h2, h3);
    reinterpret_cast<uint2*>(lo)[i] = pack4u(l0, l1, l2, l3);
}

// W [K,N] row-major -> W^T hi/lo bf16 [N,K]
__global__ void __launch_bounds__(256)
convT_split(const float* __restrict__ W, __nv_bfloat16* __restrict__ Thi,
            __nv_bfloat16* __restrict__ Tlo, int K, int N)
{
    __shared__ float sm[32][33];
    int n0 = blockIdx.x * 32, k0 = blockIdx.y * 32;
    int tx = threadIdx.x, ty = threadIdx.y;       // (32, 8)
#pragma unroll
    for (int i = 0; i < 32; i += 8)
        sm[ty + i][tx] = W[(size_t)(k0 + ty + i) * N + n0 + tx];
    __syncthreads();
#pragma unroll
    for (int i = 0; i < 32; i += 8) {
        float v = sm[tx][ty + i];
        unsigned short h, l;
        split_bf16(v, h, l);
        size_t o = (size_t)(n0 + ty + i) * K + k0 + tx;
        Thi[o] = __ushort_as_bfloat16(h);
        Tlo[o] = __ushort_as_bfloat16(l);
    }
}

// ---------------------------------------------------------------------------
// bf16x3 GEMM via mma.sync (HMMA):  D[m,n] = sum_k A[m,k]*B[n,k]
// Block 128 x NT x 32, 256 threads, 8 warps (4M x 2N), 3-stage cp.async.
// Epilogue modes:
//   0: fp32 row-major (+bias,*scale)
//   1: head-split bf16 hi/lo (+bias,*scale):  [b,h,t,d]
//   2: V^T bf16 hi/lo (+bias):  [b, col, t]
// ---------------------------------------------------------------------------
#define APAD 80                 // 32 bf16 = 64B payload, padded to 80B
#define A_TERM (128 * APAD)     // 10240

template <int NT>
__global__ void __launch_bounds__(256)
gemm_bf16x3(const __nv_bfloat16* __restrict__ Ahi, const __nv_bfloat16* __restrict__ Alo,
            size_t aBS, int lda,
            const __nv_bfloat16* __restrict__ Bhi, const __nv_bfloat16* __restrict__ Blo,
            size_t bBS, int bDiv, int ldb,
            int K,
            const float* __restrict__ bias, float scale,
            float* __restrict__ outF, size_t outBS, int ldOut,
            __nv_bfloat16* __restrict__ outHi, __nv_bfloat16* __restrict__ outLo,
            int mode)
{
    constexpr int B_TERM = NT * APAD;
    constexpr int STAGE  = 2 * A_TERM + 2 * B_TERM;
    constexpr int W      = NT / 2;
    constexpr int NTB    = W / 16;

    extern __shared__ __align__(16) char smem[];
    const uint32_t sbase = smem_u32(smem);
    const int tid  = threadIdx.x;
    const int lane = tid & 31;
    const int wid  = tid >> 5;
    const int wm   = wid & 3;
    const int wn   = wid >> 2;
    const int m0   = blockIdx.y * 128;
    const int n0   = blockIdx.x * NT;
    const int z    = blockIdx.z;

    const __nv_bfloat16* Ah = Ahi + (size_t)z * aBS;
    const __nv_bfloat16* Al = Alo + (size_t)z * aBS;
    const __nv_bfloat16* Bh = Bhi + (size_t)(z / bDiv) * bBS;
    const __nv_bfloat16* Bl = Blo + (size_t)(z / bDiv) * bBS;

    const int sRow = tid >> 2;
    const int slot = tid & 3;

    const uint32_t aLdmOff = (uint32_t)((wm * 32 + (lane & 15)) * APAD + (lane >> 4) * 16);
    const uint32_t bLdmOff = (uint32_t)((wn * W  + (lane & 15)) * APAD + (lane >> 4) * 16);

    float acc[2][NTB][2][4];
#pragma unroll
    for (int i = 0; i < 2; i++)
#pragma unroll
        for (int j = 0; j < NTB; j++)
#pragma unroll
            for (int k = 0; k < 2; k++)
#pragma unroll
                for (int l = 0; l < 4; l++) acc[i][j][k][l] = 0.0f;

    const int nc = K >> 5;

    auto stage_chunk = [&](int c) {
        const int k0 = c << 5;
        const uint32_t buf = sbase + (uint32_t)((c % 3) * STAGE);
#pragma unroll
        for (int r = 0; r < 128; r += 64) {
            int row = sRow + r;
            size_t go = (size_t)(m0 + row) * lda + k0 + slot * 8;
            uint32_t so = buf + (uint32_t)(row * APAD + slot * 16);
            cpa16(so, Ah + go);
            cpa16(so + A_TERM, Al + go);
        }
#pragma unroll
        for (int r = 0; r < NT; r += 64) {
            int row = sRow + r;
            size_t go = (size_t)(n0 + row) * ldb + k0 + slot * 8;
            uint32_t so = buf + 2 * A_TERM + (uint32_t)(row * APAD + slot * 16);
            cpa16(so, Bh + go);
            cpa16(so + B_TERM, Bl + go);
        }
        CP_COMMIT();
    };

    stage_chunk(0);
    if (nc > 1) stage_chunk(1);

    for (int c = 0; c < nc; c++) {
        if (c + 2 < nc) { stage_chunk(c + 2); CP_WAIT(2); }
        else if (c + 1 < nc) { CP_WAIT(1); }
        else { CP_WAIT(0); }
        __syncthreads();

        const uint32_t cbuf = sbase + (uint32_t)((c % 3) * STAGE);
        const uint32_t aHiB = cbuf + aLdmOff;
        const uint32_t aLoB = cbuf + A_TERM + aLdmOff;
        const uint32_t bHiB = cbuf + 2 * A_TERM + bLdmOff;
        const uint32_t bLoB = cbuf + 2 * A_TERM + B_TERM + bLdmOff;

#pragma unroll
        for (int ks = 0; ks < 2; ks++) {
            const uint32_t ko = ks * 32;
            uint32_t ahi[2][4], alo[2][4], bhi[NTB][4], blo[NTB][4];
            ldm_x4(ahi[0], aHiB + ko);
            ldm_x4(ahi[1], aHiB + ko + 16 * APAD);
            ldm_x4(alo[0], aLoB + ko);
            ldm_x4(alo[1], aLoB + ko + 16 * APAD);
#pragma unroll
            for (int nt = 0; nt < NTB; nt++) {
                ldm_x4(bhi[nt], bHiB + ko + nt * 16 * APAD);
                ldm_x4(blo[nt], bLoB + ko + nt * 16 * APAD);
            }
#pragma unroll
            for (int mt = 0; mt < 2; mt++)
#pragma unroll
                for (int nt = 0; nt < NTB; nt++)
#pragma unroll
                    for (int nh = 0; nh < 2; nh++) {
                        float* cc = acc[mt][nt][nh];
                        mma16816(cc, ahi[mt], bhi[nt][nh], bhi[nt][nh + 2]);
                        mma16816(cc, ahi[mt], blo[nt][nh], blo[nt][nh + 2]);
                        mma16816(cc, alo[mt], bhi[nt][nh], bhi[nt][nh + 2]);
                    }
        }
        __syncthreads();
    }

    // ---- epilogue ----
    const int rr = lane >> 2;
    const int cc2 = (lane & 3) << 1;
#pragma unroll
    for (int mt = 0; mt < 2; mt++)
#pragma unroll
        for (int nt = 0; nt < NTB; nt++)
#pragma unroll
            for (int nh = 0; nh < 2; nh++) {
                const float* cv = acc[mt][nt][nh];
                int gc = n0 + wn * W + nt * 16 + nh * 8 + cc2;
                float b0 = 0.f, b1 = 0.f;
                if (bias) { b0 = bias[gc]; b1 = bias[gc + 1]; }
#pragma unroll
                for (int half = 0; half < 2; half++) {
                    int gr = m0 + wm * 32 + mt * 16 + rr + half * 8;
                    float v0 = (cv[half * 2 + 0] + b0) * scale;
                    float v1 = (cv[half * 2 + 1] + b1) * scale;
                    if (mode == 0) {
                        float* p = outF + (size_t)z * outBS + (size_t)gr * ldOut + gc;
                        *reinterpret_cast<float2*>(p) = make_float2(v0, v1);
                    } else if (mode == 1) {
                        int bb = gr >> 10, t = gr & 1023;
                        int h = gc >> 6, d = gc & 63;
                        size_t idx = ((size_t)((bb << 4) + h) << 16) + ((size_t)t << 6) + d;
                        unsigned short h0, h1, l0, l1;
                        split_bf16(v0, h0, l0); split_bf16(v1, h1, l1);
                        *reinterpret_cast<uint32_t*>(outHi + idx) = pack2u(h0, h1);
                        *reinterpret_cast<uint32_t*>(outLo + idx) = pack2u(l0, l1);
                    } else { // mode 2
                        int bb = gr >> 10, t = gr & 1023;
                        unsigned short h0, h1, l0, l1;
                        split_bf16(v0, h0, l0); split_bf16(v1, h1, l1);
                        size_t i0 = ((size_t)bb << 16) + ((size_t)gc << 10) + t;
                        outHi[i0] = __ushort_as_bfloat16(h0);
                        outLo[i0] = __ushort_as_bfloat16(l0);
                        outHi[i0 + 1024] = __ushort_as_bfloat16(h1);
                        outLo[i0 + 1024] = __ushort_as_bfloat16(l1);
                    }
                }
            }
}

#define SMEM64  (3 * (2 * A_TERM + 2 * 64 * APAD))    // 92160
#define SMEM128 (3 * (2 * A_TERM + 2 * 128 * APAD))   // 122880

// ---------------------------------------------------------------------------
// Fused attention: per CTA = (bh, 32 q rows).
//   S strip (32 x 1024 fp32) built in smem by MMA over 8 key tiles;
//   in-smem softmax; in-place convert P to bf16 hi/lo; P fp16 -> gmem;
//   PV MMAs from smem P and staged V^T tiles; ctx bf16 hi/lo -> gmem.
// smem: S strip 32 x 4112B, Q hi/lo 32x144 each, 2 KV buffers 36864B each.
// ---------------------------------------------------------------------------
#define SROWB  4112
#define FA_QH  131584
#define FA_QL  (FA_QH + 4608)
#define FA_KV0 (FA_QL + 4608)
#define FA_KVSZ 36864
#define FA_KV1 (FA_KV0 + FA_KVSZ)
#define FA_SMEM (FA_KV1 + FA_KVSZ)   // 214528

__global__ void __launch_bounds__(256)
fused_attn(const __nv_bfloat16* __restrict__ Qhi_, const __nv_bfloat16* __restrict__ Qlo_,
           const __nv_bfloat16* __restrict__ Khi_, const __nv_bfloat16* __restrict__ Klo_,
           const __nv_bfloat16* __restrict__ Vhi_, const __nv_bfloat16* __restrict__ Vlo_,
           __half* __restrict__ Pout,
           __nv_bfloat16* __restrict__ Chi, __nv_bfloat16* __restrict__ Clo)
{
    extern __shared__ __align__(16) char smem[];
    const uint32_t sb = smem_u32(smem);
    const int tid = threadIdx.x, lane = tid & 31, wid = tid >> 5;
    const int q0 = blockIdx.x * 32;
    const int bh = blockIdx.y;
    const int b = bh >> 4, h = bh & 15;

    const __nv_bfloat16* Qh = Qhi_ + ((size_t)bh << 16) + ((size_t)q0 << 6);
    const __nv_bfloat16* Ql = Qlo_ + ((size_t)bh << 16) + ((size_t)q0 << 6);
    const __nv_bfloat16* Kh = Khi_ + ((size_t)bh << 16);
    const __nv_bfloat16* Kl = Klo_ + ((size_t)bh << 16);
    const __nv_bfloat16* Vh = Vhi_ + ((size_t)b << 16);
    const __nv_bfloat16* Vl = Vlo_ + ((size_t)b << 16);

    auto stageK = [&](int kt, uint32_t buf) {
#pragma unroll
        for (int i = 0; i < 4; i++) {
            int idx = tid + i * 256;
            int row = idx >> 3, slot = idx & 7;
            size_t go = ((size_t)(kt * 128 + row) << 6) + slot * 8;
            uint32_t so = buf + (uint32_t)(row * 144 + slot * 16);
            cpa16(so, Kh + go);
            cpa16(so + 18432, Kl + go);
        }
        CP_COMMIT();
    };
    auto stageV = [&](int vt, uint32_t buf) {
#pragma unroll
        for (int i = 0; i < 4; i++) {
            int idx = tid + i * 256;
            int row = idx >> 4, slot = idx & 15;
            size_t go = ((size_t)row << 10) + vt * 128 + slot * 8;
            uint32_t so = buf + (uint32_t)(row * 272 + slot * 16);
            cpa16(so, Vh + go);
            cpa16(so + 17408, Vl + go);
        }
        CP_COMMIT();
    };

    // stage Q (32x64 hi/lo) + first K tile in one group
    {
        int row = tid >> 3, slot = tid & 7;
        size_t go = ((size_t)row << 6) + slot * 8;
        cpa16(sb + FA_QH + (uint32_t)(row * 144 + slot * 16), Qh + go);
        cpa16(sb + FA_QL + (uint32_t)(row * 144 + slot * 16), Ql + go);
    }
    stageK(0, sb + FA_KV0);

    // ---------------- phase 1: S = Q K^T ----------------
    const int wm = wid & 1, wn = wid >> 1;       // 2M x 4N, warp tile 16x32
    const uint32_t aQh = sb + FA_QH + (uint32_t)((wm * 16 + (lane & 15)) * 144 + (lane >> 4) * 16);
    const uint32_t aQl = sb + FA_QL + (uint32_t)((wm * 16 + (lane & 15)) * 144 + (lane >> 4) * 16);

    for (int kt = 0; kt < 8; kt++) {
        uint32_t buf = sb + ((kt & 1) ? FA_KV1 : FA_KV0);
        if (kt < 7) { stageK(kt + 1, sb + ((kt & 1) ? FA_KV0 : FA_KV1)); CP_WAIT(1); }
        else { CP_WAIT(0); }
        __syncthreads();

        float acc[2][2][4];
#pragma unroll
        for (int i = 0; i < 2; i++)
#pragma unroll
            for (int j = 0; j < 2; j++)
#pragma unroll
                for (int l = 0; l < 4; l++) acc[i][j][l] = 0.0f;

        const uint32_t bKh = buf + (uint32_t)((wn * 32 + (lane & 15)) * 144 + (lane >> 4) * 16);
        const uint32_t bKl = bKh + 18432;
#pragma unroll
        for (int ks = 0; ks < 4; ks++) {
            const uint32_t ko = ks * 32;
            uint32_t ahi[4], alo[4], bhi[2][4], blo[2][4];
            ldm_x4(ahi, aQh + ko);
            ldm_x4(alo, aQl + ko);
            ldm_x4(bhi[0], bKh + ko);
            ldm_x4(bhi[1], bKh + ko + 16 * 144);
            ldm_x4(blo[0], bKl + ko);
            ldm_x4(blo[1], bKl + ko + 16 * 144);
#pragma unroll
            for (int nt = 0; nt < 2; nt++)
#pragma unroll
                for (int nh = 0; nh < 2; nh++) {
                    float* cc = acc[nt][nh];
                    mma16816(cc, ahi, bhi[nt][nh], bhi[nt][nh + 2]);
                    mma16816(cc, ahi, blo[nt][nh], blo[nt][nh + 2]);
                    mma16816(cc, alo, bhi[nt][nh], bhi[nt][nh + 2]);
                }
        }
        // write S tile to strip
        const int r0 = wm * 16 + (lane >> 2);
#pragma unroll
        for (int nt = 0; nt < 2; nt++)
#pragma unroll
            for (int nh = 0; nh < 2; nh++) {
                int col = kt * 128 + wn * 32 + nt * 16 + nh * 8 + ((lane & 3) << 1);
                *reinterpret_cast<float2*>(smem + r0 * SROWB + col * 4) =
                    make_float2(acc[nt][nh][0], acc[nt][nh][1]);
                *reinterpret_cast<float2*>(smem + (r0 + 8) * SROWB + col * 4) =
                    make_float2(acc[nt][nh][2], acc[nt][nh][3]);
            }
        __syncthreads();
    }

    // ---------------- phase 2: softmax + P conversion ----------------
#pragma unroll 1
    for (int rr = 0; rr < 4; rr++) {
        const int r = wid * 4 + rr;
        char* rowp = smem + r * SROWB;
        float2 v[16];
        float m = -1e30f;
#pragma unroll
        for (int i = 0; i < 16; i++) {
            v[i] = *reinterpret_cast<const float2*>(rowp + ((lane * 2 + 64 * i) << 2));
            m = fmaxf(m, fmaxf(v[i].x, v[i].y));
        }
#pragma unroll
        for (int o = 16; o; o >>= 1) m = fmaxf(m, __shfl_xor_sync(0xffffffffu, m, o));
        float s = 0.0f;
#pragma unroll
        for (int i = 0; i < 16; i++) {
            v[i].x = __expf(v[i].x - m);
            v[i].y = __expf(v[i].y - m);
            s += v[i].x + v[i].y;
        }
#pragma unroll
        for (int o = 16; o; o >>= 1) s += __shfl_xor_sync(0xffffffffu, s, o);
        const float inv = 1.0f / s;
        const size_t pbase = ((size_t)bh << 20) + ((size_t)(q0 + r) << 10);
        __syncwarp();
#pragma unroll
        for (int i = 0; i < 16; i++) {
            float p0 = v[i].x * inv, p1 = v[i].y * inv;
            int c = lane * 2 + 64 * i;
            *reinterpret_cast<__half2*>(Pout + pbase + c) = __floats2half2_rn(p0, p1);
            unsigned short h0, l0, h1, l1;
            split_bf16(p0, h0, l0); split_bf16(p1, h1, l1);
            *reinterpret_cast<uint32_t*>(rowp + c * 2) = pack2u(h0, h1);
            *reinterpret_cast<uint32_t*>(rowp + 2048 + c * 2) = pack2u(l0, l1);
        }
    }
    __syncthreads();

    // ---------------- phase 3: ctx = P V ----------------
    stageV(0, sb + FA_KV0);
    const int wm2 = wid & 1, wn2 = wid >> 1;     // 2M x 4N, warp tile 16x16
    const uint32_t aPh = sb + (uint32_t)((wm2 * 16 + (lane & 15)) * SROWB + (lane >> 4) * 16);
    const uint32_t aPl = aPh + 2048;

    float acc2[2][4];
#pragma unroll
    for (int j = 0; j < 2; j++)
#pragma unroll
        for (int l = 0; l < 4; l++) acc2[j][l] = 0.0f;

    for (int vt = 0; vt < 8; vt++) {
        uint32_t buf = sb + ((vt & 1) ? FA_KV1 : FA_KV0);
        if (vt < 7) { stageV(vt + 1, sb + ((vt & 1) ? FA_KV0 : FA_KV1)); CP_WAIT(1); }
        else { CP_WAIT(0); }
        __syncthreads();

        const uint32_t bVh = buf + (uint32_t)((wn2 * 16 + (lane & 15)) * 272 + (lane >> 4) * 16);
        const uint32_t bVl = bVh + 17408;
#pragma unroll
        for (int ks = 0; ks < 8; ks++) {
            const uint32_t ko = ks * 32;
            uint32_t ahi[4], alo[4], bhi[4], blo[4];
            ldm_x4(ahi, aPh + vt * 256 + ko);
            ldm_x4(alo, aPl + vt * 256 + ko);
            ldm_x4(bhi, bVh + ko);
            ldm_x4(blo, bVl + ko);
#pragma unroll
            for (int nh = 0; nh < 2; nh++) {
                float* cc = acc2[nh];
                mma16816(cc, ahi, bhi[nh], bhi[nh + 2]);
                mma16816(cc, ahi, blo[nh], blo[nh + 2]);
                mma16816(cc, alo, bhi[nh], bhi[nh + 2]);
            }
        }
        __syncthreads();
    }

    // epilogue: ctx bf16 hi/lo [(b*1024 + q)*1024 + h*64 + d]
    const int r0 = wm2 * 16 + (lane >> 2);
#pragma unroll
    for (int nh = 0; nh < 2; nh++) {
        int gc = wn2 * 16 + nh * 8 + ((lane & 3) << 1);
#pragma unroll
        for (int half = 0; half < 2; half++) {
            int gr = q0 + r0 + half * 8;
            float v0 = acc2[nh][half * 2 + 0];
            float v1 = acc2[nh][half * 2 + 1];
            size_t idx = (((size_t)(b << 10) + gr) << 10) + (h << 6) + gc;
            unsigned short h0, h1, l0, l1;
            split_bf16(v0, h0, l0); split_bf16(v1, h1, l1);
            *reinterpret_cast<uint32_t*>(Chi + idx) = pack2u(h0, h1);
            *reinterpret_cast<uint32_t*>(Clo + idx) = pack2u(l0, l1);
        }
    }
}

// ---------------------------------------------------------------------------
// attn_mean[b,q,k] = (1/16) * sum_h P16
// ---------------------------------------------------------------------------
__global__ void __launch_bounds__(256)
attn_mean_kernel(const __half* __restrict__ P, float* __restrict__ out)
{
    size_t idx = (size_t)blockIdx.x * 256 + threadIdx.x;
    size_t e0 = idx << 2;
    int b = (int)(e0 >> 20);
    size_t rem = e0 & 1048575;
    float a0 = 0.f, a1 = 0.f, a2 = 0.f, a3 = 0.f;
#pragma unroll
    for (int h = 0; h < 16; h++) {
        const __half2* p = reinterpret_cast<const __half2*>(
            P + (((size_t)(b * 16 + h)) << 20) + rem);
        float2 x = __half22float2(p[0]);
        float2 y = __half22float2(p[1]);
        a0 += x.x; a1 += x.y; a2 += y.x; a3 += y.y;
    }
    const float s = 1.0f / 16.0f;
    *reinterpret_cast<float4*>(out + e0) = make_float4(a0 * s, a1 * s, a2 * s, a3 * s);
}

// ---------------------------------------------------------------------------
// kernel_launch. Inputs: x, Wq, bq, Wk, bk, Wv, bv, Wo, bo
// Output: out [4,1024,1024] fp32 then attn_mean [4,1024,1024] fp32
// ---------------------------------------------------------------------------
extern "C" void kernel_launch(void* const* d_in, const int* in_sizes, int n_in,
                              void* d_out, int out_size)
{
    (void)in_sizes; (void)n_in; (void)out_size;
    const float* x  = (const float*)d_in[0];
    const float* Wq = (const float*)d_in[1];
    const float* bq = (const float*)d_in[2];
    const float* Wk = (const float*)d_in[3];
    const float* bk = (const float*)d_in[4];
    const float* Wv = (const float*)d_in[5];
    const float* bv = (const float*)d_in[6];
    const float* Wo = (const float*)d_in[7];
    const float* bo = (const float*)d_in[8];
    float* out     = (float*)d_out;
    float* outAttn = out + 4194304;

    char* hp = nullptr;
    cudaGetSymbolAddress((void**)&hp, g_heap);
    __nv_bfloat16* Xhi   = (__nv_bfloat16*)(hp + OFF_XHI);
    __nv_bfloat16* Xlo   = (__nv_bfloat16*)(hp + OFF_XLO);
    __nv_bfloat16* WqThi = (__nv_bfloat16*)(hp + OFF_WQTHI);
    __nv_bfloat16* WqTlo = (__nv_bfloat16*)(hp + OFF_WQTLO);
    __nv_bfloat16* WkThi = (__nv_bfloat16*)(hp + OFF_WKTHI);
    __nv_bfloat16* WkTlo = (__nv_bfloat16*)(hp + OFF_WKTLO);
    __nv_bfloat16* WoThi = (__nv_bfloat16*)(hp + OFF_WOTHI);
    __nv_bfloat16* WoTlo = (__nv_bfloat16*)(hp + OFF_WOTLO);
    __nv_bfloat16* WvThi = (__nv_bfloat16*)(hp + OFF_WVTHI);
    __nv_bfloat16* WvTlo = (__nv_bfloat16*)(hp + OFF_WVTLO);
    __nv_bfloat16* Qhi   = (__nv_bfloat16*)(hp + OFF_QHI);
    __nv_bfloat16* Qlo   = (__nv_bfloat16*)(hp + OFF_QLO);
    __nv_bfloat16* Khi   = (__nv_bfloat16*)(hp + OFF_KHI);
    __nv_bfloat16* Klo   = (__nv_bfloat16*)(hp + OFF_KLO);
    __nv_bfloat16* Vthi  = (__nv_bfloat16*)(hp + OFF_VTHI);
    __nv_bfloat16* Vtlo  = (__nv_bfloat16*)(hp + OFF_VTLO);
    __nv_bfloat16* Chi   = (__nv_bfloat16*)(hp + OFF_CHI);
    __nv_bfloat16* Clo   = (__nv_bfloat16*)(hp + OFF_CLO);
    __half*        P16   = (__half*)(hp + OFF_P16);

    cudaFuncSetAttribute(gemm_bf16x3<64>,  cudaFuncAttributeMaxDynamicSharedMemorySize, SMEM64);
    cudaFuncSetAttribute(gemm_bf16x3<128>, cudaFuncAttributeMaxDynamicSharedMemorySize, SMEM128);
    cudaFuncSetAttribute(fused_attn, cudaFuncAttributeMaxDynamicSharedMemorySize, FA_SMEM);

    // conversions
    conv_split<<<4096, 256>>>(x, Xhi, Xlo, 1048576);
    convT_split<<<dim3(32, 32), dim3(32, 8)>>>(Wq, WqThi, WqTlo, 1024, 1024);
    convT_split<<<dim3(32, 32), dim3(32, 8)>>>(Wk, WkThi, WkTlo, 1024, 1024);
    convT_split<<<dim3(32, 32), dim3(32, 8)>>>(Wo, WoThi, WoTlo, 1024, 1024);
    convT_split<<<dim3(2, 32),  dim3(32, 8)>>>(Wv, WvThi, WvTlo, 1024, 64);

    // Q projection (scale 1/8 folded) -> head-split bf16 hi/lo
    gemm_bf16x3<128><<<dim3(8, 32, 1), 256, SMEM128>>>(
        Xhi, Xlo, 0, 1024, WqThi, WqTlo, 0, 1, 1024, 1024,
        bq, 0.125f, nullptr, 0, 0, Qhi, Qlo, 1);
    // K projection -> head-split bf16 hi/lo
    gemm_bf16x3<128><<<dim3(8, 32, 1), 256, SMEM128>>>(
        Xhi, Xlo, 0, 1024, WkThi, WkTlo, 0, 1, 1024, 1024,
        bk, 1.0f, nullptr, 0, 0, Khi, Klo, 1);
    // V projection -> V^T [b,d,t] bf16 hi/lo
    gemm_bf16x3<64><<<dim3(1, 32, 1), 256, SMEM64>>>(
        Xhi, Xlo, 0, 1024, WvThi, WvTlo, 0, 1, 1024, 1024,
        bv, 1.0f, nullptr, 0, 0, Vthi, Vtlo, 2);
    // fused attention: S + softmax + P fp16 + ctx
    fused_attn<<<dim3(32, 64), 256, FA_SMEM>>>(
        Qhi, Qlo, Khi, Klo, Vthi, Vtlo, P16, Chi, Clo);
    // attn_mean
    attn_mean_kernel<<<4096, 256>>>(P16, outAttn);
    // out = ctx @ Wo + bo -> fp32 d_out
    gemm_bf16x3<128><<<dim3(8, 32, 1), 256, SMEM128>>>(
        Chi, Clo, 0, 1024, WoThi, WoTlo, 0, 1, 1024, 1024,
        bo, 1.0f, out, 0, 1024, nullptr, nullptr, 0);
}

// round 7
// speedup vs baseline: 1.0877x; 1.0111x over previous
#include <cuda_runtime.h>
#include <cuda_bf16.h>
#include <cuda_fp16.h>
#include <cstdint>
#include <cstddef>

// Problem constants: B=4, T=1024, D=1024, H=16, DH=64
#define MB ((size_t)1 << 20)

// ---------------------------------------------------------------------------
// Static device heap (no runtime allocation). Offsets in bytes.
// ---------------------------------------------------------------------------
#define OFF_XHI   (0 * MB)
#define OFF_XLO   (8 * MB)
#define OFF_WQTHI (16 * MB)
#define OFF_WQTLO (18 * MB)
#define OFF_WKTHI (20 * MB)
#define OFF_WKTLO (22 * MB)
#define OFF_WOTHI (24 * MB)
#define OFF_WOTLO (26 * MB)
#define OFF_WVTHI (28 * MB)
#define OFF_WVTLO (28 * MB + 131072)
#define OFF_QHI   (29 * MB)
#define OFF_QLO   (37 * MB)
#define OFF_KHI   (45 * MB)
#define OFF_KLO   (53 * MB)
#define OFF_VTHI  (61 * MB)
#define OFF_VTLO  (61 * MB + 524288)
#define OFF_CHI   (62 * MB)
#define OFF_CLO   (70 * MB)
#define OFF_P16   (78 * MB)          // probs fp16 [bh,q,k]  128 MB
#define HEAP_BYTES (206 * MB)

__device__ char g_heap[HEAP_BYTES];

// ---------------------------------------------------------------------------
// PTX helpers (Ampere-compatible: ldmatrix / mma.sync / cp.async)
// ---------------------------------------------------------------------------
__device__ __forceinline__ uint32_t smem_u32(const void* p) {
    uint32_t a;
    asm("{ .reg .u64 t; cvta.to.shared.u64 t, %1; cvt.u32.u64 %0, t; }" : "=r"(a) : "l"(p));
    return a;
}
__device__ __forceinline__ void ldm_x4(uint32_t* r, uint32_t addr) {
    asm volatile("ldmatrix.sync.aligned.m8n8.x4.shared.b16 {%0,%1,%2,%3}, [%4];"
                 : "=r"(r[0]), "=r"(r[1]), "=r"(r[2]), "=r"(r[3]) : "r"(addr));
}
__device__ __forceinline__ void mma16816(float* c, const uint32_t* a,
                                         uint32_t b0, uint32_t b1) {
    asm volatile(
        "mma.sync.aligned.m16n8k16.row.col.f32.bf16.bf16.f32 "
        "{%0,%1,%2,%3}, {%4,%5,%6,%7}, {%8,%9}, {%0,%1,%2,%3};"
        : "+f"(c[0]), "+f"(c[1]), "+f"(c[2]), "+f"(c[3])
        : "r"(a[0]), "r"(a[1]), "r"(a[2]), "r"(a[3]), "r"(b0), "r"(b1));
}
__device__ __forceinline__ void cpa16(uint32_t saddr, const void* g) {
    asm volatile("cp.async.cg.shared.global [%0], [%1], 16;" :: "r"(saddr), "l"(g));
}
#define CP_COMMIT() asm volatile("cp.async.commit_group;" ::: "memory")
#define CP_WAIT(N)  asm volatile("cp.async.wait_group %0;" :: "n"(N) : "memory")

// bf16 split helpers ---------------------------------------------------------
__device__ __forceinline__ void split_bf16(float v, unsigned short& h, unsigned short& l) {
    __nv_bfloat16 bh = __float2bfloat16(v);
    float r = v - __bfloat162float(bh);
    h = __bfloat16_as_ushort(bh);
    l = __bfloat16_as_ushort(__float2bfloat16(r));
}
__device__ __forceinline__ uint32_t pack2u(unsigned short a, unsigned short b) {
    return (uint32_t)a | ((uint32_t)b << 16);
}
__device__ __forceinline__ uint2 pack4u(unsigned short a, unsigned short b,
                                        unsigned short c, unsigned short d) {
    return make_uint2(pack2u(a, b), pack2u(c, d));
}

// ---------------------------------------------------------------------------
// Conversion kernels
// ---------------------------------------------------------------------------
__global__ void __launch_bounds__(256)
conv_split(const float* __restrict__ x, __nv_bfloat16* __restrict__ hi,
           __nv_bfloat16* __restrict__ lo, int n4)
{
    int i = blockIdx.x * 256 + threadIdx.x;
    if (i >= n4) return;
    float4 v = reinterpret_cast<const float4*>(x)[i];
    unsigned short h0, h1, h2, h3, l0, l1, l2, l3;
    split_bf16(v.x, h0, l0); split_bf16(v.y, h1, l1);
    split_bf16(v.z, h2, l2); split_bf16(v.w, h3, l3);
    reinterpret_cast<uint2*>(hi)[i] = pack4u(h0, h1, h2, h3);
    reinterpret_cast<uint2*>(lo)[i] = pack4u(l0, l1, l2, l3);
}

// W [K,N] row-major -> W^T hi/lo bf16 [N,K]
__global__ void __launch_bounds__(256)
convT_split(const float* __restrict__ W, __nv_bfloat16* __restrict__ Thi,
            __nv_bfloat16* __restrict__ Tlo, int K, int N)
{
    __shared__ float sm[32][33];
    int n0 = blockIdx.x * 32, k0 = blockIdx.y * 32;
    int tx = threadIdx.x, ty = threadIdx.y;       // (32, 8)
#pragma unroll
    for (int i = 0; i < 32; i += 8)
        sm[ty + i][tx] = W[(size_t)(k0 + ty + i) * N + n0 + tx];
    __syncthreads();
#pragma unroll
    for (int i = 0; i < 32; i += 8) {
        float v = sm[tx][ty + i];
        unsigned short h, l;
        split_bf16(v, h, l);
        size_t o = (size_t)(n0 + ty + i) * K + k0 + tx;
        Thi[o] = __ushort_as_bfloat16(h);
        Tlo[o] = __ushort_as_bfloat16(l);
    }
}

// ---------------------------------------------------------------------------
// bf16x3 GEMM via mma.sync (HMMA):  D[m,n] = sum_k A[m,k]*B[n,k]
// Block 128 x NT x 32, 512 threads, 16 warps (4M x 4N), warp tile 32 x NT/4.
// 3-stage cp.async pipeline.
// Epilogue modes:
//   0: fp32 row-major (+bias,*scale)
//   1: head-split bf16 hi/lo (+bias,*scale):  [b,h,t,d]
//   2: V^T bf16 hi/lo (+bias):  [b, col, t]
// ---------------------------------------------------------------------------
#define APAD 80                 // 32 bf16 = 64B payload, padded to 80B
#define A_TERM (128 * APAD)     // 10240

template <int NT>
__global__ void __launch_bounds__(512)
gemm_bf16x3(const __nv_bfloat16* __restrict__ Ahi, const __nv_bfloat16* __restrict__ Alo,
            size_t aBS, int lda,
            const __nv_bfloat16* __restrict__ Bhi, const __nv_bfloat16* __restrict__ Blo,
            size_t bBS, int bDiv, int ldb,
            int K,
            const float* __restrict__ bias, float scale,
            float* __restrict__ outF, size_t outBS, int ldOut,
            __nv_bfloat16* __restrict__ outHi, __nv_bfloat16* __restrict__ outLo,
            int mode)
{
    constexpr int B_TERM = NT * APAD;
    constexpr int STAGE  = 2 * A_TERM + 2 * B_TERM;
    constexpr int W      = NT / 4;     // warp n-width
    constexpr int NTB    = W / 16;     // 16-col blocks per warp (2 for NT=128, 1 for 64)

    extern __shared__ __align__(16) char smem[];
    const uint32_t sbase = smem_u32(smem);
    const int tid  = threadIdx.x;
    const int lane = tid & 31;
    const int wid  = tid >> 5;         // 0..15
    const int wm   = wid & 3;          // 4 M
    const int wn   = wid >> 2;         // 4 N
    const int m0   = blockIdx.y * 128;
    const int n0   = blockIdx.x * NT;
    const int z    = blockIdx.z;

    const __nv_bfloat16* Ah = Ahi + (size_t)z * aBS;
    const __nv_bfloat16* Al = Alo + (size_t)z * aBS;
    const __nv_bfloat16* Bh = Bhi + (size_t)(z / bDiv) * bBS;
    const __nv_bfloat16* Bl = Blo + (size_t)(z / bDiv) * bBS;

    const int sRow = tid >> 2;         // 0..127
    const int slot = tid & 3;

    const uint32_t aLdmOff = (uint32_t)((wm * 32 + (lane & 15)) * APAD + (lane >> 4) * 16);
    const uint32_t bLdmOff = (uint32_t)((wn * W  + (lane & 15)) * APAD + (lane >> 4) * 16);

    float acc[2][NTB][2][4];
#pragma unroll
    for (int i = 0; i < 2; i++)
#pragma unroll
        for (int j = 0; j < NTB; j++)
#pragma unroll
            for (int k = 0; k < 2; k++)
#pragma unroll
                for (int l = 0; l < 4; l++) acc[i][j][k][l] = 0.0f;

    const int nc = K >> 5;

    auto stage_chunk = [&](int c) {
        const int k0 = c << 5;
        const uint32_t buf = sbase + (uint32_t)((c % 3) * STAGE);
        {
            size_t go = (size_t)(m0 + sRow) * lda + k0 + slot * 8;
            uint32_t so = buf + (uint32_t)(sRow * APAD + slot * 16);
            cpa16(so, Ah + go);
            cpa16(so + A_TERM, Al + go);
        }
        for (int r = sRow; r < NT; r += 128) {
            size_t go = (size_t)(n0 + r) * ldb + k0 + slot * 8;
            uint32_t so = buf + 2 * A_TERM + (uint32_t)(r * APAD + slot * 16);
            cpa16(so, Bh + go);
            cpa16(so + B_TERM, Bl + go);
        }
        CP_COMMIT();
    };

    stage_chunk(0);
    if (nc > 1) stage_chunk(1);

    for (int c = 0; c < nc; c++) {
        if (c + 2 < nc) { stage_chunk(c + 2); CP_WAIT(2); }
        else if (c + 1 < nc) { CP_WAIT(1); }
        else { CP_WAIT(0); }
        __syncthreads();

        const uint32_t cbuf = sbase + (uint32_t)((c % 3) * STAGE);
        const uint32_t aHiB = cbuf + aLdmOff;
        const uint32_t aLoB = cbuf + A_TERM + aLdmOff;
        const uint32_t bHiB = cbuf + 2 * A_TERM + bLdmOff;
        const uint32_t bLoB = cbuf + 2 * A_TERM + B_TERM + bLdmOff;

#pragma unroll
        for (int ks = 0; ks < 2; ks++) {
            const uint32_t ko = ks * 32;
            uint32_t ahi[2][4], alo[2][4], bhi[NTB][4], blo[NTB][4];
            ldm_x4(ahi[0], aHiB + ko);
            ldm_x4(ahi[1], aHiB + ko + 16 * APAD);
            ldm_x4(alo[0], aLoB + ko);
            ldm_x4(alo[1], aLoB + ko + 16 * APAD);
#pragma unroll
            for (int nt = 0; nt < NTB; nt++) {
                ldm_x4(bhi[nt], bHiB + ko + nt * 16 * APAD);
                ldm_x4(blo[nt], bLoB + ko + nt * 16 * APAD);
            }
#pragma unroll
            for (int mt = 0; mt < 2; mt++)
#pragma unroll
                for (int nt = 0; nt < NTB; nt++)
#pragma unroll
                    for (int nh = 0; nh < 2; nh++) {
                        float* cc = acc[mt][nt][nh];
                        mma16816(cc, ahi[mt], bhi[nt][nh], bhi[nt][nh + 2]);
                        mma16816(cc, ahi[mt], blo[nt][nh], blo[nt][nh + 2]);
                        mma16816(cc, alo[mt], bhi[nt][nh], bhi[nt][nh + 2]);
                    }
        }
        __syncthreads();
    }

    // ---- epilogue ----
    const int rr = lane >> 2;
    const int cc2 = (lane & 3) << 1;
#pragma unroll
    for (int mt = 0; mt < 2; mt++)
#pragma unroll
        for (int nt = 0; nt < NTB; nt++)
#pragma unroll
            for (int nh = 0; nh < 2; nh++) {
                const float* cv = acc[mt][nt][nh];
                int gc = n0 + wn * W + nt * 16 + nh * 8 + cc2;
                float b0 = 0.f, b1 = 0.f;
                if (bias) { b0 = bias[gc]; b1 = bias[gc + 1]; }
#pragma unroll
                for (int half = 0; half < 2; half++) {
                    int gr = m0 + wm * 32 + mt * 16 + rr + half * 8;
                    float v0 = (cv[half * 2 + 0] + b0) * scale;
                    float v1 = (cv[half * 2 + 1] + b1) * scale;
                    if (mode == 0) {
                        float* p = outF + (size_t)z * outBS + (size_t)gr * ldOut + gc;
                        *reinterpret_cast<float2*>(p) = make_float2(v0, v1);
                    } else if (mode == 1) {
                        int bb = gr >> 10, t = gr & 1023;
                        int h = gc >> 6, d = gc & 63;
                        size_t idx = ((size_t)((bb << 4) + h) << 16) + ((size_t)t << 6) + d;
                        unsigned short h0, h1, l0, l1;
                        split_bf16(v0, h0, l0); split_bf16(v1, h1, l1);
                        *reinterpret_cast<uint32_t*>(outHi + idx) = pack2u(h0, h1);
                        *reinterpret_cast<uint32_t*>(outLo + idx) = pack2u(l0, l1);
                    } else { // mode 2
                        int bb = gr >> 10, t = gr & 1023;
                        unsigned short h0, h1, l0, l1;
                        split_bf16(v0, h0, l0); split_bf16(v1, h1, l1);
                        size_t i0 = ((size_t)bb << 16) + ((size_t)gc << 10) + t;
                        outHi[i0] = __ushort_as_bfloat16(h0);
                        outLo[i0] = __ushort_as_bfloat16(l0);
                        outHi[i0 + 1024] = __ushort_as_bfloat16(h1);
                        outLo[i0 + 1024] = __ushort_as_bfloat16(l1);
                    }
                }
            }
}

#define SMEM64  (3 * (2 * A_TERM + 2 * 64 * APAD))    // 92160
#define SMEM128 (3 * (2 * A_TERM + 2 * 128 * APAD))   // 122880

// ---------------------------------------------------------------------------
// Fused attention: per CTA = (bh, 32 q rows).  (unchanged from round 6)
// ---------------------------------------------------------------------------
#define SROWB  4112
#define FA_QH  131584
#define FA_QL  (FA_QH + 4608)
#define FA_KV0 (FA_QL + 4608)
#define FA_KVSZ 36864
#define FA_KV1 (FA_KV0 + FA_KVSZ)
#define FA_SMEM (FA_KV1 + FA_KVSZ)   // 214528

__global__ void __launch_bounds__(256)
fused_attn(const __nv_bfloat16* __restrict__ Qhi_, const __nv_bfloat16* __restrict__ Qlo_,
           const __nv_bfloat16* __restrict__ Khi_, const __nv_bfloat16* __restrict__ Klo_,
           const __nv_bfloat16* __restrict__ Vhi_, const __nv_bfloat16* __restrict__ Vlo_,
           __half* __restrict__ Pout,
           __nv_bfloat16* __restrict__ Chi, __nv_bfloat16* __restrict__ Clo)
{
    extern __shared__ __align__(16) char smem[];
    const uint32_t sb = smem_u32(smem);
    const int tid = threadIdx.x, lane = tid & 31, wid = tid >> 5;
    const int q0 = blockIdx.x * 32;
    const int bh = blockIdx.y;
    const int b = bh >> 4, h = bh & 15;

    const __nv_bfloat16* Qh = Qhi_ + ((size_t)bh << 16) + ((size_t)q0 << 6);
    const __nv_bfloat16* Ql = Qlo_ + ((size_t)bh << 16) + ((size_t)q0 << 6);
    const __nv_bfloat16* Kh = Khi_ + ((size_t)bh << 16);
    const __nv_bfloat16* Kl = Klo_ + ((size_t)bh << 16);
    const __nv_bfloat16* Vh = Vhi_ + ((size_t)b << 16);
    const __nv_bfloat16* Vl = Vlo_ + ((size_t)b << 16);

    auto stageK = [&](int kt, uint32_t buf) {
#pragma unroll
        for (int i = 0; i < 4; i++) {
            int idx = tid + i * 256;
            int row = idx >> 3, slot = idx & 7;
            size_t go = ((size_t)(kt * 128 + row) << 6) + slot * 8;
            uint32_t so = buf + (uint32_t)(row * 144 + slot * 16);
            cpa16(so, Kh + go);
            cpa16(so + 18432, Kl + go);
        }
        CP_COMMIT();
    };
    auto stageV = [&](int vt, uint32_t buf) {
#pragma unroll
        for (int i = 0; i < 4; i++) {
            int idx = tid + i * 256;
            int row = idx >> 4, slot = idx & 15;
            size_t go = ((size_t)row << 10) + vt * 128 + slot * 8;
            uint32_t so = buf + (uint32_t)(row * 272 + slot * 16);
            cpa16(so, Vh + go);
            cpa16(so + 17408, Vl + go);
        }
        CP_COMMIT();
    };

    // stage Q (32x64 hi/lo) + first K tile in one group
    {
        int row = tid >> 3, slot = tid & 7;
        size_t go = ((size_t)row << 6) + slot * 8;
        cpa16(sb + FA_QH + (uint32_t)(row * 144 + slot * 16), Qh + go);
        cpa16(sb + FA_QL + (uint32_t)(row * 144 + slot * 16), Ql + go);
    }
    stageK(0, sb + FA_KV0);

    // ---------------- phase 1: S = Q K^T ----------------
    const int wm = wid & 1, wn = wid >> 1;       // 2M x 4N, warp tile 16x32
    const uint32_t aQh = sb + FA_QH + (uint32_t)((wm * 16 + (lane & 15)) * 144 + (lane >> 4) * 16);
    const uint32_t aQl = sb + FA_QL + (uint32_t)((wm * 16 + (lane & 15)) * 144 + (lane >> 4) * 16);

    for (int kt = 0; kt < 8; kt++) {
        uint32_t buf = sb + ((kt & 1) ? FA_KV1 : FA_KV0);
        if (kt < 7) { stageK(kt + 1, sb + ((kt & 1) ? FA_KV0 : FA_KV1)); CP_WAIT(1); }
        else { CP_WAIT(0); }
        __syncthreads();

        float acc[2][2][4];
#pragma unroll
        for (int i = 0; i < 2; i++)
#pragma unroll
            for (int j = 0; j < 2; j++)
#pragma unroll
                for (int l = 0; l < 4; l++) acc[i][j][l] = 0.0f;

        const uint32_t bKh = buf + (uint32_t)((wn * 32 + (lane & 15)) * 144 + (lane >> 4) * 16);
        const uint32_t bKl = bKh + 18432;
#pragma unroll
        for (int ks = 0; ks < 4; ks++) {
            const uint32_t ko = ks * 32;
            uint32_t ahi[4], alo[4], bhi[2][4], blo[2][4];
            ldm_x4(ahi, aQh + ko);
            ldm_x4(alo, aQl + ko);
            ldm_x4(bhi[0], bKh + ko);
            ldm_x4(bhi[1], bKh + ko + 16 * 144);
            ldm_x4(blo[0], bKl + ko);
            ldm_x4(blo[1], bKl + ko + 16 * 144);
#pragma unroll
            for (int nt = 0; nt < 2; nt++)
#pragma unroll
                for (int nh = 0; nh < 2; nh++) {
                    float* cc = acc[nt][nh];
                    mma16816(cc, ahi, bhi[nt][nh], bhi[nt][nh + 2]);
                    mma16816(cc, ahi, blo[nt][nh], blo[nt][nh + 2]);
                    mma16816(cc, alo, bhi[nt][nh], bhi[nt][nh + 2]);
                }
        }
        // write S tile to strip
        const int r0 = wm * 16 + (lane >> 2);
#pragma unroll
        for (int nt = 0; nt < 2; nt++)
#pragma unroll
            for (int nh = 0; nh < 2; nh++) {
                int col = kt * 128 + wn * 32 + nt * 16 + nh * 8 + ((lane & 3) << 1);
                *reinterpret_cast<float2*>(smem + r0 * SROWB + col * 4) =
                    make_float2(acc[nt][nh][0], acc[nt][nh][1]);
                *reinterpret_cast<float2*>(smem + (r0 + 8) * SROWB + col * 4) =
                    make_float2(acc[nt][nh][2], acc[nt][nh][3]);
            }
        __syncthreads();
    }

    // ---------------- phase 2: softmax + P conversion ----------------
#pragma unroll 1
    for (int rr = 0; rr < 4; rr++) {
        const int r = wid * 4 + rr;
        char* rowp = smem + r * SROWB;
        float2 v[16];
        float m = -1e30f;
#pragma unroll
        for (int i = 0; i < 16; i++) {
            v[i] = *reinterpret_cast<const float2*>(rowp + ((lane * 2 + 64 * i) << 2));
            m = fmaxf(m, fmaxf(v[i].x, v[i].y));
        }
#pragma unroll
        for (int o = 16; o; o >>= 1) m = fmaxf(m, __shfl_xor_sync(0xffffffffu, m, o));
        float s = 0.0f;
#pragma unroll
        for (int i = 0; i < 16; i++) {
            v[i].x = __expf(v[i].x - m);
            v[i].y = __expf(v[i].y - m);
            s += v[i].x + v[i].y;
        }
#pragma unroll
        for (int o = 16; o; o >>= 1) s += __shfl_xor_sync(0xffffffffu, s, o);
        const float inv = 1.0f / s;
        const size_t pbase = ((size_t)bh << 20) + ((size_t)(q0 + r) << 10);
        __syncwarp();
#pragma unroll
        for (int i = 0; i < 16; i++) {
            float p0 = v[i].x * inv, p1 = v[i].y * inv;
            int c = lane * 2 + 64 * i;
            *reinterpret_cast<__half2*>(Pout + pbase + c) = __floats2half2_rn(p0, p1);
            unsigned short h0, l0, h1, l1;
            split_bf16(p0, h0, l0); split_bf16(p1, h1, l1);
            *reinterpret_cast<uint32_t*>(rowp + c * 2) = pack2u(h0, h1);
            *reinterpret_cast<uint32_t*>(rowp + 2048 + c * 2) = pack2u(l0, l1);
        }
    }
    __syncthreads();

    // ---------------- phase 3: ctx = P V ----------------
    stageV(0, sb + FA_KV0);
    const int wm2 = wid & 1, wn2 = wid >> 1;     // 2M x 4N, warp tile 16x16
    const uint32_t aPh = sb + (uint32_t)((wm2 * 16 + (lane & 15)) * SROWB + (lane >> 4) * 16);
    const uint32_t aPl = aPh + 2048;

    float acc2[2][4];
#pragma unroll
    for (int j = 0; j < 2; j++)
#pragma unroll
        for (int l = 0; l < 4; l++) acc2[j][l] = 0.0f;

    for (int vt = 0; vt < 8; vt++) {
        uint32_t buf = sb + ((vt & 1) ? FA_KV1 : FA_KV0);
        if (vt < 7) { stageV(vt + 1, sb + ((vt & 1) ? FA_KV0 : FA_KV1)); CP_WAIT(1); }
        else { CP_WAIT(0); }
        __syncthreads();

        const uint32_t bVh = buf + (uint32_t)((wn2 * 16 + (lane & 15)) * 272 + (lane >> 4) * 16);
        const uint32_t bVl = bVh + 17408;
#pragma unroll
        for (int ks = 0; ks < 8; ks++) {
            const uint32_t ko = ks * 32;
            uint32_t ahi[4], alo[4], bhi[4], blo[4];
            ldm_x4(ahi, aPh + vt * 256 + ko);
            ldm_x4(alo, aPl + vt * 256 + ko);
            ldm_x4(bhi, bVh + ko);
            ldm_x4(blo, bVl + ko);
#pragma unroll
            for (int nh = 0; nh < 2; nh++) {
                float* cc = acc2[nh];
                mma16816(cc, ahi, bhi[nh], bhi[nh + 2]);
                mma16816(cc, ahi, blo[nh], blo[nh + 2]);
                mma16816(cc, alo, bhi[nh], bhi[nh + 2]);
            }
        }
        __syncthreads();
    }

    // epilogue: ctx bf16 hi/lo [(b*1024 + q)*1024 + h*64 + d]
    const int r0 = wm2 * 16 + (lane >> 2);
#pragma unroll
    for (int nh = 0; nh < 2; nh++) {
        int gc = wn2 * 16 + nh * 8 + ((lane & 3) << 1);
#pragma unroll
        for (int half = 0; half < 2; half++) {
            int gr = q0 + r0 + half * 8;
            float v0 = acc2[nh][half * 2 + 0];
            float v1 = acc2[nh][half * 2 + 1];
            size_t idx = (((size_t)(b << 10) + gr) << 10) + (h << 6) + gc;
            unsigned short h0, h1, l0, l1;
            split_bf16(v0, h0, l0); split_bf16(v1, h1, l1);
            *reinterpret_cast<uint32_t*>(Chi + idx) = pack2u(h0, h1);
            *reinterpret_cast<uint32_t*>(Clo + idx) = pack2u(l0, l1);
        }
    }
}

// ---------------------------------------------------------------------------
// attn_mean[b,q,k] = (1/16) * sum_h P16
// ---------------------------------------------------------------------------
__global__ void __launch_bounds__(256)
attn_mean_kernel(const __half* __restrict__ P, float* __restrict__ out)
{
    size_t idx = (size_t)blockIdx.x * 256 + threadIdx.x;
    size_t e0 = idx << 2;
    int b = (int)(e0 >> 20);
    size_t rem = e0 & 1048575;
    float a0 = 0.f, a1 = 0.f, a2 = 0.f, a3 = 0.f;
#pragma unroll
    for (int h = 0; h < 16; h++) {
        const __half2* p = reinterpret_cast<const __half2*>(
            P + (((size_t)(b * 16 + h)) << 20) + rem);
        float2 x = __half22float2(p[0]);
        float2 y = __half22float2(p[1]);
        a0 += x.x; a1 += x.y; a2 += y.x; a3 += y.y;
    }
    const float s = 1.0f / 16.0f;
    *reinterpret_cast<float4*>(out + e0) = make_float4(a0 * s, a1 * s, a2 * s, a3 * s);
}

// ---------------------------------------------------------------------------
// kernel_launch. Inputs: x, Wq, bq, Wk, bk, Wv, bv, Wo, bo
// Output: out [4,1024,1024] fp32 then attn_mean [4,1024,1024] fp32
// ---------------------------------------------------------------------------
extern "C" void kernel_launch(void* const* d_in, const int* in_sizes, int n_in,
                              void* d_out, int out_size)
{
    (void)in_sizes; (void)n_in; (void)out_size;
    const float* x  = (const float*)d_in[0];
    const float* Wq = (const float*)d_in[1];
    const float* bq = (const float*)d_in[2];
    const float* Wk = (const float*)d_in[3];
    const float* bk = (const float*)d_in[4];
    const float* Wv = (const float*)d_in[5];
    const float* bv = (const float*)d_in[6];
    const float* Wo = (const float*)d_in[7];
    const float* bo = (const float*)d_in[8];
    float* out     = (float*)d_out;
    float* outAttn = out + 4194304;

    char* hp = nullptr;
    cudaGetSymbolAddress((void**)&hp, g_heap);
    __nv_bfloat16* Xhi   = (__nv_bfloat16*)(hp + OFF_XHI);
    __nv_bfloat16* Xlo   = (__nv_bfloat16*)(hp + OFF_XLO);
    __nv_bfloat16* WqThi = (__nv_bfloat16*)(hp + OFF_WQTHI);
    __nv_bfloat16* WqTlo = (__nv_bfloat16*)(hp + OFF_WQTLO);
    __nv_bfloat16* WkThi = (__nv_bfloat16*)(hp + OFF_WKTHI);
    __nv_bfloat16* WkTlo = (__nv_bfloat16*)(hp + OFF_WKTLO);
    __nv_bfloat16* WoThi = (__nv_bfloat16*)(hp + OFF_WOTHI);
    __nv_bfloat16* WoTlo = (__nv_bfloat16*)(hp + OFF_WOTLO);
    __nv_bfloat16* WvThi = (__nv_bfloat16*)(hp + OFF_WVTHI);
    __nv_bfloat16* WvTlo = (__nv_bfloat16*)(hp + OFF_WVTLO);
    __nv_bfloat16* Qhi   = (__nv_bfloat16*)(hp + OFF_QHI);
    __nv_bfloat16* Qlo   = (__nv_bfloat16*)(hp + OFF_QLO);
    __nv_bfloat16* Khi   = (__nv_bfloat16*)(hp + OFF_KHI);
    __nv_bfloat16* Klo   = (__nv_bfloat16*)(hp + OFF_KLO);
    __nv_bfloat16* Vthi  = (__nv_bfloat16*)(hp + OFF_VTHI);
    __nv_bfloat16* Vtlo  = (__nv_bfloat16*)(hp + OFF_VTLO);
    __nv_bfloat16* Chi   = (__nv_bfloat16*)(hp + OFF_CHI);
    __nv_bfloat16* Clo   = (__nv_bfloat16*)(hp + OFF_CLO);
    __half*        P16   = (__half*)(hp + OFF_P16);

    cudaFuncSetAttribute(gemm_bf16x3<64>,  cudaFuncAttributeMaxDynamicSharedMemorySize, SMEM64);
    cudaFuncSetAttribute(gemm_bf16x3<128>, cudaFuncAttributeMaxDynamicSharedMemorySize, SMEM128);
    cudaFuncSetAttribute(fused_attn, cudaFuncAttributeMaxDynamicSharedMemorySize, FA_SMEM);

    // conversions
    conv_split<<<4096, 256>>>(x, Xhi, Xlo, 1048576);
    convT_split<<<dim3(32, 32), dim3(32, 8)>>>(Wq, WqThi, WqTlo, 1024, 1024);
    convT_split<<<dim3(32, 32), dim3(32, 8)>>>(Wk, WkThi, WkTlo, 1024, 1024);
    convT_split<<<dim3(32, 32), dim3(32, 8)>>>(Wo, WoThi, WoTlo, 1024, 1024);
    convT_split<<<dim3(2, 32),  dim3(32, 8)>>>(Wv, WvThi, WvTlo, 1024, 64);

    // Q projection (scale 1/8 folded) -> head-split bf16 hi/lo
    gemm_bf16x3<128><<<dim3(8, 32, 1), 512, SMEM128>>>(
        Xhi, Xlo, 0, 1024, WqThi, WqTlo, 0, 1, 1024, 1024,
        bq, 0.125f, nullptr, 0, 0, Qhi, Qlo, 1);
    // K projection -> head-split bf16 hi/lo
    gemm_bf16x3<128><<<dim3(8, 32, 1), 512, SMEM128>>>(
        Xhi, Xlo, 0, 1024, WkThi, WkTlo, 0, 1, 1024, 1024,
        bk, 1.0f, nullptr, 0, 0, Khi, Klo, 1);
    // V projection -> V^T [b,d,t] bf16 hi/lo
    gemm_bf16x3<64><<<dim3(1, 32, 1), 512, SMEM64>>>(
        Xhi, Xlo, 0, 1024, WvThi, WvTlo, 0, 1, 1024, 1024,
        bv, 1.0f, nullptr, 0, 0, Vthi, Vtlo, 2);
    // fused attention: S + softmax + P fp16 + ctx
    fused_attn<<<dim3(32, 64), 256, FA_SMEM>>>(
        Qhi, Qlo, Khi, Klo, Vthi, Vtlo, P16, Chi, Clo);
    // attn_mean
    attn_mean_kernel<<<4096, 256>>>(P16, outAttn);
    // out = ctx @ Wo + bo -> fp32 d_out
    gemm_bf16x3<128><<<dim3(8, 32, 1), 512, SMEM128>>>(
        Chi, Clo, 0, 1024, WoThi, WoTlo, 0, 1, 1024, 1024,
        bo, 1.0f, out, 0, 1024, nullptr, nullptr, 0);
}

// round 8
// speedup vs baseline: 1.3141x; 1.2081x over previous
#include <cuda_runtime.h>
#include <cuda_bf16.h>
#include <cuda_fp16.h>
#include <cstdint>
#include <cstddef>

// Problem constants: B=4, T=1024, D=1024, H=16, DH=64
#define MB ((size_t)1 << 20)

// ---------------------------------------------------------------------------
// Static device heap (no runtime allocation). Offsets in bytes.
// ---------------------------------------------------------------------------
#define OFF_XHI   (0 * MB)
#define OFF_XLO   (8 * MB)
#define OFF_WQTHI (16 * MB)
#define OFF_WQTLO (18 * MB)
#define OFF_WKTHI (20 * MB)
#define OFF_WKTLO (22 * MB)
#define OFF_WOTHI (24 * MB)
#define OFF_WOTLO (26 * MB)
#define OFF_WVTHI (28 * MB)
#define OFF_WVTLO (28 * MB + 131072)
#define OFF_Q16   (29 * MB)          // Q fp16 head-split [b,h,t,d]   8 MB
#define OFF_K16   (37 * MB)
#define OFF_VT16  (45 * MB)          // V^T fp16 [b,d,t]            512 KB
#define OFF_CHI   (46 * MB)          // ctx bf16 hi                   8 MB
#define OFF_CLO   (54 * MB)
#define OFF_P16   (62 * MB)          // probs fp16 [bh,q,k]         128 MB
#define HEAP_BYTES (190 * MB)

__device__ char g_heap[HEAP_BYTES];

// ---------------------------------------------------------------------------
// PTX helpers (Ampere-compatible: ldmatrix / mma.sync / cp.async)
// ---------------------------------------------------------------------------
__device__ __forceinline__ uint32_t smem_u32(const void* p) {
    uint32_t a;
    asm("{ .reg .u64 t; cvta.to.shared.u64 t, %1; cvt.u32.u64 %0, t; }" : "=r"(a) : "l"(p));
    return a;
}
__device__ __forceinline__ void ldm_x4(uint32_t* r, uint32_t addr) {
    asm volatile("ldmatrix.sync.aligned.m8n8.x4.shared.b16 {%0,%1,%2,%3}, [%4];"
                 : "=r"(r[0]), "=r"(r[1]), "=r"(r[2]), "=r"(r[3]) : "r"(addr));
}
// bf16 MMA (projections)
__device__ __forceinline__ void mma16816(float* c, const uint32_t* a,
                                         uint32_t b0, uint32_t b1) {
    asm volatile(
        "mma.sync.aligned.m16n8k16.row.col.f32.bf16.bf16.f32 "
        "{%0,%1,%2,%3}, {%4,%5,%6,%7}, {%8,%9}, {%0,%1,%2,%3};"
        : "+f"(c[0]), "+f"(c[1]), "+f"(c[2]), "+f"(c[3])
        : "r"(a[0]), "r"(a[1]), "r"(a[2]), "r"(a[3]), "r"(b0), "r"(b1));
}
// fp16 MMA (attention)
__device__ __forceinline__ void mma16816h(float* c, const uint32_t* a,
                                          uint32_t b0, uint32_t b1) {
    asm volatile(
        "mma.sync.aligned.m16n8k16.row.col.f32.f16.f16.f32 "
        "{%0,%1,%2,%3}, {%4,%5,%6,%7}, {%8,%9}, {%0,%1,%2,%3};"
        : "+f"(c[0]), "+f"(c[1]), "+f"(c[2]), "+f"(c[3])
        : "r"(a[0]), "r"(a[1]), "r"(a[2]), "r"(a[3]), "r"(b0), "r"(b1));
}
__device__ __forceinline__ void cpa16(uint32_t saddr, const void* g) {
    asm volatile("cp.async.cg.shared.global [%0], [%1], 16;" :: "r"(saddr), "l"(g));
}
#define CP_COMMIT() asm volatile("cp.async.commit_group;" ::: "memory")
#define CP_WAIT(N)  asm volatile("cp.async.wait_group %0;" :: "n"(N) : "memory")

// bf16 split helpers ---------------------------------------------------------
__device__ __forceinline__ void split_bf16(float v, unsigned short& h, unsigned short& l) {
    __nv_bfloat16 bh = __float2bfloat16(v);
    float r = v - __bfloat162float(bh);
    h = __bfloat16_as_ushort(bh);
    l = __bfloat16_as_ushort(__float2bfloat16(r));
}
__device__ __forceinline__ uint32_t pack2u(unsigned short a, unsigned short b) {
    return (uint32_t)a | ((uint32_t)b << 16);
}
__device__ __forceinline__ uint2 pack4u(unsigned short a, unsigned short b,
                                        unsigned short c, unsigned short d) {
    return make_uint2(pack2u(a, b), pack2u(c, d));
}

// ---------------------------------------------------------------------------
// Conversion kernels
// ---------------------------------------------------------------------------
__global__ void __launch_bounds__(256)
conv_split(const float* __restrict__ x, __nv_bfloat16* __restrict__ hi,
           __nv_bfloat16* __restrict__ lo, int n4)
{
    int i = blockIdx.x * 256 + threadIdx.x;
    if (i >= n4) return;
    float4 v = reinterpret_cast<const float4*>(x)[i];
    unsigned short h0, h1, h2, h3, l0, l1, l2, l3;
    split_bf16(v.x, h0, l0); split_bf16(v.y, h1, l1);
    split_bf16(v.z, h2, l2); split_bf16(v.w, h3, l3);
    reinterpret_cast<uint2*>(hi)[i] = pack4u(h0, h1, h2, h3);
    reinterpret_cast<uint2*>(lo)[i] = pack4u(l0, l1, l2, l3);
}

// W [K,N] row-major -> W^T hi/lo bf16 [N,K]
__global__ void __launch_bounds__(256)
convT_split(const float* __restrict__ W, __nv_bfloat16* __restrict__ Thi,
            __nv_bfloat16* __restrict__ Tlo, int K, int N)
{
    __shared__ float sm[32][33];
    int n0 = blockIdx.x * 32, k0 = blockIdx.y * 32;
    int tx = threadIdx.x, ty = threadIdx.y;       // (32, 8)
#pragma unroll
    for (int i = 0; i < 32; i += 8)
        sm[ty + i][tx] = W[(size_t)(k0 + ty + i) * N + n0 + tx];
    __syncthreads();
#pragma unroll
    for (int i = 0; i < 32; i += 8) {
        float v = sm[tx][ty + i];
        unsigned short h, l;
        split_bf16(v, h, l);
        size_t o = (size_t)(n0 + ty + i) * K + k0 + tx;
        Thi[o] = __ushort_as_bfloat16(h);
        Tlo[o] = __ushort_as_bfloat16(l);
    }
}

// ---------------------------------------------------------------------------
// bf16x3 GEMM via mma.sync (HMMA):  D[m,n] = sum_k A[m,k]*B[n,k]
// Block 128 x NT x 32, 512 threads, 16 warps (4M x 4N). 3-stage cp.async.
// Epilogue modes:
//   0: fp32 row-major (+bias,*scale)
//   1: head-split fp16 (+bias,*scale):  [b,h,t,d]
//   2: V^T fp16 (+bias):  [b, col, t]
// ---------------------------------------------------------------------------
#define APAD 80                 // 32 bf16 = 64B payload, padded to 80B
#define A_TERM (128 * APAD)     // 10240

template <int NT>
__global__ void __launch_bounds__(512)
gemm_bf16x3(const __nv_bfloat16* __restrict__ Ahi, const __nv_bfloat16* __restrict__ Alo,
            size_t aBS, int lda,
            const __nv_bfloat16* __restrict__ Bhi, const __nv_bfloat16* __restrict__ Blo,
            size_t bBS, int bDiv, int ldb,
            int K,
            const float* __restrict__ bias, float scale,
            float* __restrict__ outF, size_t outBS, int ldOut,
            __half* __restrict__ outH,
            int mode)
{
    constexpr int B_TERM = NT * APAD;
    constexpr int STAGE  = 2 * A_TERM + 2 * B_TERM;
    constexpr int W      = NT / 4;
    constexpr int NTB    = W / 16;

    extern __shared__ __align__(16) char smem[];
    const uint32_t sbase = smem_u32(smem);
    const int tid  = threadIdx.x;
    const int lane = tid & 31;
    const int wid  = tid >> 5;
    const int wm   = wid & 3;
    const int wn   = wid >> 2;
    const int m0   = blockIdx.y * 128;
    const int n0   = blockIdx.x * NT;
    const int z    = blockIdx.z;

    const __nv_bfloat16* Ah = Ahi + (size_t)z * aBS;
    const __nv_bfloat16* Al = Alo + (size_t)z * aBS;
    const __nv_bfloat16* Bh = Bhi + (size_t)(z / bDiv) * bBS;
    const __nv_bfloat16* Bl = Blo + (size_t)(z / bDiv) * bBS;

    const int sRow = tid >> 2;
    const int slot = tid & 3;

    const uint32_t aLdmOff = (uint32_t)((wm * 32 + (lane & 15)) * APAD + (lane >> 4) * 16);
    const uint32_t bLdmOff = (uint32_t)((wn * W  + (lane & 15)) * APAD + (lane >> 4) * 16);

    float acc[2][NTB][2][4];
#pragma unroll
    for (int i = 0; i < 2; i++)
#pragma unroll
        for (int j = 0; j < NTB; j++)
#pragma unroll
            for (int k = 0; k < 2; k++)
#pragma unroll
                for (int l = 0; l < 4; l++) acc[i][j][k][l] = 0.0f;

    const int nc = K >> 5;

    auto stage_chunk = [&](int c) {
        const int k0 = c << 5;
        const uint32_t buf = sbase + (uint32_t)((c % 3) * STAGE);
        {
            size_t go = (size_t)(m0 + sRow) * lda + k0 + slot * 8;
            uint32_t so = buf + (uint32_t)(sRow * APAD + slot * 16);
            cpa16(so, Ah + go);
            cpa16(so + A_TERM, Al + go);
        }
        for (int r = sRow; r < NT; r += 128) {
            size_t go = (size_t)(n0 + r) * ldb + k0 + slot * 8;
            uint32_t so = buf + 2 * A_TERM + (uint32_t)(r * APAD + slot * 16);
            cpa16(so, Bh + go);
            cpa16(so + B_TERM, Bl + go);
        }
        CP_COMMIT();
    };

    stage_chunk(0);
    if (nc > 1) stage_chunk(1);

    for (int c = 0; c < nc; c++) {
        if (c + 2 < nc) { stage_chunk(c + 2); CP_WAIT(2); }
        else if (c + 1 < nc) { CP_WAIT(1); }
        else { CP_WAIT(0); }
        __syncthreads();

        const uint32_t cbuf = sbase + (uint32_t)((c % 3) * STAGE);
        const uint32_t aHiB = cbuf + aLdmOff;
        const uint32_t aLoB = cbuf + A_TERM + aLdmOff;
        const uint32_t bHiB = cbuf + 2 * A_TERM + bLdmOff;
        const uint32_t bLoB = cbuf + 2 * A_TERM + B_TERM + bLdmOff;

#pragma unroll
        for (int ks = 0; ks < 2; ks++) {
            const uint32_t ko = ks * 32;
            uint32_t ahi[2][4], alo[2][4], bhi[NTB][4], blo[NTB][4];
            ldm_x4(ahi[0], aHiB + ko);
            ldm_x4(ahi[1], aHiB + ko + 16 * APAD);
            ldm_x4(alo[0], aLoB + ko);
            ldm_x4(alo[1], aLoB + ko + 16 * APAD);
#pragma unroll
            for (int nt = 0; nt < NTB; nt++) {
                ldm_x4(bhi[nt], bHiB + ko + nt * 16 * APAD);
                ldm_x4(blo[nt], bLoB + ko + nt * 16 * APAD);
            }
#pragma unroll
            for (int mt = 0; mt < 2; mt++)
#pragma unroll
                for (int nt = 0; nt < NTB; nt++)
#pragma unroll
                    for (int nh = 0; nh < 2; nh++) {
                        float* cc = acc[mt][nt][nh];
                        mma16816(cc, ahi[mt], bhi[nt][nh], bhi[nt][nh + 2]);
                        mma16816(cc, ahi[mt], blo[nt][nh], blo[nt][nh + 2]);
                        mma16816(cc, alo[mt], bhi[nt][nh], bhi[nt][nh + 2]);
                    }
        }
        __syncthreads();
    }

    // ---- epilogue ----
    const int rr = lane >> 2;
    const int cc2 = (lane & 3) << 1;
#pragma unroll
    for (int mt = 0; mt < 2; mt++)
#pragma unroll
        for (int nt = 0; nt < NTB; nt++)
#pragma unroll
            for (int nh = 0; nh < 2; nh++) {
                const float* cv = acc[mt][nt][nh];
                int gc = n0 + wn * W + nt * 16 + nh * 8 + cc2;
                float b0 = 0.f, b1 = 0.f;
                if (bias) { b0 = bias[gc]; b1 = bias[gc + 1]; }
#pragma unroll
                for (int half = 0; half < 2; half++) {
                    int gr = m0 + wm * 32 + mt * 16 + rr + half * 8;
                    float v0 = (cv[half * 2 + 0] + b0) * scale;
                    float v1 = (cv[half * 2 + 1] + b1) * scale;
                    if (mode == 0) {
                        float* p = outF + (size_t)z * outBS + (size_t)gr * ldOut + gc;
                        *reinterpret_cast<float2*>(p) = make_float2(v0, v1);
                    } else if (mode == 1) {
                        int bb = gr >> 10, t = gr & 1023;
                        int h = gc >> 6, d = gc & 63;
                        size_t idx = ((size_t)((bb << 4) + h) << 16) + ((size_t)t << 6) + d;
                        *reinterpret_cast<__half2*>(outH + idx) = __floats2half2_rn(v0, v1);
                    } else { // mode 2: V^T fp16 [b, col, t]
                        int bb = gr >> 10, t = gr & 1023;
                        size_t i0 = ((size_t)bb << 16) + ((size_t)gc << 10) + t;
                        outH[i0] = __float2half_rn(v0);
                        outH[i0 + 1024] = __float2half_rn(v1);
                    }
                }
            }
}

#define SMEM64  (3 * (2 * A_TERM + 2 * 64 * APAD))    // 92160
#define SMEM128 (3 * (2 * A_TERM + 2 * 128 * APAD))   // 122880

// ---------------------------------------------------------------------------
// Fused attention (fp16 single-product MMA): per CTA = (bh, 32 q rows).
//   S strip (32 x 1024 fp32) via fp16 MMA over 8 key tiles; in-smem softmax;
//   P fp16 in place + fp16 -> gmem; PV fp16 MMA; ctx bf16 hi/lo -> gmem.
// smem: S strip 32x4112, Q 32x144, 2 KV buffers 18432 each = 173056 B.
// ---------------------------------------------------------------------------
#define SROWB  4112
#define FA_Q   131584
#define FA_KV0 (FA_Q + 4608)
#define FA_KVSZ 18432
#define FA_KV1 (FA_KV0 + FA_KVSZ)
#define FA_SMEM (FA_KV1 + FA_KVSZ)   // 173056

__global__ void __launch_bounds__(256)
fused_attn(const __half* __restrict__ Q_, const __half* __restrict__ K_,
           const __half* __restrict__ V_,
           __half* __restrict__ Pout,
           __nv_bfloat16* __restrict__ Chi, __nv_bfloat16* __restrict__ Clo)
{
    extern __shared__ __align__(16) char smem[];
    const uint32_t sb = smem_u32(smem);
    const int tid = threadIdx.x, lane = tid & 31, wid = tid >> 5;
    const int q0 = blockIdx.x * 32;
    const int bh = blockIdx.y;
    const int b = bh >> 4, h = bh & 15;

    const __half* Qg = Q_ + ((size_t)bh << 16) + ((size_t)q0 << 6);
    const __half* Kg = K_ + ((size_t)bh << 16);
    const __half* Vg = V_ + ((size_t)b << 16);

    auto stageK = [&](int kt, uint32_t buf) {
#pragma unroll
        for (int i = 0; i < 4; i++) {
            int idx = tid + i * 256;
            int row = idx >> 3, slot = idx & 7;
            size_t go = ((size_t)(kt * 128 + row) << 6) + slot * 8;
            cpa16(buf + (uint32_t)(row * 144 + slot * 16), Kg + go);
        }
        CP_COMMIT();
    };
    auto stageV = [&](int vt, uint32_t buf) {
#pragma unroll
        for (int i = 0; i < 4; i++) {
            int idx = tid + i * 256;
            int row = idx >> 4, slot = idx & 15;
            size_t go = ((size_t)row << 10) + vt * 128 + slot * 8;
            cpa16(buf + (uint32_t)(row * 272 + slot * 16), Vg + go);
        }
        CP_COMMIT();
    };

    // stage Q (32x64 fp16) + first K tile in one group
    {
        int row = tid >> 3, slot = tid & 7;
        size_t go = ((size_t)row << 6) + slot * 8;
        cpa16(sb + FA_Q + (uint32_t)(row * 144 + slot * 16), Qg + go);
    }
    stageK(0, sb + FA_KV0);

    // ---------------- phase 1: S = Q K^T ----------------
    const int wm = wid & 1, wn = wid >> 1;       // 2M x 4N, warp tile 16x32
    const uint32_t aQ = sb + FA_Q + (uint32_t)((wm * 16 + (lane & 15)) * 144 + (lane >> 4) * 16);

    for (int kt = 0; kt < 8; kt++) {
        uint32_t buf = sb + ((kt & 1) ? FA_KV1 : FA_KV0);
        if (kt < 7) { stageK(kt + 1, sb + ((kt & 1) ? FA_KV0 : FA_KV1)); CP_WAIT(1); }
        else { CP_WAIT(0); }
        __syncthreads();

        float acc[2][2][4];
#pragma unroll
        for (int i = 0; i < 2; i++)
#pragma unroll
            for (int j = 0; j < 2; j++)
#pragma unroll
                for (int l = 0; l < 4; l++) acc[i][j][l] = 0.0f;

        const uint32_t bK = buf + (uint32_t)((wn * 32 + (lane & 15)) * 144 + (lane >> 4) * 16);
#pragma unroll
        for (int ks = 0; ks < 4; ks++) {
            const uint32_t ko = ks * 32;
            uint32_t a[4], b0[4], b1[4];
            ldm_x4(a, aQ + ko);
            ldm_x4(b0, bK + ko);
            ldm_x4(b1, bK + ko + 16 * 144);
#pragma unroll
            for (int nh = 0; nh < 2; nh++) {
                mma16816h(acc[0][nh], a, b0[nh], b0[nh + 2]);
                mma16816h(acc[1][nh], a, b1[nh], b1[nh + 2]);
            }
        }
        // write S tile to strip
        const int r0 = wm * 16 + (lane >> 2);
#pragma unroll
        for (int nt = 0; nt < 2; nt++)
#pragma unroll
            for (int nh = 0; nh < 2; nh++) {
                int col = kt * 128 + wn * 32 + nt * 16 + nh * 8 + ((lane & 3) << 1);
                *reinterpret_cast<float2*>(smem + r0 * SROWB + col * 4) =
                    make_float2(acc[nt][nh][0], acc[nt][nh][1]);
                *reinterpret_cast<float2*>(smem + (r0 + 8) * SROWB + col * 4) =
                    make_float2(acc[nt][nh][2], acc[nt][nh][3]);
            }
        __syncthreads();
    }

    // ---------------- phase 2: softmax + P fp16 (in place + gmem) ----------
#pragma unroll 1
    for (int rr = 0; rr < 4; rr++) {
        const int r = wid * 4 + rr;
        char* rowp = smem + r * SROWB;
        float2 v[16];
        float m = -1e30f;
#pragma unroll
        for (int i = 0; i < 16; i++) {
            v[i] = *reinterpret_cast<const float2*>(rowp + ((lane * 2 + 64 * i) << 2));
            m = fmaxf(m, fmaxf(v[i].x, v[i].y));
        }
#pragma unroll
        for (int o = 16; o; o >>= 1) m = fmaxf(m, __shfl_xor_sync(0xffffffffu, m, o));
        float s = 0.0f;
#pragma unroll
        for (int i = 0; i < 16; i++) {
            v[i].x = __expf(v[i].x - m);
            v[i].y = __expf(v[i].y - m);
            s += v[i].x + v[i].y;
        }
#pragma unroll
        for (int o = 16; o; o >>= 1) s += __shfl_xor_sync(0xffffffffu, s, o);
        const float inv = 1.0f / s;
        const size_t pbase = ((size_t)bh << 20) + ((size_t)(q0 + r) << 10);
        __syncwarp();
#pragma unroll
        for (int i = 0; i < 16; i++) {
            int c = lane * 2 + 64 * i;
            __half2 ph = __floats2half2_rn(v[i].x * inv, v[i].y * inv);
            *reinterpret_cast<__half2*>(Pout + pbase + c) = ph;
            *reinterpret_cast<__half2*>(rowp + c * 2) = ph;
        }
    }
    __syncthreads();

    // ---------------- phase 3: ctx = P V ----------------
    stageV(0, sb + FA_KV0);
    const int wm2 = wid & 1, wn2 = wid >> 1;     // 2M x 4N, warp tile 16x16
    const uint32_t aP = sb + (uint32_t)((wm2 * 16 + (lane & 15)) * SROWB + (lane >> 4) * 16);

    float acc2[2][4];
#pragma unroll
    for (int j = 0; j < 2; j++)
#pragma unroll
        for (int l = 0; l < 4; l++) acc2[j][l] = 0.0f;

    for (int vt = 0; vt < 8; vt++) {
        uint32_t buf = sb + ((vt & 1) ? FA_KV1 : FA_KV0);
        if (vt < 7) { stageV(vt + 1, sb + ((vt & 1) ? FA_KV0 : FA_KV1)); CP_WAIT(1); }
        else { CP_WAIT(0); }
        __syncthreads();

        const uint32_t bV = buf + (uint32_t)((wn2 * 16 + (lane & 15)) * 272 + (lane >> 4) * 16);
#pragma unroll
        for (int ks = 0; ks < 8; ks++) {
            const uint32_t ko = ks * 32;
            uint32_t a[4], bv[4];
            ldm_x4(a, aP + vt * 256 + ko);
            ldm_x4(bv, bV + ko);
            mma16816h(acc2[0], a, bv[0], bv[2]);
            mma16816h(acc2[1], a, bv[1], bv[3]);
        }
        __syncthreads();
    }

    // epilogue: ctx bf16 hi/lo [(b*1024 + q)*1024 + h*64 + d]
    const int r0 = wm2 * 16 + (lane >> 2);
#pragma unroll
    for (int nh = 0; nh < 2; nh++) {
        int gc = wn2 * 16 + nh * 8 + ((lane & 3) << 1);
#pragma unroll
        for (int half = 0; half < 2; half++) {
            int gr = q0 + r0 + half * 8;
            float v0 = acc2[nh][half * 2 + 0];
            float v1 = acc2[nh][half * 2 + 1];
            size_t idx = (((size_t)(b << 10) + gr) << 10) + (h << 6) + gc;
            unsigned short h0, h1, l0, l1;
            split_bf16(v0, h0, l0); split_bf16(v1, h1, l1);
            *reinterpret_cast<uint32_t*>(Chi + idx) = pack2u(h0, h1);
            *reinterpret_cast<uint32_t*>(Clo + idx) = pack2u(l0, l1);
        }
    }
}

// ---------------------------------------------------------------------------
// attn_mean[b,q,k] = (1/16) * sum_h P16
// ---------------------------------------------------------------------------
__global__ void __launch_bounds__(256)
attn_mean_kernel(const __half* __restrict__ P, float* __restrict__ out)
{
    size_t idx = (size_t)blockIdx.x * 256 + threadIdx.x;
    size_t e0 = idx << 2;
    int b = (int)(e0 >> 20);
    size_t rem = e0 & 1048575;
    float a0 = 0.f, a1 = 0.f, a2 = 0.f, a3 = 0.f;
#pragma unroll
    for (int h = 0; h < 16; h++) {
        const __half2* p = reinterpret_cast<const __half2*>(
            P + (((size_t)(b * 16 + h)) << 20) + rem);
        float2 x = __half22float2(p[0]);
        float2 y = __half22float2(p[1]);
        a0 += x.x; a1 += x.y; a2 += y.x; a3 += y.y;
    }
    const float s = 1.0f / 16.0f;
    *reinterpret_cast<float4*>(out + e0) = make_float4(a0 * s, a1 * s, a2 * s, a3 * s);
}

// ---------------------------------------------------------------------------
// kernel_launch. Inputs: x, Wq, bq, Wk, bk, Wv, bv, Wo, bo
// Output: out [4,1024,1024] fp32 then attn_mean [4,1024,1024] fp32
// ---------------------------------------------------------------------------
extern "C" void kernel_launch(void* const* d_in, const int* in_sizes, int n_in,
                              void* d_out, int out_size)
{
    (void)in_sizes; (void)n_in; (void)out_size;
    const float* x  = (const float*)d_in[0];
    const float* Wq = (const float*)d_in[1];
    const float* bq = (const float*)d_in[2];
    const float* Wk = (const float*)d_in[3];
    const float* bk = (const float*)d_in[4];
    const float* Wv = (const float*)d_in[5];
    const float* bv = (const float*)d_in[6];
    const float* Wo = (const float*)d_in[7];
    const float* bo = (const float*)d_in[8];
    float* out     = (float*)d_out;
    float* outAttn = out + 4194304;

    char* hp = nullptr;
    cudaGetSymbolAddress((void**)&hp, g_heap);
    __nv_bfloat16* Xhi   = (__nv_bfloat16*)(hp + OFF_XHI);
    __nv_bfloat16* Xlo   = (__nv_bfloat16*)(hp + OFF_XLO);
    __nv_bfloat16* WqThi = (__nv_bfloat16*)(hp + OFF_WQTHI);
    __nv_bfloat16* WqTlo = (__nv_bfloat16*)(hp + OFF_WQTLO);
    __nv_bfloat16* WkThi = (__nv_bfloat16*)(hp + OFF_WKTHI);
    __nv_bfloat16* WkTlo = (__nv_bfloat16*)(hp + OFF_WKTLO);
    __nv_bfloat16* WoThi = (__nv_bfloat16*)(hp + OFF_WOTHI);
    __nv_bfloat16* WoTlo = (__nv_bfloat16*)(hp + OFF_WOTLO);
    __nv_bfloat16* WvThi = (__nv_bfloat16*)(hp + OFF_WVTHI);
    __nv_bfloat16* WvTlo = (__nv_bfloat16*)(hp + OFF_WVTLO);
    __half*        Q16   = (__half*)(hp + OFF_Q16);
    __half*        K16   = (__half*)(hp + OFF_K16);
    __half*        VT16  = (__half*)(hp + OFF_VT16);
    __nv_bfloat16* Chi   = (__nv_bfloat16*)(hp + OFF_CHI);
    __nv_bfloat16* Clo   = (__nv_bfloat16*)(hp + OFF_CLO);
    __half*        P16   = (__half*)(hp + OFF_P16);

    cudaFuncSetAttribute(gemm_bf16x3<64>,  cudaFuncAttributeMaxDynamicSharedMemorySize, SMEM64);
    cudaFuncSetAttribute(gemm_bf16x3<128>, cudaFuncAttributeMaxDynamicSharedMemorySize, SMEM128);
    cudaFuncSetAttribute(fused_attn, cudaFuncAttributeMaxDynamicSharedMemorySize, FA_SMEM);

    // conversions
    conv_split<<<4096, 256>>>(x, Xhi, Xlo, 1048576);
    convT_split<<<dim3(32, 32), dim3(32, 8)>>>(Wq, WqThi, WqTlo, 1024, 1024);
    convT_split<<<dim3(32, 32), dim3(32, 8)>>>(Wk, WkThi, WkTlo, 1024, 1024);
    convT_split<<<dim3(32, 32), dim3(32, 8)>>>(Wo, WoThi, WoTlo, 1024, 1024);
    convT_split<<<dim3(2, 32),  dim3(32, 8)>>>(Wv, WvThi, WvTlo, 1024, 64);

    // Q projection (scale 1/8 folded) -> head-split fp16
    gemm_bf16x3<128><<<dim3(8, 32, 1), 512, SMEM128>>>(
        Xhi, Xlo, 0, 1024, WqThi, WqTlo, 0, 1, 1024, 1024,
        bq, 0.125f, nullptr, 0, 0, Q16, 1);
    // K projection -> head-split fp16
    gemm_bf16x3<128><<<dim3(8, 32, 1), 512, SMEM128>>>(
        Xhi, Xlo, 0, 1024, WkThi, WkTlo, 0, 1, 1024, 1024,
        bk, 1.0f, nullptr, 0, 0, K16, 1);
    // V projection -> V^T fp16 [b,d,t]
    gemm_bf16x3<64><<<dim3(1, 32, 1), 512, SMEM64>>>(
        Xhi, Xlo, 0, 1024, WvThi, WvTlo, 0, 1, 1024, 1024,
        bv, 1.0f, nullptr, 0, 0, VT16, 2);
    // fused attention: S + softmax + P fp16 + ctx (fp16 MMA)
    fused_attn<<<dim3(32, 64), 256, FA_SMEM>>>(Q16, K16, VT16, P16, Chi, Clo);
    // attn_mean
    attn_mean_kernel<<<4096, 256>>>(P16, outAttn);
    // out = ctx @ Wo + bo -> fp32 d_out  (bf16x3, accurate)
    gemm_bf16x3<128><<<dim3(8, 32, 1), 512, SMEM128>>>(
        Chi, Clo, 0, 1024, WoThi, WoTlo, 0, 1, 1024, 1024,
        bo, 1.0f, out, 0, 1024, nullptr, 0);
}

// round 11
// speedup vs baseline: 1.5662x; 1.1919x over previous
#include <cuda_runtime.h>
#include <cuda_bf16.h>
#include <cuda_fp16.h>
#include <cstdint>
#include <cstddef>

// Problem constants: B=4, T=1024, D=1024, H=16, DH=64
#define MB ((size_t)1 << 20)

// ---------------------------------------------------------------------------
// Static device heap (no runtime allocation). Offsets in bytes.
// ---------------------------------------------------------------------------
#define OFF_XHI16  (0 * MB)           // x fp16 hi  [4096,1024]   8 MB
#define OFF_XLO16  (8 * MB)           // x fp16 lo               8 MB
#define OFF_WQT16  (16 * MB)          // Wq^T fp16 [1024,1024]   2 MB
#define OFF_WKT16  (18 * MB)
#define OFF_WOT16  (20 * MB)
#define OFF_WVT16  (22 * MB)          // Wv^T fp16 [64,1024]   128 KB
#define OFF_Q16    (23 * MB)          // Q fp16 head-split       8 MB
#define OFF_K16    (31 * MB)
#define OFF_VT16   (39 * MB)          // V^T fp16 [b,d,t]      512 KB
#define OFF_CHI16  (40 * MB)          // ctx fp16 hi             8 MB
#define OFF_CLO16  (48 * MB)          // ctx fp16 lo             8 MB
#define OFF_P16    (56 * MB)          // probs fp16 [bh,q,k]   128 MB
#define HEAP_BYTES (184 * MB)

__device__ char g_heap[HEAP_BYTES];

// ---------------------------------------------------------------------------
// PTX helpers (Ampere-compatible: ldmatrix / mma.sync / cp.async)
// ---------------------------------------------------------------------------
__device__ __forceinline__ uint32_t smem_u32(const void* p) {
    uint32_t a;
    asm("{ .reg .u64 t; cvta.to.shared.u64 t, %1; cvt.u32.u64 %0, t; }" : "=r"(a) : "l"(p));
    return a;
}
__device__ __forceinline__ void ldm_x4(uint32_t* r, uint32_t addr) {
    asm volatile("ldmatrix.sync.aligned.m8n8.x4.shared.b16 {%0,%1,%2,%3}, [%4];"
                 : "=r"(r[0]), "=r"(r[1]), "=r"(r[2]), "=r"(r[3]) : "r"(addr));
}
// fp16 MMA
__device__ __forceinline__ void mma16816h(float* c, const uint32_t* a,
                                          uint32_t b0, uint32_t b1) {
    asm volatile(
        "mma.sync.aligned.m16n8k16.row.col.f32.f16.f16.f32 "
        "{%0,%1,%2,%3}, {%4,%5,%6,%7}, {%8,%9}, {%0,%1,%2,%3};"
        : "+f"(c[0]), "+f"(c[1]), "+f"(c[2]), "+f"(c[3])
        : "r"(a[0]), "r"(a[1]), "r"(a[2]), "r"(a[3]), "r"(b0), "r"(b1));
}
__device__ __forceinline__ void cpa16(uint32_t saddr, const void* g) {
    asm volatile("cp.async.cg.shared.global [%0], [%1], 16;" :: "r"(saddr), "l"(g));
}
#define CP_COMMIT() asm volatile("cp.async.commit_group;" ::: "memory")
#define CP_WAIT(N)  asm volatile("cp.async.wait_group %0;" :: "n"(N) : "memory")

// packing helpers -------------------------------------------------------------
__device__ __forceinline__ uint32_t pack2u(unsigned short a, unsigned short b) {
    return (uint32_t)a | ((uint32_t)b << 16);
}
// fp16 hi/lo split: v = hi + lo with |lo| <= ulp(hi)/2
__device__ __forceinline__ void split_h(float v, unsigned short& h, unsigned short& l) {
    __half hh = __float2half_rn(v);
    float r = v - __half2float(hh);
    h = __half_as_ushort(hh);
    l = __half_as_ushort(__float2half_rn(r));
}

// ---------------------------------------------------------------------------
// Conversion kernels
// ---------------------------------------------------------------------------
__global__ void __launch_bounds__(256)
conv_split_h(const float* __restrict__ x, __half* __restrict__ hi,
             __half* __restrict__ lo, int n4)
{
    int i = blockIdx.x * 256 + threadIdx.x;
    if (i >= n4) return;
    float4 v = reinterpret_cast<const float4*>(x)[i];
    unsigned short h0, h1, h2, h3, l0, l1, l2, l3;
    split_h(v.x, h0, l0); split_h(v.y, h1, l1);
    split_h(v.z, h2, l2); split_h(v.w, h3, l3);
    reinterpret_cast<uint2*>(hi)[i] = make_uint2(pack2u(h0, h1), pack2u(h2, h3));
    reinterpret_cast<uint2*>(lo)[i] = make_uint2(pack2u(l0, l1), pack2u(l2, l3));
}

// W [K,N] row-major -> W^T fp16 [N,K]
__global__ void __launch_bounds__(256)
convT_h(const float* __restrict__ W, __half* __restrict__ T, int K, int N)
{
    __shared__ float sm[32][33];
    int n0 = blockIdx.x * 32, k0 = blockIdx.y * 32;
    int tx = threadIdx.x, ty = threadIdx.y;       // (32, 8)
#pragma unroll
    for (int i = 0; i < 32; i += 8)
        sm[ty + i][tx] = W[(size_t)(k0 + ty + i) * N + n0 + tx];
    __syncthreads();
#pragma unroll
    for (int i = 0; i < 32; i += 8)
        T[(size_t)(n0 + ty + i) * K + k0 + tx] = __float2half_rn(sm[tx][ty + i]);
}

// ---------------------------------------------------------------------------
// fp16x2 GEMM via mma.sync:  D[m,n] = sum_k (Ahi+Alo)[m,k] * B[n,k]
// A is an fp16 hi/lo pair (reconstructs fp32 to 2^-21); B single fp16.
// Block 128 x NT x 32, 512 threads, 16 warps (4M x 4N). 3-stage cp.async.
// STAGE keeps the proven 2A+2B geometry (second B region unused padding).
// Epilogue modes:
//   0: fp32 row-major (+bias,*scale)
//   1: head-split fp16 (+bias,*scale):  [b,h,t,d]
//   2: V^T fp16 (+bias):  [b, col, t]
// ---------------------------------------------------------------------------
#define APAD 80                 // 32 fp16 = 64B payload, padded to 80B
#define A_TERM (128 * APAD)     // 10240

template <int NT>
__global__ void __launch_bounds__(512)
gemm_fp16x2(const __half* __restrict__ Ahi, const __half* __restrict__ Alo,
            size_t aBS, int lda,
            const __half* __restrict__ Bp,
            size_t bBS, int bDiv, int ldb,
            int K,
            const float* __restrict__ bias, float scale,
            float* __restrict__ outF, size_t outBS, int ldOut,
            __half* __restrict__ outH,
            int mode)
{
    constexpr int B_TERM = NT * APAD;
    constexpr int STAGE  = 2 * A_TERM + 2 * B_TERM;   // proven geometry (pad)
    constexpr int W      = NT / 4;
    constexpr int NTB    = W / 16;

    extern __shared__ __align__(16) char smem[];
    const uint32_t sbase = smem_u32(smem);
    const int tid  = threadIdx.x;
    const int lane = tid & 31;
    const int wid  = tid >> 5;
    const int wm   = wid & 3;
    const int wn   = wid >> 2;
    const int m0   = blockIdx.y * 128;
    const int n0   = blockIdx.x * NT;
    const int z    = blockIdx.z;

    const __half* Ah = Ahi + (size_t)z * aBS;
    const __half* Al = Alo + (size_t)z * aBS;
    const __half* Bg = Bp + (size_t)(z / bDiv) * bBS;

    const int sRow = tid >> 2;
    const int slot = tid & 3;

    const uint32_t aLdmOff = (uint32_t)((wm * 32 + (lane & 15)) * APAD + (lane >> 4) * 16);
    const uint32_t bLdmOff = (uint32_t)((wn * W  + (lane & 15)) * APAD + (lane >> 4) * 16);

    float acc[2][NTB][2][4];
#pragma unroll
    for (int i = 0; i < 2; i++)
#pragma unroll
        for (int j = 0; j < NTB; j++)
#pragma unroll
            for (int k = 0; k < 2; k++)
#pragma unroll
                for (int l = 0; l < 4; l++) acc[i][j][k][l] = 0.0f;

    const int nc = K >> 5;

    auto stage_chunk = [&](int c) {
        const int k0 = c << 5;
        const uint32_t buf = sbase + (uint32_t)((c % 3) * STAGE);
        {
            size_t go = (size_t)(m0 + sRow) * lda + k0 + slot * 8;
            uint32_t so = buf + (uint32_t)(sRow * APAD + slot * 16);
            cpa16(so, Ah + go);
            cpa16(so + A_TERM, Al + go);
        }
        for (int r = sRow; r < NT; r += 128) {
            size_t go = (size_t)(n0 + r) * ldb + k0 + slot * 8;
            cpa16(buf + 2 * A_TERM + (uint32_t)(r * APAD + slot * 16), Bg + go);
        }
        CP_COMMIT();
    };

    stage_chunk(0);
    if (nc > 1) stage_chunk(1);

    for (int c = 0; c < nc; c++) {
        if (c + 2 < nc) { stage_chunk(c + 2); CP_WAIT(2); }
        else if (c + 1 < nc) { CP_WAIT(1); }
        else { CP_WAIT(0); }
        __syncthreads();

        const uint32_t cbuf = sbase + (uint32_t)((c % 3) * STAGE);
        const uint32_t aHiB = cbuf + aLdmOff;
        const uint32_t aLoB = cbuf + A_TERM + aLdmOff;
        const uint32_t bB   = cbuf + 2 * A_TERM + bLdmOff;

#pragma unroll
        for (int ks = 0; ks < 2; ks++) {
            const uint32_t ko = ks * 32;
            uint32_t ahi[2][4], alo[2][4], bb[NTB][4];
            ldm_x4(ahi[0], aHiB + ko);
            ldm_x4(ahi[1], aHiB + ko + 16 * APAD);
            ldm_x4(alo[0], aLoB + ko);
            ldm_x4(alo[1], aLoB + ko + 16 * APAD);
#pragma unroll
            for (int nt = 0; nt < NTB; nt++)
                ldm_x4(bb[nt], bB + ko + nt * 16 * APAD);
#pragma unroll
            for (int mt = 0; mt < 2; mt++)
#pragma unroll
                for (int nt = 0; nt < NTB; nt++)
#pragma unroll
                    for (int nh = 0; nh < 2; nh++) {
                        float* cc = acc[mt][nt][nh];
                        mma16816h(cc, ahi[mt], bb[nt][nh], bb[nt][nh + 2]);
                        mma16816h(cc, alo[mt], bb[nt][nh], bb[nt][nh + 2]);
                    }
        }
        __syncthreads();
    }

    // ---- epilogue ----
    const int rr = lane >> 2;
    const int cc2 = (lane & 3) << 1;
#pragma unroll
    for (int mt = 0; mt < 2; mt++)
#pragma unroll
        for (int nt = 0; nt < NTB; nt++)
#pragma unroll
            for (int nh = 0; nh < 2; nh++) {
                const float* cv = acc[mt][nt][nh];
                int gc = n0 + wn * W + nt * 16 + nh * 8 + cc2;
                float b0 = 0.f, b1 = 0.f;
                if (bias) { b0 = bias[gc]; b1 = bias[gc + 1]; }
#pragma unroll
                for (int half = 0; half < 2; half++) {
                    int gr = m0 + wm * 32 + mt * 16 + rr + half * 8;
                    float v0 = (cv[half * 2 + 0] + b0) * scale;
                    float v1 = (cv[half * 2 + 1] + b1) * scale;
                    if (mode == 0) {
                        float* p = outF + (size_t)z * outBS + (size_t)gr * ldOut + gc;
                        *reinterpret_cast<float2*>(p) = make_float2(v0, v1);
                    } else if (mode == 1) {
                        int bb = gr >> 10, t = gr & 1023;
                        int h = gc >> 6, d = gc & 63;
                        size_t idx = ((size_t)((bb << 4) + h) << 16) + ((size_t)t << 6) + d;
                        *reinterpret_cast<__half2*>(outH + idx) = __floats2half2_rn(v0, v1);
                    } else { // mode 2: V^T fp16 [b, col, t]
                        int bb = gr >> 10, t = gr & 1023;
                        size_t i0 = ((size_t)bb << 16) + ((size_t)gc << 10) + t;
                        outH[i0] = __float2half_rn(v0);
                        outH[i0 + 1024] = __float2half_rn(v1);
                    }
                }
            }
}

#define SMEM64  (3 * (2 * A_TERM + 2 * 64 * APAD))    // 92160
#define SMEM128 (3 * (2 * A_TERM + 2 * 128 * APAD))   // 122880

// ---------------------------------------------------------------------------
// Fused attention (fp16 single-product MMA): per CTA = (bh, 32 q rows).
//   S strip (32 x 1024 fp32) via fp16 MMA over 8 key tiles; in-smem softmax;
//   P fp16 in place + fp16 -> gmem; PV fp16 MMA; ctx fp16 hi/lo -> gmem.
// smem: S strip 32x4112, Q 32x144, 2 KV buffers 18432 each = 173056 B.
// ---------------------------------------------------------------------------
#define SROWB  4112
#define FA_Q   131584
#define FA_KV0 (FA_Q + 4608)
#define FA_KVSZ 18432
#define FA_KV1 (FA_KV0 + FA_KVSZ)
#define FA_SMEM (FA_KV1 + FA_KVSZ)   // 173056

__global__ void __launch_bounds__(256)
fused_attn(const __half* __restrict__ Q_, const __half* __restrict__ K_,
           const __half* __restrict__ V_,
           __half* __restrict__ Pout,
           __half* __restrict__ Chi, __half* __restrict__ Clo)
{
    extern __shared__ __align__(16) char smem[];
    const uint32_t sb = smem_u32(smem);
    const int tid = threadIdx.x, lane = tid & 31, wid = tid >> 5;
    const int q0 = blockIdx.x * 32;
    const int bh = blockIdx.y;
    const int b = bh >> 4, h = bh & 15;

    const __half* Qg = Q_ + ((size_t)bh << 16) + ((size_t)q0 << 6);
    const __half* Kg = K_ + ((size_t)bh << 16);
    const __half* Vg = V_ + ((size_t)b << 16);

    auto stageK = [&](int kt, uint32_t buf) {
#pragma unroll
        for (int i = 0; i < 4; i++) {
            int idx = tid + i * 256;
            int row = idx >> 3, slot = idx & 7;
            size_t go = ((size_t)(kt * 128 + row) << 6) + slot * 8;
            cpa16(buf + (uint32_t)(row * 144 + slot * 16), Kg + go);
        }
        CP_COMMIT();
    };
    auto stageV = [&](int vt, uint32_t buf) {
#pragma unroll
        for (int i = 0; i < 4; i++) {
            int idx = tid + i * 256;
            int row = idx >> 4, slot = idx & 15;
            size_t go = ((size_t)row << 10) + vt * 128 + slot * 8;
            cpa16(buf + (uint32_t)(row * 272 + slot * 16), Vg + go);
        }
        CP_COMMIT();
    };

    // stage Q (32x64 fp16) + first K tile in one group
    {
        int row = tid >> 3, slot = tid & 7;
        size_t go = ((size_t)row << 6) + slot * 8;
        cpa16(sb + FA_Q + (uint32_t)(row * 144 + slot * 16), Qg + go);
    }
    stageK(0, sb + FA_KV0);

    // ---------------- phase 1: S = Q K^T ----------------
    const int wm = wid & 1, wn = wid >> 1;       // 2M x 4N, warp tile 16x32
    const uint32_t aQ = sb + FA_Q + (uint32_t)((wm * 16 + (lane & 15)) * 144 + (lane >> 4) * 16);

    for (int kt = 0; kt < 8; kt++) {
        uint32_t buf = sb + ((kt & 1) ? FA_KV1 : FA_KV0);
        if (kt < 7) { stageK(kt + 1, sb + ((kt & 1) ? FA_KV0 : FA_KV1)); CP_WAIT(1); }
        else { CP_WAIT(0); }
        __syncthreads();

        float acc[2][2][4];
#pragma unroll
        for (int i = 0; i < 2; i++)
#pragma unroll
            for (int j = 0; j < 2; j++)
#pragma unroll
                for (int l = 0; l < 4; l++) acc[i][j][l] = 0.0f;

        const uint32_t bK = buf + (uint32_t)((wn * 32 + (lane & 15)) * 144 + (lane >> 4) * 16);
#pragma unroll
        for (int ks = 0; ks < 4; ks++) {
            const uint32_t ko = ks * 32;
            uint32_t a[4], b0[4], b1[4];
            ldm_x4(a, aQ + ko);
            ldm_x4(b0, bK + ko);
            ldm_x4(b1, bK + ko + 16 * 144);
#pragma unroll
            for (int nh = 0; nh < 2; nh++) {
                mma16816h(acc[0][nh], a, b0[nh], b0[nh + 2]);
                mma16816h(acc[1][nh], a, b1[nh], b1[nh + 2]);
            }
        }
        // write S tile to strip
        const int r0 = wm * 16 + (lane >> 2);
#pragma unroll
        for (int nt = 0; nt < 2; nt++)
#pragma unroll
            for (int nh = 0; nh < 2; nh++) {
                int col = kt * 128 + wn * 32 + nt * 16 + nh * 8 + ((lane & 3) << 1);
                *reinterpret_cast<float2*>(smem + r0 * SROWB + col * 4) =
                    make_float2(acc[nt][nh][0], acc[nt][nh][1]);
                *reinterpret_cast<float2*>(smem + (r0 + 8) * SROWB + col * 4) =
                    make_float2(acc[nt][nh][2], acc[nt][nh][3]);
            }
        __syncthreads();
    }

    // ---------------- phase 2: softmax + P fp16 (in place + gmem) ----------
#pragma unroll 1
    for (int rr = 0; rr < 4; rr++) {
        const int r = wid * 4 + rr;
        char* rowp = smem + r * SROWB;
        float2 v[16];
        float m = -1e30f;
#pragma unroll
        for (int i = 0; i < 16; i++) {
            v[i] = *reinterpret_cast<const float2*>(rowp + ((lane * 2 + 64 * i) << 2));
            m = fmaxf(m, fmaxf(v[i].x, v[i].y));
        }
#pragma unroll
        for (int o = 16; o; o >>= 1) m = fmaxf(m, __shfl_xor_sync(0xffffffffu, m, o));
        float s = 0.0f;
#pragma unroll
        for (int i = 0; i < 16; i++) {
            v[i].x = __expf(v[i].x - m);
            v[i].y = __expf(v[i].y - m);
            s += v[i].x + v[i].y;
        }
#pragma unroll
        for (int o = 16; o; o >>= 1) s += __shfl_xor_sync(0xffffffffu, s, o);
        const float inv = 1.0f / s;
        const size_t pbase = ((size_t)bh << 20) + ((size_t)(q0 + r) << 10);
        __syncwarp();
#pragma unroll
        for (int i = 0; i < 16; i++) {
            int c = lane * 2 + 64 * i;
            __half2 ph = __floats2half2_rn(v[i].x * inv, v[i].y * inv);
            *reinterpret_cast<__half2*>(Pout + pbase + c) = ph;
            *reinterpret_cast<__half2*>(rowp + c * 2) = ph;
        }
    }
    __syncthreads();

    // ---------------- phase 3: ctx = P V ----------------
    stageV(0, sb + FA_KV0);
    const int wm2 = wid & 1, wn2 = wid >> 1;     // 2M x 4N, warp tile 16x16
    const uint32_t aP = sb + (uint32_t)((wm2 * 16 + (lane & 15)) * SROWB + (lane >> 4) * 16);

    float acc2[2][4];
#pragma unroll
    for (int j = 0; j < 2; j++)
#pragma unroll
        for (int l = 0; l < 4; l++) acc2[j][l] = 0.0f;

    for (int vt = 0; vt < 8; vt++) {
        uint32_t buf = sb + ((vt & 1) ? FA_KV1 : FA_KV0);
        if (vt < 7) { stageV(vt + 1, sb + ((vt & 1) ? FA_KV0 : FA_KV1)); CP_WAIT(1); }
        else { CP_WAIT(0); }
        __syncthreads();

        const uint32_t bV = buf + (uint32_t)((wn2 * 16 + (lane & 15)) * 272 + (lane >> 4) * 16);
#pragma unroll
        for (int ks = 0; ks < 8; ks++) {
            const uint32_t ko = ks * 32;
            uint32_t a[4], bv[4];
            ldm_x4(a, aP + vt * 256 + ko);
            ldm_x4(bv, bV + ko);
            mma16816h(acc2[0], a, bv[0], bv[2]);
            mma16816h(acc2[1], a, bv[1], bv[3]);
        }
        __syncthreads();
    }

    // epilogue: ctx fp16 hi/lo [(b*1024 + q)*1024 + h*64 + d]
    const int r0 = wm2 * 16 + (lane >> 2);
#pragma unroll
    for (int nh = 0; nh < 2; nh++) {
        int gc = wn2 * 16 + nh * 8 + ((lane & 3) << 1);
#pragma unroll
        for (int half = 0; half < 2; half++) {
            int gr = q0 + r0 + half * 8;
            float v0 = acc2[nh][half * 2 + 0];
            float v1 = acc2[nh][half * 2 + 1];
            size_t idx = (((size_t)(b << 10) + gr) << 10) + (h << 6) + gc;
            unsigned short h0, h1, l0, l1;
            split_h(v0, h0, l0); split_h(v1, h1, l1);
            *reinterpret_cast<uint32_t*>(Chi + idx) = pack2u(h0, h1);
            *reinterpret_cast<uint32_t*>(Clo + idx) = pack2u(l0, l1);
        }
    }
}

// ---------------------------------------------------------------------------
// attn_mean[b,q,k] = (1/16) * sum_h P16
// ---------------------------------------------------------------------------
__global__ void __launch_bounds__(256)
attn_mean_kernel(const __half* __restrict__ P, float* __restrict__ out)
{
    size_t idx = (size_t)blockIdx.x * 256 + threadIdx.x;
    size_t e0 = idx << 2;
    int b = (int)(e0 >> 20);
    size_t rem = e0 & 1048575;
    float a0 = 0.f, a1 = 0.f, a2 = 0.f, a3 = 0.f;
#pragma unroll
    for (int h = 0; h < 16; h++) {
        const __half2* p = reinterpret_cast<const __half2*>(
            P + (((size_t)(b * 16 + h)) << 20) + rem);
        float2 x = __half22float2(p[0]);
        float2 y = __half22float2(p[1]);
        a0 += x.x; a1 += x.y; a2 += y.x; a3 += y.y;
    }
    const float s = 1.0f / 16.0f;
    *reinterpret_cast<float4*>(out + e0) = make_float4(a0 * s, a1 * s, a2 * s, a3 * s);
}

// ---------------------------------------------------------------------------
// kernel_launch. Inputs: x, Wq, bq, Wk, bk, Wv, bv, Wo, bo
// Output: out [4,1024,1024] fp32 then attn_mean [4,1024,1024] fp32
// ---------------------------------------------------------------------------
extern "C" void kernel_launch(void* const* d_in, const int* in_sizes, int n_in,
                              void* d_out, int out_size)
{
    (void)in_sizes; (void)n_in; (void)out_size;
    const float* x  = (const float*)d_in[0];
    const float* Wq = (const float*)d_in[1];
    const float* bq = (const float*)d_in[2];
    const float* Wk = (const float*)d_in[3];
    const float* bk = (const float*)d_in[4];
    const float* Wv = (const float*)d_in[5];
    const float* bv = (const float*)d_in[6];
    const float* Wo = (const float*)d_in[7];
    const float* bo = (const float*)d_in[8];
    float* out     = (float*)d_out;
    float* outAttn = out + 4194304;

    char* hp = nullptr;
    cudaGetSymbolAddress((void**)&hp, g_heap);
    __half* Xhi16 = (__half*)(hp + OFF_XHI16);
    __half* Xlo16 = (__half*)(hp + OFF_XLO16);
    __half* WqT16 = (__half*)(hp + OFF_WQT16);
    __half* WkT16 = (__half*)(hp + OFF_WKT16);
    __half* WoT16 = (__half*)(hp + OFF_WOT16);
    __half* WvT16 = (__half*)(hp + OFF_WVT16);
    __half* Q16   = (__half*)(hp + OFF_Q16);
    __half* K16   = (__half*)(hp + OFF_K16);
    __half* VT16  = (__half*)(hp + OFF_VT16);
    __half* Chi16 = (__half*)(hp + OFF_CHI16);
    __half* Clo16 = (__half*)(hp + OFF_CLO16);
    __half* P16   = (__half*)(hp + OFF_P16);

    cudaFuncSetAttribute(gemm_fp16x2<64>,  cudaFuncAttributeMaxDynamicSharedMemorySize, SMEM64);
    cudaFuncSetAttribute(gemm_fp16x2<128>, cudaFuncAttributeMaxDynamicSharedMemorySize, SMEM128);
    cudaFuncSetAttribute(fused_attn, cudaFuncAttributeMaxDynamicSharedMemorySize, FA_SMEM);

    // conversions
    conv_split_h<<<4096, 256>>>(x, Xhi16, Xlo16, 1048576);
    convT_h<<<dim3(32, 32), dim3(32, 8)>>>(Wq, WqT16, 1024, 1024);
    convT_h<<<dim3(32, 32), dim3(32, 8)>>>(Wk, WkT16, 1024, 1024);
    convT_h<<<dim3(32, 32), dim3(32, 8)>>>(Wo, WoT16, 1024, 1024);
    convT_h<<<dim3(2, 32),  dim3(32, 8)>>>(Wv, WvT16, 1024, 64);

    // Q projection (scale 1/8 folded) -> head-split fp16
    gemm_fp16x2<128><<<dim3(8, 32, 1), 512, SMEM128>>>(
        Xhi16, Xlo16, 0, 1024, WqT16, 0, 1, 1024, 1024,
        bq, 0.125f, nullptr, 0, 0, Q16, 1);
    // K projection -> head-split fp16
    gemm_fp16x2<128><<<dim3(8, 32, 1), 512, SMEM128>>>(
        Xhi16, Xlo16, 0, 1024, WkT16, 0, 1, 1024, 1024,
        bk, 1.0f, nullptr, 0, 0, K16, 1);
    // V projection -> V^T fp16 [b,d,t]
    gemm_fp16x2<64><<<dim3(1, 32, 1), 512, SMEM64>>>(
        Xhi16, Xlo16, 0, 1024, WvT16, 0, 1, 1024, 1024,
        bv, 1.0f, nullptr, 0, 0, VT16, 2);
    // fused attention: S + softmax + P fp16 + ctx fp16 hi/lo
    fused_attn<<<dim3(32, 64), 256, FA_SMEM>>>(Q16, K16, VT16, P16, Chi16, Clo16);
    // attn_mean
    attn_mean_kernel<<<4096, 256>>>(P16, outAttn);
    // out = (Chi+Clo) @ Wo + bo -> fp32 d_out
    gemm_fp16x2<128><<<dim3(8, 32, 1), 512, SMEM128>>>(
        Chi16, Clo16, 0, 1024, WoT16, 0, 1, 1024, 1024,
        bo, 1.0f, out, 0, 1024, nullptr, 0);
}

// round 12
// speedup vs baseline: 1.6804x; 1.0729x over previous
#include <cuda_runtime.h>
#include <cuda_bf16.h>
#include <cuda_fp16.h>
#include <cstdint>
#include <cstddef>

// Problem constants: B=4, T=1024, D=1024, H=16, DH=64
#define MB ((size_t)1 << 20)

// ---------------------------------------------------------------------------
// Static device heap (no runtime allocation). Offsets in bytes.
// ---------------------------------------------------------------------------
#define OFF_XHI16  (0 * MB)           // x fp16 hi  [4096,1024]   8 MB
#define OFF_XLO16  (8 * MB)           // x fp16 lo               8 MB
#define OFF_WQT16  (16 * MB)          // Wq^T fp16 [1024,1024]   2 MB
#define OFF_WKT16  (18 * MB)
#define OFF_WOT16  (20 * MB)
#define OFF_WVT16  (22 * MB)          // Wv^T fp16 [64,1024]   128 KB
#define OFF_Q16    (23 * MB)          // Q fp16 head-split       8 MB
#define OFF_K16    (31 * MB)
#define OFF_VT16   (39 * MB)          // V^T fp16 [b,d,t]      512 KB
#define OFF_C16    (40 * MB)          // ctx fp16                8 MB
#define OFF_P16    (48 * MB)          // probs fp16 [bh,q,k]   128 MB
#define HEAP_BYTES (176 * MB)

__device__ char g_heap[HEAP_BYTES];

// ---------------------------------------------------------------------------
// PTX helpers (Ampere-compatible: ldmatrix / mma.sync / cp.async)
// ---------------------------------------------------------------------------
__device__ __forceinline__ uint32_t smem_u32(const void* p) {
    uint32_t a;
    asm("{ .reg .u64 t; cvta.to.shared.u64 t, %1; cvt.u32.u64 %0, t; }" : "=r"(a) : "l"(p));
    return a;
}
__device__ __forceinline__ void ldm_x4(uint32_t* r, uint32_t addr) {
    asm volatile("ldmatrix.sync.aligned.m8n8.x4.shared.b16 {%0,%1,%2,%3}, [%4];"
                 : "=r"(r[0]), "=r"(r[1]), "=r"(r[2]), "=r"(r[3]) : "r"(addr));
}
// fp16 MMA
__device__ __forceinline__ void mma16816h(float* c, const uint32_t* a,
                                          uint32_t b0, uint32_t b1) {
    asm volatile(
        "mma.sync.aligned.m16n8k16.row.col.f32.f16.f16.f32 "
        "{%0,%1,%2,%3}, {%4,%5,%6,%7}, {%8,%9}, {%0,%1,%2,%3};"
        : "+f"(c[0]), "+f"(c[1]), "+f"(c[2]), "+f"(c[3])
        : "r"(a[0]), "r"(a[1]), "r"(a[2]), "r"(a[3]), "r"(b0), "r"(b1));
}
__device__ __forceinline__ void cpa16(uint32_t saddr, const void* g) {
    asm volatile("cp.async.cg.shared.global [%0], [%1], 16;" :: "r"(saddr), "l"(g));
}
#define CP_COMMIT() asm volatile("cp.async.commit_group;" ::: "memory")
#define CP_WAIT(N)  asm volatile("cp.async.wait_group %0;" :: "n"(N) : "memory")

// packing helpers -------------------------------------------------------------
__device__ __forceinline__ uint32_t pack2u(unsigned short a, unsigned short b) {
    return (uint32_t)a | ((uint32_t)b << 16);
}
// fp16 hi/lo split: v = hi + lo with |lo| <= ulp(hi)/2
__device__ __forceinline__ void split_h(float v, unsigned short& h, unsigned short& l) {
    __half hh = __float2half_rn(v);
    float r = v - __half2float(hh);
    h = __half_as_ushort(hh);
    l = __half_as_ushort(__float2half_rn(r));
}

// ---------------------------------------------------------------------------
// Conversion kernels
// ---------------------------------------------------------------------------
__global__ void __launch_bounds__(256)
conv_split_h(const float* __restrict__ x, __half* __restrict__ hi,
             __half* __restrict__ lo, int n4)
{
    int i = blockIdx.x * 256 + threadIdx.x;
    if (i >= n4) return;
    float4 v = reinterpret_cast<const float4*>(x)[i];
    unsigned short h0, h1, h2, h3, l0, l1, l2, l3;
    split_h(v.x, h0, l0); split_h(v.y, h1, l1);
    split_h(v.z, h2, l2); split_h(v.w, h3, l3);
    reinterpret_cast<uint2*>(hi)[i] = make_uint2(pack2u(h0, h1), pack2u(h2, h3));
    reinterpret_cast<uint2*>(lo)[i] = make_uint2(pack2u(l0, l1), pack2u(l2, l3));
}

// W [K,N] row-major -> W^T fp16 [N,K]
__global__ void __launch_bounds__(256)
convT_h(const float* __restrict__ W, __half* __restrict__ T, int K, int N)
{
    __shared__ float sm[32][33];
    int n0 = blockIdx.x * 32, k0 = blockIdx.y * 32;
    int tx = threadIdx.x, ty = threadIdx.y;       // (32, 8)
#pragma unroll
    for (int i = 0; i < 32; i += 8)
        sm[ty + i][tx] = W[(size_t)(k0 + ty + i) * N + n0 + tx];
    __syncthreads();
#pragma unroll
    for (int i = 0; i < 32; i += 8)
        T[(size_t)(n0 + ty + i) * K + k0 + tx] = __float2half_rn(sm[tx][ty + i]);
}

// ---------------------------------------------------------------------------
// fp16 GEMM via mma.sync:  D[m,n] = sum_k (Ahi [+ Alo])[m,k] * B[n,k]
// ALO=true: A is an fp16 hi/lo pair (2 MMA terms, fp32-grade A).
// ALO=false: single-fp16 A (1 MMA term).
// Block 128 x NT x 32, 512 threads, 16 warps (4M x 4N). 3-stage cp.async.
// STAGE keeps the proven 2A+2B geometry (unused regions are padding).
// Epilogue modes:
//   0: fp32 row-major (+bias,*scale)
//   1: head-split fp16 (+bias,*scale):  [b,h,t,d]
//   2: V^T fp16 (+bias):  [b, col, t]
// ---------------------------------------------------------------------------
#define APAD 80                 // 32 fp16 = 64B payload, padded to 80B
#define A_TERM (128 * APAD)     // 10240

template <int NT, bool ALO>
__global__ void __launch_bounds__(512)
gemm_fp16x2(const __half* __restrict__ Ahi, const __half* __restrict__ Alo,
            size_t aBS, int lda,
            const __half* __restrict__ Bp,
            size_t bBS, int bDiv, int ldb,
            int K,
            const float* __restrict__ bias, float scale,
            float* __restrict__ outF, size_t outBS, int ldOut,
            __half* __restrict__ outH,
            int mode)
{
    constexpr int B_TERM = NT * APAD;
    constexpr int STAGE  = 2 * A_TERM + 2 * B_TERM;   // proven geometry (pad)
    constexpr int W      = NT / 4;
    constexpr int NTB    = W / 16;

    extern __shared__ __align__(16) char smem[];
    const uint32_t sbase = smem_u32(smem);
    const int tid  = threadIdx.x;
    const int lane = tid & 31;
    const int wid  = tid >> 5;
    const int wm   = wid & 3;
    const int wn   = wid >> 2;
    const int m0   = blockIdx.y * 128;
    const int n0   = blockIdx.x * NT;
    const int z    = blockIdx.z;

    const __half* Ah = Ahi + (size_t)z * aBS;
    const __half* Al = ALO ? (Alo + (size_t)z * aBS) : nullptr;
    const __half* Bg = Bp + (size_t)(z / bDiv) * bBS;

    const int sRow = tid >> 2;
    const int slot = tid & 3;

    const uint32_t aLdmOff = (uint32_t)((wm * 32 + (lane & 15)) * APAD + (lane >> 4) * 16);
    const uint32_t bLdmOff = (uint32_t)((wn * W  + (lane & 15)) * APAD + (lane >> 4) * 16);

    float acc[2][NTB][2][4];
#pragma unroll
    for (int i = 0; i < 2; i++)
#pragma unroll
        for (int j = 0; j < NTB; j++)
#pragma unroll
            for (int k = 0; k < 2; k++)
#pragma unroll
                for (int l = 0; l < 4; l++) acc[i][j][k][l] = 0.0f;

    const int nc = K >> 5;

    auto stage_chunk = [&](int c) {
        const int k0 = c << 5;
        const uint32_t buf = sbase + (uint32_t)((c % 3) * STAGE);
        {
            size_t go = (size_t)(m0 + sRow) * lda + k0 + slot * 8;
            uint32_t so = buf + (uint32_t)(sRow * APAD + slot * 16);
            cpa16(so, Ah + go);
            if (ALO) cpa16(so + A_TERM, Al + go);
        }
        for (int r = sRow; r < NT; r += 128) {
            size_t go = (size_t)(n0 + r) * ldb + k0 + slot * 8;
            cpa16(buf + 2 * A_TERM + (uint32_t)(r * APAD + slot * 16), Bg + go);
        }
        CP_COMMIT();
    };

    stage_chunk(0);
    if (nc > 1) stage_chunk(1);

    for (int c = 0; c < nc; c++) {
        if (c + 2 < nc) { stage_chunk(c + 2); CP_WAIT(2); }
        else if (c + 1 < nc) { CP_WAIT(1); }
        else { CP_WAIT(0); }
        __syncthreads();

        const uint32_t cbuf = sbase + (uint32_t)((c % 3) * STAGE);
        const uint32_t aHiB = cbuf + aLdmOff;
        const uint32_t aLoB = cbuf + A_TERM + aLdmOff;
        const uint32_t bB   = cbuf + 2 * A_TERM + bLdmOff;

#pragma unroll
        for (int ks = 0; ks < 2; ks++) {
            const uint32_t ko = ks * 32;
            uint32_t ahi[2][4], alo[2][4], bb[NTB][4];
            ldm_x4(ahi[0], aHiB + ko);
            ldm_x4(ahi[1], aHiB + ko + 16 * APAD);
            if (ALO) {
                ldm_x4(alo[0], aLoB + ko);
                ldm_x4(alo[1], aLoB + ko + 16 * APAD);
            }
#pragma unroll
            for (int nt = 0; nt < NTB; nt++)
                ldm_x4(bb[nt], bB + ko + nt * 16 * APAD);
#pragma unroll
            for (int mt = 0; mt < 2; mt++)
#pragma unroll
                for (int nt = 0; nt < NTB; nt++)
#pragma unroll
                    for (int nh = 0; nh < 2; nh++) {
                        float* cc = acc[mt][nt][nh];
                        mma16816h(cc, ahi[mt], bb[nt][nh], bb[nt][nh + 2]);
                        if (ALO) mma16816h(cc, alo[mt], bb[nt][nh], bb[nt][nh + 2]);
                    }
        }
        __syncthreads();
    }

    // ---- epilogue ----
    const int rr = lane >> 2;
    const int cc2 = (lane & 3) << 1;
#pragma unroll
    for (int mt = 0; mt < 2; mt++)
#pragma unroll
        for (int nt = 0; nt < NTB; nt++)
#pragma unroll
            for (int nh = 0; nh < 2; nh++) {
                const float* cv = acc[mt][nt][nh];
                int gc = n0 + wn * W + nt * 16 + nh * 8 + cc2;
                float b0 = 0.f, b1 = 0.f;
                if (bias) { b0 = bias[gc]; b1 = bias[gc + 1]; }
#pragma unroll
                for (int half = 0; half < 2; half++) {
                    int gr = m0 + wm * 32 + mt * 16 + rr + half * 8;
                    float v0 = (cv[half * 2 + 0] + b0) * scale;
                    float v1 = (cv[half * 2 + 1] + b1) * scale;
                    if (mode == 0) {
                        float* p = outF + (size_t)z * outBS + (size_t)gr * ldOut + gc;
                        *reinterpret_cast<float2*>(p) = make_float2(v0, v1);
                    } else if (mode == 1) {
                        int bb = gr >> 10, t = gr & 1023;
                        int h = gc >> 6, d = gc & 63;
                        size_t idx = ((size_t)((bb << 4) + h) << 16) + ((size_t)t << 6) + d;
                        *reinterpret_cast<__half2*>(outH + idx) = __floats2half2_rn(v0, v1);
                    } else { // mode 2: V^T fp16 [b, col, t]
                        int bb = gr >> 10, t = gr & 1023;
                        size_t i0 = ((size_t)bb << 16) + ((size_t)gc << 10) + t;
                        outH[i0] = __float2half_rn(v0);
                        outH[i0 + 1024] = __float2half_rn(v1);
                    }
                }
            }
}

#define SMEM64  (3 * (2 * A_TERM + 2 * 64 * APAD))    // 92160
#define SMEM128 (3 * (2 * A_TERM + 2 * 128 * APAD))   // 122880

// ---------------------------------------------------------------------------
// Fused attention (fp16 single-product MMA): per CTA = (bh, 32 q rows).
//   S strip (32 x 1024 fp32) via fp16 MMA over 8 key tiles; in-smem softmax;
//   P fp16 in place + fp16 -> gmem; PV fp16 MMA; ctx fp16 -> gmem.
// smem: S strip 32x4112, Q 32x144, 2 KV buffers 18432 each = 173056 B.
// ---------------------------------------------------------------------------
#define SROWB  4112
#define FA_Q   131584
#define FA_KV0 (FA_Q + 4608)
#define FA_KVSZ 18432
#define FA_KV1 (FA_KV0 + FA_KVSZ)
#define FA_SMEM (FA_KV1 + FA_KVSZ)   // 173056

__global__ void __launch_bounds__(256)
fused_attn(const __half* __restrict__ Q_, const __half* __restrict__ K_,
           const __half* __restrict__ V_,
           __half* __restrict__ Pout, __half* __restrict__ Cout)
{
    extern __shared__ __align__(16) char smem[];
    const uint32_t sb = smem_u32(smem);
    const int tid = threadIdx.x, lane = tid & 31, wid = tid >> 5;
    const int q0 = blockIdx.x * 32;
    const int bh = blockIdx.y;
    const int b = bh >> 4, h = bh & 15;

    const __half* Qg = Q_ + ((size_t)bh << 16) + ((size_t)q0 << 6);
    const __half* Kg = K_ + ((size_t)bh << 16);
    const __half* Vg = V_ + ((size_t)b << 16);

    auto stageK = [&](int kt, uint32_t buf) {
#pragma unroll
        for (int i = 0; i < 4; i++) {
            int idx = tid + i * 256;
            int row = idx >> 3, slot = idx & 7;
            size_t go = ((size_t)(kt * 128 + row) << 6) + slot * 8;
            cpa16(buf + (uint32_t)(row * 144 + slot * 16), Kg + go);
        }
        CP_COMMIT();
    };
    auto stageV = [&](int vt, uint32_t buf) {
#pragma unroll
        for (int i = 0; i < 4; i++) {
            int idx = tid + i * 256;
            int row = idx >> 4, slot = idx & 15;
            size_t go = ((size_t)row << 10) + vt * 128 + slot * 8;
            cpa16(buf + (uint32_t)(row * 272 + slot * 16), Vg + go);
        }
        CP_COMMIT();
    };

    // stage Q (32x64 fp16) + first K tile in one group
    {
        int row = tid >> 3, slot = tid & 7;
        size_t go = ((size_t)row << 6) + slot * 8;
        cpa16(sb + FA_Q + (uint32_t)(row * 144 + slot * 16), Qg + go);
    }
    stageK(0, sb + FA_KV0);

    // ---------------- phase 1: S = Q K^T ----------------
    const int wm = wid & 1, wn = wid >> 1;       // 2M x 4N, warp tile 16x32
    const uint32_t aQ = sb + FA_Q + (uint32_t)((wm * 16 + (lane & 15)) * 144 + (lane >> 4) * 16);

    for (int kt = 0; kt < 8; kt++) {
        uint32_t buf = sb + ((kt & 1) ? FA_KV1 : FA_KV0);
        if (kt < 7) { stageK(kt + 1, sb + ((kt & 1) ? FA_KV0 : FA_KV1)); CP_WAIT(1); }
        else { CP_WAIT(0); }
        __syncthreads();

        float acc[2][2][4];
#pragma unroll
        for (int i = 0; i < 2; i++)
#pragma unroll
            for (int j = 0; j < 2; j++)
#pragma unroll
                for (int l = 0; l < 4; l++) acc[i][j][l] = 0.0f;

        const uint32_t bK = buf + (uint32_t)((wn * 32 + (lane & 15)) * 144 + (lane >> 4) * 16);
#pragma unroll
        for (int ks = 0; ks < 4; ks++) {
            const uint32_t ko = ks * 32;
            uint32_t a[4], b0[4], b1[4];
            ldm_x4(a, aQ + ko);
            ldm_x4(b0, bK + ko);
            ldm_x4(b1, bK + ko + 16 * 144);
#pragma unroll
            for (int nh = 0; nh < 2; nh++) {
                mma16816h(acc[0][nh], a, b0[nh], b0[nh + 2]);
                mma16816h(acc[1][nh], a, b1[nh], b1[nh + 2]);
            }
        }
        // write S tile to strip
        const int r0 = wm * 16 + (lane >> 2);
#pragma unroll
        for (int nt = 0; nt < 2; nt++)
#pragma unroll
            for (int nh = 0; nh < 2; nh++) {
                int col = kt * 128 + wn * 32 + nt * 16 + nh * 8 + ((lane & 3) << 1);
                *reinterpret_cast<float2*>(smem + r0 * SROWB + col * 4) =
                    make_float2(acc[nt][nh][0], acc[nt][nh][1]);
                *reinterpret_cast<float2*>(smem + (r0 + 8) * SROWB + col * 4) =
                    make_float2(acc[nt][nh][2], acc[nt][nh][3]);
            }
        __syncthreads();
    }

    // ---------------- phase 2: softmax + P fp16 (in place + gmem) ----------
#pragma unroll 1
    for (int rr = 0; rr < 4; rr++) {
        const int r = wid * 4 + rr;
        char* rowp = smem + r * SROWB;
        float2 v[16];
        float m = -1e30f;
#pragma unroll
        for (int i = 0; i < 16; i++) {
            v[i] = *reinterpret_cast<const float2*>(rowp + ((lane * 2 + 64 * i) << 2));
            m = fmaxf(m, fmaxf(v[i].x, v[i].y));
        }
#pragma unroll
        for (int o = 16; o; o >>= 1) m = fmaxf(m, __shfl_xor_sync(0xffffffffu, m, o));
        float s = 0.0f;
#pragma unroll
        for (int i = 0; i < 16; i++) {
            v[i].x = __expf(v[i].x - m);
            v[i].y = __expf(v[i].y - m);
            s += v[i].x + v[i].y;
        }
#pragma unroll
        for (int o = 16; o; o >>= 1) s += __shfl_xor_sync(0xffffffffu, s, o);
        const float inv = 1.0f / s;
        const size_t pbase = ((size_t)bh << 20) + ((size_t)(q0 + r) << 10);
        __syncwarp();
#pragma unroll
        for (int i = 0; i < 16; i++) {
            int c = lane * 2 + 64 * i;
            __half2 ph = __floats2half2_rn(v[i].x * inv, v[i].y * inv);
            *reinterpret_cast<__half2*>(Pout + pbase + c) = ph;
            *reinterpret_cast<__half2*>(rowp + c * 2) = ph;
        }
    }
    __syncthreads();

    // ---------------- phase 3: ctx = P V ----------------
    stageV(0, sb + FA_KV0);
    const int wm2 = wid & 1, wn2 = wid >> 1;     // 2M x 4N, warp tile 16x16
    const uint32_t aP = sb + (uint32_t)((wm2 * 16 + (lane & 15)) * SROWB + (lane >> 4) * 16);

    float acc2[2][4];
#pragma unroll
    for (int j = 0; j < 2; j++)
#pragma unroll
        for (int l = 0; l < 4; l++) acc2[j][l] = 0.0f;

    for (int vt = 0; vt < 8; vt++) {
        uint32_t buf = sb + ((vt & 1) ? FA_KV1 : FA_KV0);
        if (vt < 7) { stageV(vt + 1, sb + ((vt & 1) ? FA_KV0 : FA_KV1)); CP_WAIT(1); }
        else { CP_WAIT(0); }
        __syncthreads();

        const uint32_t bV = buf + (uint32_t)((wn2 * 16 + (lane & 15)) * 272 + (lane >> 4) * 16);
#pragma unroll
        for (int ks = 0; ks < 8; ks++) {
            const uint32_t ko = ks * 32;
            uint32_t a[4], bv[4];
            ldm_x4(a, aP + vt * 256 + ko);
            ldm_x4(bv, bV + ko);
            mma16816h(acc2[0], a, bv[0], bv[2]);
            mma16816h(acc2[1], a, bv[1], bv[3]);
        }
        __syncthreads();
    }

    // epilogue: ctx fp16 [(b*1024 + q)*1024 + h*64 + d]
    const int r0 = wm2 * 16 + (lane >> 2);
#pragma unroll
    for (int nh = 0; nh < 2; nh++) {
        int gc = wn2 * 16 + nh * 8 + ((lane & 3) << 1);
#pragma unroll
        for (int half = 0; half < 2; half++) {
            int gr = q0 + r0 + half * 8;
            float v0 = acc2[nh][half * 2 + 0];
            float v1 = acc2[nh][half * 2 + 1];
            size_t idx = (((size_t)(b << 10) + gr) << 10) + (h << 6) + gc;
            *reinterpret_cast<__half2*>(Cout + idx) = __floats2half2_rn(v0, v1);
        }
    }
}

// ---------------------------------------------------------------------------
// attn_mean[b,q,k] = (1/16) * sum_h P16
// ---------------------------------------------------------------------------
__global__ void __launch_bounds__(256)
attn_mean_kernel(const __half* __restrict__ P, float* __restrict__ out)
{
    size_t idx = (size_t)blockIdx.x * 256 + threadIdx.x;
    size_t e0 = idx << 2;
    int b = (int)(e0 >> 20);
    size_t rem = e0 & 1048575;
    float a0 = 0.f, a1 = 0.f, a2 = 0.f, a3 = 0.f;
#pragma unroll
    for (int h = 0; h < 16; h++) {
        const __half2* p = reinterpret_cast<const __half2*>(
            P + (((size_t)(b * 16 + h)) << 20) + rem);
        float2 x = __half22float2(p[0]);
        float2 y = __half22float2(p[1]);
        a0 += x.x; a1 += x.y; a2 += y.x; a3 += y.y;
    }
    const float s = 1.0f / 16.0f;
    *reinterpret_cast<float4*>(out + e0) = make_float4(a0 * s, a1 * s, a2 * s, a3 * s);
}

// ---------------------------------------------------------------------------
// kernel_launch. Inputs: x, Wq, bq, Wk, bk, Wv, bv, Wo, bo
// Output: out [4,1024,1024] fp32 then attn_mean [4,1024,1024] fp32
// ---------------------------------------------------------------------------
extern "C" void kernel_launch(void* const* d_in, const int* in_sizes, int n_in,
                              void* d_out, int out_size)
{
    (void)in_sizes; (void)n_in; (void)out_size;
    const float* x  = (const float*)d_in[0];
    const float* Wq = (const float*)d_in[1];
    const float* bq = (const float*)d_in[2];
    const float* Wk = (const float*)d_in[3];
    const float* bk = (const float*)d_in[4];
    const float* Wv = (const float*)d_in[5];
    const float* bv = (const float*)d_in[6];
    const float* Wo = (const float*)d_in[7];
    const float* bo = (const float*)d_in[8];
    float* out     = (float*)d_out;
    float* outAttn = out + 4194304;

    char* hp = nullptr;
    cudaGetSymbolAddress((void**)&hp, g_heap);
    __half* Xhi16 = (__half*)(hp + OFF_XHI16);
    __half* Xlo16 = (__half*)(hp + OFF_XLO16);
    __half* WqT16 = (__half*)(hp + OFF_WQT16);
    __half* WkT16 = (__half*)(hp + OFF_WKT16);
    __half* WoT16 = (__half*)(hp + OFF_WOT16);
    __half* WvT16 = (__half*)(hp + OFF_WVT16);
    __half* Q16   = (__half*)(hp + OFF_Q16);
    __half* K16   = (__half*)(hp + OFF_K16);
    __half* VT16  = (__half*)(hp + OFF_VT16);
    __half* C16   = (__half*)(hp + OFF_C16);
    __half* P16   = (__half*)(hp + OFF_P16);

    cudaFuncSetAttribute(gemm_fp16x2<64, true>,   cudaFuncAttributeMaxDynamicSharedMemorySize, SMEM64);
    cudaFuncSetAttribute(gemm_fp16x2<128, true>,  cudaFuncAttributeMaxDynamicSharedMemorySize, SMEM128);
    cudaFuncSetAttribute(gemm_fp16x2<128, false>, cudaFuncAttributeMaxDynamicSharedMemorySize, SMEM128);
    cudaFuncSetAttribute(fused_attn, cudaFuncAttributeMaxDynamicSharedMemorySize, FA_SMEM);

    // conversions
    conv_split_h<<<4096, 256>>>(x, Xhi16, Xlo16, 1048576);
    convT_h<<<dim3(32, 32), dim3(32, 8)>>>(Wq, WqT16, 1024, 1024);
    convT_h<<<dim3(32, 32), dim3(32, 8)>>>(Wk, WkT16, 1024, 1024);
    convT_h<<<dim3(32, 32), dim3(32, 8)>>>(Wo, WoT16, 1024, 1024);
    convT_h<<<dim3(2, 32),  dim3(32, 8)>>>(Wv, WvT16, 1024, 64);

    // Q projection (scale 1/8 folded) -> head-split fp16   [2-term A]
    gemm_fp16x2<128, true><<<dim3(8, 32, 1), 512, SMEM128>>>(
        Xhi16, Xlo16, 0, 1024, WqT16, 0, 1, 1024, 1024,
        bq, 0.125f, nullptr, 0, 0, Q16, 1);
    // K projection -> head-split fp16   [2-term A]
    gemm_fp16x2<128, true><<<dim3(8, 32, 1), 512, SMEM128>>>(
        Xhi16, Xlo16, 0, 1024, WkT16, 0, 1, 1024, 1024,
        bk, 1.0f, nullptr, 0, 0, K16, 1);
    // V projection -> V^T fp16 [b,d,t]   [2-term A]
    gemm_fp16x2<64, true><<<dim3(1, 32, 1), 512, SMEM64>>>(
        Xhi16, Xlo16, 0, 1024, WvT16, 0, 1, 1024, 1024,
        bv, 1.0f, nullptr, 0, 0, VT16, 2);
    // fused attention: S + softmax + P fp16 + ctx fp16
    fused_attn<<<dim3(32, 64), 256, FA_SMEM>>>(Q16, K16, VT16, P16, C16);
    // attn_mean
    attn_mean_kernel<<<4096, 256>>>(P16, outAttn);
    // out = ctx @ Wo + bo -> fp32 d_out   [1-term A]
    gemm_fp16x2<128, false><<<dim3(8, 32, 1), 512, SMEM128>>>(
        C16, nullptr, 0, 1024, WoT16, 0, 1, 1024, 1024,
        bo, 1.0f, out, 0, 1024, nullptr, 0);
}

// round 13
// speedup vs baseline: 1.9777x; 1.1769x over previous
#include <cuda_runtime.h>
#include <cuda_bf16.h>
#include <cuda_fp16.h>
#include <cstdint>
#include <cstddef>

// Problem constants: B=4, T=1024, D=1024, H=16, DH=64
#define MB ((size_t)1 << 20)

// ---------------------------------------------------------------------------
// Static device heap (no runtime allocation). Offsets in bytes.
// ---------------------------------------------------------------------------
#define OFF_X16    (0 * MB)           // x fp16 [4096,1024]      8 MB
#define OFF_WQT16  (8 * MB)           // Wq^T fp16 [1024,1024]   2 MB
#define OFF_WKT16  (10 * MB)
#define OFF_WOT16  (12 * MB)
#define OFF_WVT16  (14 * MB)          // Wv^T fp16 [64,1024]   128 KB
#define OFF_Q16    (15 * MB)          // Q fp16 head-split       8 MB
#define OFF_K16    (23 * MB)
#define OFF_VT16   (31 * MB)          // V^T fp16 [b,d,t]      512 KB
#define OFF_C16    (32 * MB)          // ctx fp16                8 MB
#define OFF_P16    (40 * MB)          // probs fp16 [bh,q,k]   128 MB
#define HEAP_BYTES (168 * MB)

__device__ char g_heap[HEAP_BYTES];

// ---------------------------------------------------------------------------
// PTX helpers (Ampere-compatible: ldmatrix / mma.sync / cp.async)
// ---------------------------------------------------------------------------
__device__ __forceinline__ uint32_t smem_u32(const void* p) {
    uint32_t a;
    asm("{ .reg .u64 t; cvta.to.shared.u64 t, %1; cvt.u32.u64 %0, t; }" : "=r"(a) : "l"(p));
    return a;
}
__device__ __forceinline__ void ldm_x4(uint32_t* r, uint32_t addr) {
    asm volatile("ldmatrix.sync.aligned.m8n8.x4.shared.b16 {%0,%1,%2,%3}, [%4];"
                 : "=r"(r[0]), "=r"(r[1]), "=r"(r[2]), "=r"(r[3]) : "r"(addr));
}
// fp16 MMA
__device__ __forceinline__ void mma16816h(float* c, const uint32_t* a,
                                          uint32_t b0, uint32_t b1) {
    asm volatile(
        "mma.sync.aligned.m16n8k16.row.col.f32.f16.f16.f32 "
        "{%0,%1,%2,%3}, {%4,%5,%6,%7}, {%8,%9}, {%0,%1,%2,%3};"
        : "+f"(c[0]), "+f"(c[1]), "+f"(c[2]), "+f"(c[3])
        : "r"(a[0]), "r"(a[1]), "r"(a[2]), "r"(a[3]), "r"(b0), "r"(b1));
}
__device__ __forceinline__ void cpa16(uint32_t saddr, const void* g) {
    asm volatile("cp.async.cg.shared.global [%0], [%1], 16;" :: "r"(saddr), "l"(g));
}
#define CP_COMMIT() asm volatile("cp.async.commit_group;" ::: "memory")
#define CP_WAIT(N)  asm volatile("cp.async.wait_group %0;" :: "n"(N) : "memory")

// packing helpers -------------------------------------------------------------
__device__ __forceinline__ uint32_t pack2u(unsigned short a, unsigned short b) {
    return (uint32_t)a | ((uint32_t)b << 16);
}

// ---------------------------------------------------------------------------
// Conversion kernels
// ---------------------------------------------------------------------------
__global__ void __launch_bounds__(256)
conv_h(const float* __restrict__ x, __half* __restrict__ o, int n4)
{
    int i = blockIdx.x * 256 + threadIdx.x;
    if (i >= n4) return;
    float4 v = reinterpret_cast<const float4*>(x)[i];
    __half2 a = __floats2half2_rn(v.x, v.y);
    __half2 b = __floats2half2_rn(v.z, v.w);
    reinterpret_cast<uint2*>(o)[i] =
        make_uint2(*reinterpret_cast<uint32_t*>(&a), *reinterpret_cast<uint32_t*>(&b));
}

// W [K,N] row-major -> W^T fp16 [N,K]
__global__ void __launch_bounds__(256)
convT_h(const float* __restrict__ W, __half* __restrict__ T, int K, int N)
{
    __shared__ float sm[32][33];
    int n0 = blockIdx.x * 32, k0 = blockIdx.y * 32;
    int tx = threadIdx.x, ty = threadIdx.y;       // (32, 8)
#pragma unroll
    for (int i = 0; i < 32; i += 8)
        sm[ty + i][tx] = W[(size_t)(k0 + ty + i) * N + n0 + tx];
    __syncthreads();
#pragma unroll
    for (int i = 0; i < 32; i += 8)
        T[(size_t)(n0 + ty + i) * K + k0 + tx] = __float2half_rn(sm[tx][ty + i]);
}

// ---------------------------------------------------------------------------
// fp16 GEMM via mma.sync:  D[m,n] = sum_k (Ahi [+ Alo])[m,k] * B[n,k]
// ALO=true: A is an fp16 hi/lo pair (2 MMA terms). ALO=false: 1 term.
// Block 128 x NT x 32, 512 threads, 16 warps (4M x 4N). 3-stage cp.async.
// STAGE keeps the proven 2A+2B geometry (unused regions are padding).
// Epilogue modes:
//   0: fp32 row-major (+bias,*scale)
//   1: head-split fp16 (+bias,*scale):  [b,h,t,d]
//   2: V^T fp16 (+bias):  [b, col, t]
// ---------------------------------------------------------------------------
#define APAD 80                 // 32 fp16 = 64B payload, padded to 80B
#define A_TERM (128 * APAD)     // 10240

template <int NT, bool ALO>
__global__ void __launch_bounds__(512)
gemm_fp16x2(const __half* __restrict__ Ahi, const __half* __restrict__ Alo,
            size_t aBS, int lda,
            const __half* __restrict__ Bp,
            size_t bBS, int bDiv, int ldb,
            int K,
            const float* __restrict__ bias, float scale,
            float* __restrict__ outF, size_t outBS, int ldOut,
            __half* __restrict__ outH,
            int mode)
{
    constexpr int B_TERM = NT * APAD;
    constexpr int STAGE  = 2 * A_TERM + 2 * B_TERM;   // proven geometry (pad)
    constexpr int W      = NT / 4;
    constexpr int NTB    = W / 16;

    extern __shared__ __align__(16) char smem[];
    const uint32_t sbase = smem_u32(smem);
    const int tid  = threadIdx.x;
    const int lane = tid & 31;
    const int wid  = tid >> 5;
    const int wm   = wid & 3;
    const int wn   = wid >> 2;
    const int m0   = blockIdx.y * 128;
    const int n0   = blockIdx.x * NT;
    const int z    = blockIdx.z;

    const __half* Ah = Ahi + (size_t)z * aBS;
    const __half* Al = ALO ? (Alo + (size_t)z * aBS) : nullptr;
    const __half* Bg = Bp + (size_t)(z / bDiv) * bBS;

    const int sRow = tid >> 2;
    const int slot = tid & 3;

    const uint32_t aLdmOff = (uint32_t)((wm * 32 + (lane & 15)) * APAD + (lane >> 4) * 16);
    const uint32_t bLdmOff = (uint32_t)((wn * W  + (lane & 15)) * APAD + (lane >> 4) * 16);

    float acc[2][NTB][2][4];
#pragma unroll
    for (int i = 0; i < 2; i++)
#pragma unroll
        for (int j = 0; j < NTB; j++)
#pragma unroll
            for (int k = 0; k < 2; k++)
#pragma unroll
                for (int l = 0; l < 4; l++) acc[i][j][k][l] = 0.0f;

    const int nc = K >> 5;

    auto stage_chunk = [&](int c) {
        const int k0 = c << 5;
        const uint32_t buf = sbase + (uint32_t)((c % 3) * STAGE);
        {
            size_t go = (size_t)(m0 + sRow) * lda + k0 + slot * 8;
            uint32_t so = buf + (uint32_t)(sRow * APAD + slot * 16);
            cpa16(so, Ah + go);
            if (ALO) cpa16(so + A_TERM, Al + go);
        }
        for (int r = sRow; r < NT; r += 128) {
            size_t go = (size_t)(n0 + r) * ldb + k0 + slot * 8;
            cpa16(buf + 2 * A_TERM + (uint32_t)(r * APAD + slot * 16), Bg + go);
        }
        CP_COMMIT();
    };

    stage_chunk(0);
    if (nc > 1) stage_chunk(1);

    for (int c = 0; c < nc; c++) {
        if (c + 2 < nc) { stage_chunk(c + 2); CP_WAIT(2); }
        else if (c + 1 < nc) { CP_WAIT(1); }
        else { CP_WAIT(0); }
        __syncthreads();

        const uint32_t cbuf = sbase + (uint32_t)((c % 3) * STAGE);
        const uint32_t aHiB = cbuf + aLdmOff;
        const uint32_t aLoB = cbuf + A_TERM + aLdmOff;
        const uint32_t bB   = cbuf + 2 * A_TERM + bLdmOff;

#pragma unroll
        for (int ks = 0; ks < 2; ks++) {
            const uint32_t ko = ks * 32;
            uint32_t ahi[2][4], alo[2][4], bb[NTB][4];
            ldm_x4(ahi[0], aHiB + ko);
            ldm_x4(ahi[1], aHiB + ko + 16 * APAD);
            if (ALO) {
                ldm_x4(alo[0], aLoB + ko);
                ldm_x4(alo[1], aLoB + ko + 16 * APAD);
            }
#pragma unroll
            for (int nt = 0; nt < NTB; nt++)
                ldm_x4(bb[nt], bB + ko + nt * 16 * APAD);
#pragma unroll
            for (int mt = 0; mt < 2; mt++)
#pragma unroll
                for (int nt = 0; nt < NTB; nt++)
#pragma unroll
                    for (int nh = 0; nh < 2; nh++) {
                        float* cc = acc[mt][nt][nh];
                        mma16816h(cc, ahi[mt], bb[nt][nh], bb[nt][nh + 2]);
                        if (ALO) mma16816h(cc, alo[mt], bb[nt][nh], bb[nt][nh + 2]);
                    }
        }
        __syncthreads();
    }

    // ---- epilogue ----
    const int rr = lane >> 2;
    const int cc2 = (lane & 3) << 1;
#pragma unroll
    for (int mt = 0; mt < 2; mt++)
#pragma unroll
        for (int nt = 0; nt < NTB; nt++)
#pragma unroll
            for (int nh = 0; nh < 2; nh++) {
                const float* cv = acc[mt][nt][nh];
                int gc = n0 + wn * W + nt * 16 + nh * 8 + cc2;
                float b0 = 0.f, b1 = 0.f;
                if (bias) { b0 = bias[gc]; b1 = bias[gc + 1]; }
#pragma unroll
                for (int half = 0; half < 2; half++) {
                    int gr = m0 + wm * 32 + mt * 16 + rr + half * 8;
                    float v0 = (cv[half * 2 + 0] + b0) * scale;
                    float v1 = (cv[half * 2 + 1] + b1) * scale;
                    if (mode == 0) {
                        float* p = outF + (size_t)z * outBS + (size_t)gr * ldOut + gc;
                        *reinterpret_cast<float2*>(p) = make_float2(v0, v1);
                    } else if (mode == 1) {
                        int bb = gr >> 10, t = gr & 1023;
                        int h = gc >> 6, d = gc & 63;
                        size_t idx = ((size_t)((bb << 4) + h) << 16) + ((size_t)t << 6) + d;
                        *reinterpret_cast<__half2*>(outH + idx) = __floats2half2_rn(v0, v1);
                    } else { // mode 2: V^T fp16 [b, col, t]
                        int bb = gr >> 10, t = gr & 1023;
                        size_t i0 = ((size_t)bb << 16) + ((size_t)gc << 10) + t;
                        outH[i0] = __float2half_rn(v0);
                        outH[i0 + 1024] = __float2half_rn(v1);
                    }
                }
            }
}

#define SMEM64  (3 * (2 * A_TERM + 2 * 64 * APAD))    // 92160
#define SMEM128 (3 * (2 * A_TERM + 2 * 128 * APAD))   // 122880

// ---------------------------------------------------------------------------
// Fused attention (fp16 single-product MMA): per CTA = (bh, 32 q rows).
//   S strip (32 x 1024 fp32) via fp16 MMA over 8 key tiles; in-smem softmax;
//   P fp16 in place + fp16 -> gmem; PV fp16 MMA; ctx fp16 -> gmem.
// smem: S strip 32x4112, Q 32x144, 2 KV buffers 18432 each = 173056 B.
// ---------------------------------------------------------------------------
#define SROWB  4112
#define FA_Q   131584
#define FA_KV0 (FA_Q + 4608)
#define FA_KVSZ 18432
#define FA_KV1 (FA_KV0 + FA_KVSZ)
#define FA_SMEM (FA_KV1 + FA_KVSZ)   // 173056

__global__ void __launch_bounds__(256)
fused_attn(const __half* __restrict__ Q_, const __half* __restrict__ K_,
           const __half* __restrict__ V_,
           __half* __restrict__ Pout, __half* __restrict__ Cout)
{
    extern __shared__ __align__(16) char smem[];
    const uint32_t sb = smem_u32(smem);
    const int tid = threadIdx.x, lane = tid & 31, wid = tid >> 5;
    const int q0 = blockIdx.x * 32;
    const int bh = blockIdx.y;
    const int b = bh >> 4, h = bh & 15;

    const __half* Qg = Q_ + ((size_t)bh << 16) + ((size_t)q0 << 6);
    const __half* Kg = K_ + ((size_t)bh << 16);
    const __half* Vg = V_ + ((size_t)b << 16);

    auto stageK = [&](int kt, uint32_t buf) {
#pragma unroll
        for (int i = 0; i < 4; i++) {
            int idx = tid + i * 256;
            int row = idx >> 3, slot = idx & 7;
            size_t go = ((size_t)(kt * 128 + row) << 6) + slot * 8;
            cpa16(buf + (uint32_t)(row * 144 + slot * 16), Kg + go);
        }
        CP_COMMIT();
    };
    auto stageV = [&](int vt, uint32_t buf) {
#pragma unroll
        for (int i = 0; i < 4; i++) {
            int idx = tid + i * 256;
            int row = idx >> 4, slot = idx & 15;
            size_t go = ((size_t)row << 10) + vt * 128 + slot * 8;
            cpa16(buf + (uint32_t)(row * 272 + slot * 16), Vg + go);
        }
        CP_COMMIT();
    };

    // stage Q (32x64 fp16) + first K tile in one group
    {
        int row = tid >> 3, slot = tid & 7;
        size_t go = ((size_t)row << 6) + slot * 8;
        cpa16(sb + FA_Q + (uint32_t)(row * 144 + slot * 16), Qg + go);
    }
    stageK(0, sb + FA_KV0);

    // ---------------- phase 1: S = Q K^T ----------------
    const int wm = wid & 1, wn = wid >> 1;       // 2M x 4N, warp tile 16x32
    const uint32_t aQ = sb + FA_Q + (uint32_t)((wm * 16 + (lane & 15)) * 144 + (lane >> 4) * 16);

    for (int kt = 0; kt < 8; kt++) {
        uint32_t buf = sb + ((kt & 1) ? FA_KV1 : FA_KV0);
        if (kt < 7) { stageK(kt + 1, sb + ((kt & 1) ? FA_KV0 : FA_KV1)); CP_WAIT(1); }
        else { CP_WAIT(0); }
        __syncthreads();

        float acc[2][2][4];
#pragma unroll
        for (int i = 0; i < 2; i++)
#pragma unroll
            for (int j = 0; j < 2; j++)
#pragma unroll
                for (int l = 0; l < 4; l++) acc[i][j][l] = 0.0f;

        const uint32_t bK = buf + (uint32_t)((wn * 32 + (lane & 15)) * 144 + (lane >> 4) * 16);
#pragma unroll
        for (int ks = 0; ks < 4; ks++) {
            const uint32_t ko = ks * 32;
            uint32_t a[4], b0[4], b1[4];
            ldm_x4(a, aQ + ko);
            ldm_x4(b0, bK + ko);
            ldm_x4(b1, bK + ko + 16 * 144);
#pragma unroll
            for (int nh = 0; nh < 2; nh++) {
                mma16816h(acc[0][nh], a, b0[nh], b0[nh + 2]);
                mma16816h(acc[1][nh], a, b1[nh], b1[nh + 2]);
            }
        }
        // write S tile to strip
        const int r0 = wm * 16 + (lane >> 2);
#pragma unroll
        for (int nt = 0; nt < 2; nt++)
#pragma unroll
            for (int nh = 0; nh < 2; nh++) {
                int col = kt * 128 + wn * 32 + nt * 16 + nh * 8 + ((lane & 3) << 1);
                *reinterpret_cast<float2*>(smem + r0 * SROWB + col * 4) =
                    make_float2(acc[nt][nh][0], acc[nt][nh][1]);
                *reinterpret_cast<float2*>(smem + (r0 + 8) * SROWB + col * 4) =
                    make_float2(acc[nt][nh][2], acc[nt][nh][3]);
            }
        __syncthreads();
    }

    // ---------------- phase 2: softmax + P fp16 (in place + gmem) ----------
#pragma unroll 1
    for (int rr = 0; rr < 4; rr++) {
        const int r = wid * 4 + rr;
        char* rowp = smem + r * SROWB;
        float2 v[16];
        float m = -1e30f;
#pragma unroll
        for (int i = 0; i < 16; i++) {
            v[i] = *reinterpret_cast<const float2*>(rowp + ((lane * 2 + 64 * i) << 2));
            m = fmaxf(m, fmaxf(v[i].x, v[i].y));
        }
#pragma unroll
        for (int o = 16; o; o >>= 1) m = fmaxf(m, __shfl_xor_sync(0xffffffffu, m, o));
        float s = 0.0f;
#pragma unroll
        for (int i = 0; i < 16; i++) {
            v[i].x = __expf(v[i].x - m);
            v[i].y = __expf(v[i].y - m);
            s += v[i].x + v[i].y;
        }
#pragma unroll
        for (int o = 16; o; o >>= 1) s += __shfl_xor_sync(0xffffffffu, s, o);
        const float inv = 1.0f / s;
        const size_t pbase = ((size_t)bh << 20) + ((size_t)(q0 + r) << 10);
        __syncwarp();
#pragma unroll
        for (int i = 0; i < 16; i++) {
            int c = lane * 2 + 64 * i;
            __half2 ph = __floats2half2_rn(v[i].x * inv, v[i].y * inv);
            *reinterpret_cast<__half2*>(Pout + pbase + c) = ph;
            *reinterpret_cast<__half2*>(rowp + c * 2) = ph;
        }
    }
    __syncthreads();

    // ---------------- phase 3: ctx = P V ----------------
    stageV(0, sb + FA_KV0);
    const int wm2 = wid & 1, wn2 = wid >> 1;     // 2M x 4N, warp tile 16x16
    const uint32_t aP = sb + (uint32_t)((wm2 * 16 + (lane & 15)) * SROWB + (lane >> 4) * 16);

    float acc2[2][4];
#pragma unroll
    for (int j = 0; j < 2; j++)
#pragma unroll
        for (int l = 0; l < 4; l++) acc2[j][l] = 0.0f;

    for (int vt = 0; vt < 8; vt++) {
        uint32_t buf = sb + ((vt & 1) ? FA_KV1 : FA_KV0);
        if (vt < 7) { stageV(vt + 1, sb + ((vt & 1) ? FA_KV0 : FA_KV1)); CP_WAIT(1); }
        else { CP_WAIT(0); }
        __syncthreads();

        const uint32_t bV = buf + (uint32_t)((wn2 * 16 + (lane & 15)) * 272 + (lane >> 4) * 16);
#pragma unroll
        for (int ks = 0; ks < 8; ks++) {
            const uint32_t ko = ks * 32;
            uint32_t a[4], bv[4];
            ldm_x4(a, aP + vt * 256 + ko);
            ldm_x4(bv, bV + ko);
            mma16816h(acc2[0], a, bv[0], bv[2]);
            mma16816h(acc2[1], a, bv[1], bv[3]);
        }
        __syncthreads();
    }

    // epilogue: ctx fp16 [(b*1024 + q)*1024 + h*64 + d]
    const int r0 = wm2 * 16 + (lane >> 2);
#pragma unroll
    for (int nh = 0; nh < 2; nh++) {
        int gc = wn2 * 16 + nh * 8 + ((lane & 3) << 1);
#pragma unroll
        for (int half = 0; half < 2; half++) {
            int gr = q0 + r0 + half * 8;
            float v0 = acc2[nh][half * 2 + 0];
            float v1 = acc2[nh][half * 2 + 1];
            size_t idx = (((size_t)(b << 10) + gr) << 10) + (h << 6) + gc;
            *reinterpret_cast<__half2*>(Cout + idx) = __floats2half2_rn(v0, v1);
        }
    }
}

// ---------------------------------------------------------------------------
// attn_mean[b,q,k] = (1/16) * sum_h P16
// ---------------------------------------------------------------------------
__global__ void __launch_bounds__(256)
attn_mean_kernel(const __half* __restrict__ P, float* __restrict__ out)
{
    size_t idx = (size_t)blockIdx.x * 256 + threadIdx.x;
    size_t e0 = idx << 2;
    int b = (int)(e0 >> 20);
    size_t rem = e0 & 1048575;
    float a0 = 0.f, a1 = 0.f, a2 = 0.f, a3 = 0.f;
#pragma unroll
    for (int h = 0; h < 16; h++) {
        const __half2* p = reinterpret_cast<const __half2*>(
            P + (((size_t)(b * 16 + h)) << 20) + rem);
        float2 x = __half22float2(p[0]);
        float2 y = __half22float2(p[1]);
        a0 += x.x; a1 += x.y; a2 += y.x; a3 += y.y;
    }
    const float s = 1.0f / 16.0f;
    *reinterpret_cast<float4*>(out + e0) = make_float4(a0 * s, a1 * s, a2 * s, a3 * s);
}

// ---------------------------------------------------------------------------
// kernel_launch. Inputs: x, Wq, bq, Wk, bk, Wv, bv, Wo, bo
// Output: out [4,1024,1024] fp32 then attn_mean [4,1024,1024] fp32
// ---------------------------------------------------------------------------
extern "C" void kernel_launch(void* const* d_in, const int* in_sizes, int n_in,
                              void* d_out, int out_size)
{
    (void)in_sizes; (void)n_in; (void)out_size;
    const float* x  = (const float*)d_in[0];
    const float* Wq = (const float*)d_in[1];
    const float* bq = (const float*)d_in[2];
    const float* Wk = (const float*)d_in[3];
    const float* bk = (const float*)d_in[4];
    const float* Wv = (const float*)d_in[5];
    const float* bv = (const float*)d_in[6];
    const float* Wo = (const float*)d_in[7];
    const float* bo = (const float*)d_in[8];
    float* out     = (float*)d_out;
    float* outAttn = out + 4194304;

    char* hp = nullptr;
    cudaGetSymbolAddress((void**)&hp, g_heap);
    __half* X16   = (__half*)(hp + OFF_X16);
    __half* WqT16 = (__half*)(hp + OFF_WQT16);
    __half* WkT16 = (__half*)(hp + OFF_WKT16);
    __half* WoT16 = (__half*)(hp + OFF_WOT16);
    __half* WvT16 = (__half*)(hp + OFF_WVT16);
    __half* Q16   = (__half*)(hp + OFF_Q16);
    __half* K16   = (__half*)(hp + OFF_K16);
    __half* VT16  = (__half*)(hp + OFF_VT16);
    __half* C16   = (__half*)(hp + OFF_C16);
    __half* P16   = (__half*)(hp + OFF_P16);

    cudaFuncSetAttribute(gemm_fp16x2<64, false>,  cudaFuncAttributeMaxDynamicSharedMemorySize, SMEM64);
    cudaFuncSetAttribute(gemm_fp16x2<128, false>, cudaFuncAttributeMaxDynamicSharedMemorySize, SMEM128);
    cudaFuncSetAttribute(fused_attn, cudaFuncAttributeMaxDynamicSharedMemorySize, FA_SMEM);

    // conversions
    conv_h<<<4096, 256>>>(x, X16, 1048576);
    convT_h<<<dim3(32, 32), dim3(32, 8)>>>(Wq, WqT16, 1024, 1024);
    convT_h<<<dim3(32, 32), dim3(32, 8)>>>(Wk, WkT16, 1024, 1024);
    convT_h<<<dim3(32, 32), dim3(32, 8)>>>(Wo, WoT16, 1024, 1024);
    convT_h<<<dim3(2, 32),  dim3(32, 8)>>>(Wv, WvT16, 1024, 64);

    // Q projection (scale 1/8 folded) -> head-split fp16   [1-term]
    gemm_fp16x2<128, false><<<dim3(8, 32, 1), 512, SMEM128>>>(
        X16, nullptr, 0, 1024, WqT16, 0, 1, 1024, 1024,
        bq, 0.125f, nullptr, 0, 0, Q16, 1);
    // K projection -> head-split fp16   [1-term]
    gemm_fp16x2<128, false><<<dim3(8, 32, 1), 512, SMEM128>>>(
        X16, nullptr, 0, 1024, WkT16, 0, 1, 1024, 1024,
        bk, 1.0f, nullptr, 0, 0, K16, 1);
    // V projection -> V^T fp16 [b,d,t]   [1-term]
    gemm_fp16x2<64, false><<<dim3(1, 32, 1), 512, SMEM64>>>(
        X16, nullptr, 0, 1024, WvT16, 0, 1, 1024, 1024,
        bv, 1.0f, nullptr, 0, 0, VT16, 2);
    // fused attention: S + softmax + P fp16 + ctx fp16
    fused_attn<<<dim3(32, 64), 256, FA_SMEM>>>(Q16, K16, VT16, P16, C16);
    // attn_mean
    attn_mean_kernel<<<4096, 256>>>(P16, outAttn);
    // out = ctx @ Wo + bo -> fp32 d_out   [1-term]
    gemm_fp16x2<128, false><<<dim3(8, 32, 1), 512, SMEM128>>>(
        C16, nullptr, 0, 1024, WoT16, 0, 1, 1024, 1024,
        bo, 1.0f, out, 0, 1024, nullptr, 0);
}

// round 14
// speedup vs baseline: 1.9878x; 1.0051x over previous
#include <cuda_runtime.h>
#include <cuda_bf16.h>
#include <cuda_fp16.h>
#include <cstdint>
#include <cstddef>

// Problem constants: B=4, T=1024, D=1024, H=16, DH=64
#define MB ((size_t)1 << 20)

// ---------------------------------------------------------------------------
// Static device heap (no runtime allocation). Offsets in bytes.
// ---------------------------------------------------------------------------
#define OFF_X16    (0 * MB)           // x fp16 [4096,1024]      8 MB
#define OFF_WQT16  (8 * MB)           // Wq^T fp16 [1024,1024]   2 MB
#define OFF_WKT16  (10 * MB)
#define OFF_WOT16  (12 * MB)
#define OFF_WVT16  (14 * MB)          // Wv^T fp16 [64,1024]   128 KB
#define OFF_Q16    (15 * MB)          // Q fp16 head-split       8 MB
#define OFF_K16    (23 * MB)
#define OFF_VT16   (31 * MB)          // V^T fp16 [b,d,t]      512 KB
#define OFF_C16    (32 * MB)          // ctx fp16                8 MB
#define OFF_P16    (40 * MB)          // probs fp16 [bh,q,k]   128 MB
#define HEAP_BYTES (168 * MB)

__device__ char g_heap[HEAP_BYTES];

// ---------------------------------------------------------------------------
// PTX helpers (Ampere-compatible: ldmatrix / mma.sync / cp.async)
// ---------------------------------------------------------------------------
__device__ __forceinline__ uint32_t smem_u32(const void* p) {
    uint32_t a;
    asm("{ .reg .u64 t; cvta.to.shared.u64 t, %1; cvt.u32.u64 %0, t; }" : "=r"(a) : "l"(p));
    return a;
}
__device__ __forceinline__ void ldm_x4(uint32_t* r, uint32_t addr) {
    asm volatile("ldmatrix.sync.aligned.m8n8.x4.shared.b16 {%0,%1,%2,%3}, [%4];"
                 : "=r"(r[0]), "=r"(r[1]), "=r"(r[2]), "=r"(r[3]) : "r"(addr));
}
// fp16 MMA
__device__ __forceinline__ void mma16816h(float* c, const uint32_t* a,
                                          uint32_t b0, uint32_t b1) {
    asm volatile(
        "mma.sync.aligned.m16n8k16.row.col.f32.f16.f16.f32 "
        "{%0,%1,%2,%3}, {%4,%5,%6,%7}, {%8,%9}, {%0,%1,%2,%3};"
        : "+f"(c[0]), "+f"(c[1]), "+f"(c[2]), "+f"(c[3])
        : "r"(a[0]), "r"(a[1]), "r"(a[2]), "r"(a[3]), "r"(b0), "r"(b1));
}
__device__ __forceinline__ void cpa16(uint32_t saddr, const void* g) {
    asm volatile("cp.async.cg.shared.global [%0], [%1], 16;" :: "r"(saddr), "l"(g));
}
#define CP_COMMIT() asm volatile("cp.async.commit_group;" ::: "memory")
#define CP_WAIT(N)  asm volatile("cp.async.wait_group %0;" :: "n"(N) : "memory")

// packing helpers -------------------------------------------------------------
__device__ __forceinline__ uint32_t pack2u(unsigned short a, unsigned short b) {
    return (uint32_t)a | ((uint32_t)b << 16);
}

// ---------------------------------------------------------------------------
// Conversion kernels
// ---------------------------------------------------------------------------
__global__ void __launch_bounds__(256)
conv_h(const float* __restrict__ x, __half* __restrict__ o, int n4)
{
    int i = blockIdx.x * 256 + threadIdx.x;
    if (i >= n4) return;
    float4 v = reinterpret_cast<const float4*>(x)[i];
    __half2 a = __floats2half2_rn(v.x, v.y);
    __half2 b = __floats2half2_rn(v.z, v.w);
    reinterpret_cast<uint2*>(o)[i] =
        make_uint2(*reinterpret_cast<uint32_t*>(&a), *reinterpret_cast<uint32_t*>(&b));
}

// W [K,N] row-major -> W^T fp16 [N,K]
__global__ void __launch_bounds__(256)
convT_h(const float* __restrict__ W, __half* __restrict__ T, int K, int N)
{
    __shared__ float sm[32][33];
    int n0 = blockIdx.x * 32, k0 = blockIdx.y * 32;
    int tx = threadIdx.x, ty = threadIdx.y;       // (32, 8)
#pragma unroll
    for (int i = 0; i < 32; i += 8)
        sm[ty + i][tx] = W[(size_t)(k0 + ty + i) * N + n0 + tx];
    __syncthreads();
#pragma unroll
    for (int i = 0; i < 32; i += 8)
        T[(size_t)(n0 + ty + i) * K + k0 + tx] = __float2half_rn(sm[tx][ty + i]);
}

// ---------------------------------------------------------------------------
// fp16 GEMM via mma.sync:  D[m,n] = sum_k A[m,k] * B[n,k]   (1-term fp16)
// Block 128 x NT x 32, 512 threads, 16 warps (4M x 4N). 3-stage cp.async.
// STAGE keeps the proven 2A+2B geometry (unused regions are padding).
// Epilogue modes:
//   0: fp32 row-major (+bias,*scale)
//   1: head-split fp16 (+bias,*scale):  [b,h,t,d]
//   2: V^T fp16 (+bias):  [b, col, t]
// ---------------------------------------------------------------------------
#define APAD 80                 // 32 fp16 = 64B payload, padded to 80B
#define A_TERM (128 * APAD)     // 10240

template <int NT>
__global__ void __launch_bounds__(512)
gemm_fp16(const __half* __restrict__ Ap,
          size_t aBS, int lda,
          const __half* __restrict__ Bp,
          size_t bBS, int bDiv, int ldb,
          int K,
          const float* __restrict__ bias, float scale,
          float* __restrict__ outF, size_t outBS, int ldOut,
          __half* __restrict__ outH,
          int mode)
{
    constexpr int B_TERM = NT * APAD;
    constexpr int STAGE  = 2 * A_TERM + 2 * B_TERM;   // proven geometry (pad)
    constexpr int W      = NT / 4;
    constexpr int NTB    = W / 16;

    extern __shared__ __align__(16) char smem[];
    const uint32_t sbase = smem_u32(smem);
    const int tid  = threadIdx.x;
    const int lane = tid & 31;
    const int wid  = tid >> 5;
    const int wm   = wid & 3;
    const int wn   = wid >> 2;
    const int m0   = blockIdx.y * 128;
    const int n0   = blockIdx.x * NT;
    const int z    = blockIdx.z;

    const __half* Ah = Ap + (size_t)z * aBS;
    const __half* Bg = Bp + (size_t)(z / bDiv) * bBS;

    const int sRow = tid >> 2;
    const int slot = tid & 3;

    const uint32_t aLdmOff = (uint32_t)((wm * 32 + (lane & 15)) * APAD + (lane >> 4) * 16);
    const uint32_t bLdmOff = (uint32_t)((wn * W  + (lane & 15)) * APAD + (lane >> 4) * 16);

    float acc[2][NTB][2][4];
#pragma unroll
    for (int i = 0; i < 2; i++)
#pragma unroll
        for (int j = 0; j < NTB; j++)
#pragma unroll
            for (int k = 0; k < 2; k++)
#pragma unroll
                for (int l = 0; l < 4; l++) acc[i][j][k][l] = 0.0f;

    const int nc = K >> 5;

    auto stage_chunk = [&](int c) {
        const int k0 = c << 5;
        const uint32_t buf = sbase + (uint32_t)((c % 3) * STAGE);
        {
            size_t go = (size_t)(m0 + sRow) * lda + k0 + slot * 8;
            cpa16(buf + (uint32_t)(sRow * APAD + slot * 16), Ah + go);
        }
        for (int r = sRow; r < NT; r += 128) {
            size_t go = (size_t)(n0 + r) * ldb + k0 + slot * 8;
            cpa16(buf + 2 * A_TERM + (uint32_t)(r * APAD + slot * 16), Bg + go);
        }
        CP_COMMIT();
    };

    stage_chunk(0);
    if (nc > 1) stage_chunk(1);

    for (int c = 0; c < nc; c++) {
        if (c + 2 < nc) { stage_chunk(c + 2); CP_WAIT(2); }
        else if (c + 1 < nc) { CP_WAIT(1); }
        else { CP_WAIT(0); }
        __syncthreads();

        const uint32_t cbuf = sbase + (uint32_t)((c % 3) * STAGE);
        const uint32_t aHiB = cbuf + aLdmOff;
        const uint32_t bB   = cbuf + 2 * A_TERM + bLdmOff;

#pragma unroll
        for (int ks = 0; ks < 2; ks++) {
            const uint32_t ko = ks * 32;
            uint32_t ahi[2][4], bb[NTB][4];
            ldm_x4(ahi[0], aHiB + ko);
            ldm_x4(ahi[1], aHiB + ko + 16 * APAD);
#pragma unroll
            for (int nt = 0; nt < NTB; nt++)
                ldm_x4(bb[nt], bB + ko + nt * 16 * APAD);
#pragma unroll
            for (int mt = 0; mt < 2; mt++)
#pragma unroll
                for (int nt = 0; nt < NTB; nt++)
#pragma unroll
                    for (int nh = 0; nh < 2; nh++)
                        mma16816h(acc[mt][nt][nh], ahi[mt], bb[nt][nh], bb[nt][nh + 2]);
        }
        __syncthreads();
    }

    // ---- epilogue ----
    const int rr = lane >> 2;
    const int cc2 = (lane & 3) << 1;
#pragma unroll
    for (int mt = 0; mt < 2; mt++)
#pragma unroll
        for (int nt = 0; nt < NTB; nt++)
#pragma unroll
            for (int nh = 0; nh < 2; nh++) {
                const float* cv = acc[mt][nt][nh];
                int gc = n0 + wn * W + nt * 16 + nh * 8 + cc2;
                float b0 = 0.f, b1 = 0.f;
                if (bias) { b0 = bias[gc]; b1 = bias[gc + 1]; }
#pragma unroll
                for (int half = 0; half < 2; half++) {
                    int gr = m0 + wm * 32 + mt * 16 + rr + half * 8;
                    float v0 = (cv[half * 2 + 0] + b0) * scale;
                    float v1 = (cv[half * 2 + 1] + b1) * scale;
                    if (mode == 0) {
                        float* p = outF + (size_t)z * outBS + (size_t)gr * ldOut + gc;
                        *reinterpret_cast<float2*>(p) = make_float2(v0, v1);
                    } else if (mode == 1) {
                        int bb = gr >> 10, t = gr & 1023;
                        int h = gc >> 6, d = gc & 63;
                        size_t idx = ((size_t)((bb << 4) + h) << 16) + ((size_t)t << 6) + d;
                        *reinterpret_cast<__half2*>(outH + idx) = __floats2half2_rn(v0, v1);
                    } else { // mode 2: V^T fp16 [b, col, t]
                        int bb = gr >> 10, t = gr & 1023;
                        size_t i0 = ((size_t)bb << 16) + ((size_t)gc << 10) + t;
                        outH[i0] = __float2half_rn(v0);
                        outH[i0 + 1024] = __float2half_rn(v1);
                    }
                }
            }
}

#define SMEM64  (3 * (2 * A_TERM + 2 * 64 * APAD))    // 92160
#define SMEM128 (3 * (2 * A_TERM + 2 * 128 * APAD))   // 122880

// ---------------------------------------------------------------------------
// Fused attention, 512 threads (16 warps): per CTA = (bh, 32 q rows).
//   Phase 1: S strip via fp16 MMA, 2M x 8N warp grid (warp tile 16x16).
//   stageV(0) hoisted before softmax (overlaps V0 fetch with softmax).
//   Phase 2: softmax, 2 rows/warp; P fp16 in place + gmem.
//   Phase 3: PV with K-dim split across warp halves + smem reduction.
// smem: S strip 32x4112, Q 32x144, 2 KV buffers 18432 each = 173056 B.
// ---------------------------------------------------------------------------
#define SROWB  4112
#define FA_Q   131584
#define FA_KV0 (FA_Q + 4608)
#define FA_KVSZ 18432
#define FA_KV1 (FA_KV0 + FA_KVSZ)
#define FA_SMEM (FA_KV1 + FA_KVSZ)   // 173056

__global__ void __launch_bounds__(512)
fused_attn(const __half* __restrict__ Q_, const __half* __restrict__ K_,
           const __half* __restrict__ V_,
           __half* __restrict__ Pout, __half* __restrict__ Cout)
{
    extern __shared__ __align__(16) char smem[];
    const uint32_t sb = smem_u32(smem);
    const int tid = threadIdx.x, lane = tid & 31, wid = tid >> 5;
    const int q0 = blockIdx.x * 32;
    const int bh = blockIdx.y;
    const int b = bh >> 4, h = bh & 15;

    const __half* Qg = Q_ + ((size_t)bh << 16) + ((size_t)q0 << 6);
    const __half* Kg = K_ + ((size_t)bh << 16);
    const __half* Vg = V_ + ((size_t)b << 16);

    auto stageK = [&](int kt, uint32_t buf) {
#pragma unroll
        for (int i = 0; i < 2; i++) {
            int idx = tid + i * 512;
            int row = idx >> 3, slot = idx & 7;
            size_t go = ((size_t)(kt * 128 + row) << 6) + slot * 8;
            cpa16(buf + (uint32_t)(row * 144 + slot * 16), Kg + go);
        }
        CP_COMMIT();
    };
    auto stageV = [&](int vt, uint32_t buf) {
#pragma unroll
        for (int i = 0; i < 2; i++) {
            int idx = tid + i * 512;
            int row = idx >> 4, slot = idx & 15;
            size_t go = ((size_t)row << 10) + vt * 128 + slot * 8;
            cpa16(buf + (uint32_t)(row * 272 + slot * 16), Vg + go);
        }
        CP_COMMIT();
    };

    // stage Q (32x64 fp16, 256 slots) + first K tile in one group
    if (tid < 256) {
        int row = tid >> 3, slot = tid & 7;
        size_t go = ((size_t)row << 6) + slot * 8;
        cpa16(sb + FA_Q + (uint32_t)(row * 144 + slot * 16), Qg + go);
    }
    stageK(0, sb + FA_KV0);

    // ---------------- phase 1: S = Q K^T  (2M x 8N, warp tile 16x16) -------
    const int wm = wid & 1, wn = wid >> 1;       // wn 0..7
    const uint32_t aQ = sb + FA_Q + (uint32_t)((wm * 16 + (lane & 15)) * 144 + (lane >> 4) * 16);

    for (int kt = 0; kt < 8; kt++) {
        uint32_t buf = sb + ((kt & 1) ? FA_KV1 : FA_KV0);
        if (kt < 7) { stageK(kt + 1, sb + ((kt & 1) ? FA_KV0 : FA_KV1)); CP_WAIT(1); }
        else { CP_WAIT(0); }
        __syncthreads();

        float acc[2][4];
#pragma unroll
        for (int j = 0; j < 2; j++)
#pragma unroll
            for (int l = 0; l < 4; l++) acc[j][l] = 0.0f;

        const uint32_t bK = buf + (uint32_t)((wn * 16 + (lane & 15)) * 144 + (lane >> 4) * 16);
#pragma unroll
        for (int ks = 0; ks < 4; ks++) {
            const uint32_t ko = ks * 32;
            uint32_t a[4], bb[4];
            ldm_x4(a, aQ + ko);
            ldm_x4(bb, bK + ko);
            mma16816h(acc[0], a, bb[0], bb[2]);
            mma16816h(acc[1], a, bb[1], bb[3]);
        }
        // write S tile to strip
        const int r0 = wm * 16 + (lane >> 2);
#pragma unroll
        for (int nh = 0; nh < 2; nh++) {
            int col = kt * 128 + wn * 16 + nh * 8 + ((lane & 3) << 1);
            *reinterpret_cast<float2*>(smem + r0 * SROWB + col * 4) =
                make_float2(acc[nh][0], acc[nh][1]);
            *reinterpret_cast<float2*>(smem + (r0 + 8) * SROWB + col * 4) =
                make_float2(acc[nh][2], acc[nh][3]);
        }
        __syncthreads();
    }

    // hoisted V0 stage: overlap fetch with softmax (KV0 free after kt=6)
    stageV(0, sb + FA_KV0);

    // ---------------- phase 2: softmax + P fp16 (2 rows/warp) --------------
#pragma unroll 1
    for (int rr = 0; rr < 2; rr++) {
        const int r = wid * 2 + rr;
        char* rowp = smem + r * SROWB;
        float2 v[16];
        float m = -1e30f;
#pragma unroll
        for (int i = 0; i < 16; i++) {
            v[i] = *reinterpret_cast<const float2*>(rowp + ((lane * 2 + 64 * i) << 2));
            m = fmaxf(m, fmaxf(v[i].x, v[i].y));
        }
#pragma unroll
        for (int o = 16; o; o >>= 1) m = fmaxf(m, __shfl_xor_sync(0xffffffffu, m, o));
        float s = 0.0f;
#pragma unroll
        for (int i = 0; i < 16; i++) {
            v[i].x = __expf(v[i].x - m);
            v[i].y = __expf(v[i].y - m);
            s += v[i].x + v[i].y;
        }
#pragma unroll
        for (int o = 16; o; o >>= 1) s += __shfl_xor_sync(0xffffffffu, s, o);
        const float inv = 1.0f / s;
        const size_t pbase = ((size_t)bh << 20) + ((size_t)(q0 + r) << 10);
        __syncwarp();
#pragma unroll
        for (int i = 0; i < 16; i++) {
            int c = lane * 2 + 64 * i;
            __half2 ph = __floats2half2_rn(v[i].x * inv, v[i].y * inv);
            *reinterpret_cast<__half2*>(Pout + pbase + c) = ph;
            *reinterpret_cast<__half2*>(rowp + c * 2) = ph;
        }
    }
    __syncthreads();

    // ---------------- phase 3: ctx = P V  (K-split across warp halves) -----
    const int kh  = wid >> 3;        // 0: ks 0-3, 1: ks 4-7
    const int w2  = wid & 7;
    const int wm2 = w2 & 1, wn2 = w2 >> 1;    // 2M x 4N, warp tile 16x16
    const uint32_t aP = sb + (uint32_t)((wm2 * 16 + (lane & 15)) * SROWB + (lane >> 4) * 16);

    float acc2[2][4];
#pragma unroll
    for (int j = 0; j < 2; j++)
#pragma unroll
        for (int l = 0; l < 4; l++) acc2[j][l] = 0.0f;

    for (int vt = 0; vt < 8; vt++) {
        uint32_t buf = sb + ((vt & 1) ? FA_KV1 : FA_KV0);
        if (vt < 7) { stageV(vt + 1, sb + ((vt & 1) ? FA_KV0 : FA_KV1)); CP_WAIT(1); }
        else { CP_WAIT(0); }
        __syncthreads();

        const uint32_t bV = buf + (uint32_t)((wn2 * 16 + (lane & 15)) * 272 + (lane >> 4) * 16);
#pragma unroll
        for (int ks = 0; ks < 4; ks++) {
            const uint32_t ko = (kh * 4 + ks) * 32;
            uint32_t a[4], bv[4];
            ldm_x4(a, aP + vt * 256 + ko);
            ldm_x4(bv, bV + ko);
            mma16816h(acc2[0], a, bv[0], bv[2]);
            mma16816h(acc2[1], a, bv[1], bv[3]);
        }
        __syncthreads();
    }

    // reduce kh=1 partials into kh=0 via smem scratch (S strip is done)
    if (kh == 1) {
        float4* sc = reinterpret_cast<float4*>(smem + (size_t)(w2 * 32 + lane) * 32);
        sc[0] = make_float4(acc2[0][0], acc2[0][1], acc2[0][2], acc2[0][3]);
        sc[1] = make_float4(acc2[1][0], acc2[1][1], acc2[1][2], acc2[1][3]);
    }
    __syncthreads();

    if (kh == 0) {
        const float4* sc = reinterpret_cast<const float4*>(smem + (size_t)(w2 * 32 + lane) * 32);
        float4 p0 = sc[0], p1 = sc[1];
        acc2[0][0] += p0.x; acc2[0][1] += p0.y; acc2[0][2] += p0.z; acc2[0][3] += p0.w;
        acc2[1][0] += p1.x; acc2[1][1] += p1.y; acc2[1][2] += p1.z; acc2[1][3] += p1.w;

        // epilogue: ctx fp16 [(b*1024 + q)*1024 + h*64 + d]
        const int r0 = wm2 * 16 + (lane >> 2);
#pragma unroll
        for (int nh = 0; nh < 2; nh++) {
            int gc = wn2 * 16 + nh * 8 + ((lane & 3) << 1);
#pragma unroll
            for (int half = 0; half < 2; half++) {
                int gr = q0 + r0 + half * 8;
                float v0 = acc2[nh][half * 2 + 0];
                float v1 = acc2[nh][half * 2 + 1];
                size_t idx = (((size_t)(b << 10) + gr) << 10) + (h << 6) + gc;
                *reinterpret_cast<__half2*>(Cout + idx) = __floats2half2_rn(v0, v1);
            }
        }
    }
}

// ---------------------------------------------------------------------------
// attn_mean[b,q,k] = (1/16) * sum_h P16
// ---------------------------------------------------------------------------
__global__ void __launch_bounds__(256)
attn_mean_kernel(const __half* __restrict__ P, float* __restrict__ out)
{
    size_t idx = (size_t)blockIdx.x * 256 + threadIdx.x;
    size_t e0 = idx << 2;
    int b = (int)(e0 >> 20);
    size_t rem = e0 & 1048575;
    float a0 = 0.f, a1 = 0.f, a2 = 0.f, a3 = 0.f;
#pragma unroll
    for (int h = 0; h < 16; h++) {
        const __half2* p = reinterpret_cast<const __half2*>(
            P + (((size_t)(b * 16 + h)) << 20) + rem);
        float2 x = __half22float2(p[0]);
        float2 y = __half22float2(p[1]);
        a0 += x.x; a1 += x.y; a2 += y.x; a3 += y.y;
    }
    const float s = 1.0f / 16.0f;
    *reinterpret_cast<float4*>(out + e0) = make_float4(a0 * s, a1 * s, a2 * s, a3 * s);
}

// ---------------------------------------------------------------------------
// kernel_launch. Inputs: x, Wq, bq, Wk, bk, Wv, bv, Wo, bo
// Output: out [4,1024,1024] fp32 then attn_mean [4,1024,1024] fp32
// ---------------------------------------------------------------------------
extern "C" void kernel_launch(void* const* d_in, const int* in_sizes, int n_in,
                              void* d_out, int out_size)
{
    (void)in_sizes; (void)n_in; (void)out_size;
    const float* x  = (const float*)d_in[0];
    const float* Wq = (const float*)d_in[1];
    const float* bq = (const float*)d_in[2];
    const float* Wk = (const float*)d_in[3];
    const float* bk = (const float*)d_in[4];
    const float* Wv = (const float*)d_in[5];
    const float* bv = (const float*)d_in[6];
    const float* Wo = (const float*)d_in[7];
    const float* bo = (const float*)d_in[8];
    float* out     = (float*)d_out;
    float* outAttn = out + 4194304;

    char* hp = nullptr;
    cudaGetSymbolAddress((void**)&hp, g_heap);
    __half* X16   = (__half*)(hp + OFF_X16);
    __half* WqT16 = (__half*)(hp + OFF_WQT16);
    __half* WkT16 = (__half*)(hp + OFF_WKT16);
    __half* WoT16 = (__half*)(hp + OFF_WOT16);
    __half* WvT16 = (__half*)(hp + OFF_WVT16);
    __half* Q16   = (__half*)(hp + OFF_Q16);
    __half* K16   = (__half*)(hp + OFF_K16);
    __half* VT16  = (__half*)(hp + OFF_VT16);
    __half* C16   = (__half*)(hp + OFF_C16);
    __half* P16   = (__half*)(hp + OFF_P16);

    cudaFuncSetAttribute(gemm_fp16<64>,  cudaFuncAttributeMaxDynamicSharedMemorySize, SMEM64);
    cudaFuncSetAttribute(gemm_fp16<128>, cudaFuncAttributeMaxDynamicSharedMemorySize, SMEM128);
    cudaFuncSetAttribute(fused_attn, cudaFuncAttributeMaxDynamicSharedMemorySize, FA_SMEM);

    // conversions
    conv_h<<<4096, 256>>>(x, X16, 1048576);
    convT_h<<<dim3(32, 32), dim3(32, 8)>>>(Wq, WqT16, 1024, 1024);
    convT_h<<<dim3(32, 32), dim3(32, 8)>>>(Wk, WkT16, 1024, 1024);
    convT_h<<<dim3(32, 32), dim3(32, 8)>>>(Wo, WoT16, 1024, 1024);
    convT_h<<<dim3(2, 32),  dim3(32, 8)>>>(Wv, WvT16, 1024, 64);

    // Q projection (scale 1/8 folded) -> head-split fp16
    gemm_fp16<128><<<dim3(8, 32, 1), 512, SMEM128>>>(
        X16, 0, 1024, WqT16, 0, 1, 1024, 1024,
        bq, 0.125f, nullptr, 0, 0, Q16, 1);
    // K projection -> head-split fp16
    gemm_fp16<128><<<dim3(8, 32, 1), 512, SMEM128>>>(
        X16, 0, 1024, WkT16, 0, 1, 1024, 1024,
        bk, 1.0f, nullptr, 0, 0, K16, 1);
    // V projection -> V^T fp16 [b,d,t]
    gemm_fp16<64><<<dim3(1, 32, 1), 512, SMEM64>>>(
        X16, 0, 1024, WvT16, 0, 1, 1024, 1024,
        bv, 1.0f, nullptr, 0, 0, VT16, 2);
    // fused attention: S + softmax + P fp16 + ctx fp16  (512 threads)
    fused_attn<<<dim3(32, 64), 512, FA_SMEM>>>(Q16, K16, VT16, P16, C16);
    // attn_mean
    attn_mean_kernel<<<4096, 256>>>(P16, outAttn);
    // out = ctx @ Wo + bo -> fp32 d_out
    gemm_fp16<128><<<dim3(8, 32, 1), 512, SMEM128>>>(
        C16, 0, 1024, WoT16, 0, 1, 1024, 1024,
        bo, 1.0f, out, 0, 1024, nullptr, 0);
}

// round 15
// speedup vs baseline: 2.0849x; 1.0488x over previous
#include <cuda_runtime.h>
#include <cuda_bf16.h>
#include <cuda_fp16.h>
#include <cstdint>
#include <cstddef>

// Problem constants: B=4, T=1024, D=1024, H=16, DH=64
#define MB ((size_t)1 << 20)

// ---------------------------------------------------------------------------
// Static device heap (no runtime allocation). Offsets in bytes.
// ---------------------------------------------------------------------------
#define OFF_X16    (0 * MB)           // x fp16 [4096,1024]      8 MB
#define OFF_WQT16  (8 * MB)           // Wq^T fp16 [1024,1024]   2 MB
#define OFF_WKT16  (10 * MB)
#define OFF_WOT16  (12 * MB)
#define OFF_WVT16  (14 * MB)          // Wv^T fp16 [64,1024]   128 KB
#define OFF_Q16    (15 * MB)          // Q fp16 head-split       8 MB
#define OFF_K16    (23 * MB)
#define OFF_VT16   (31 * MB)          // V^T fp16 [b,d,t]      512 KB
#define OFF_C16    (32 * MB)          // ctx fp16                8 MB
#define OFF_P16    (40 * MB)          // probs fp16 [bh,q,k]   128 MB
#define HEAP_BYTES (168 * MB)

__device__ char g_heap[HEAP_BYTES];

// ---------------------------------------------------------------------------
// Side stream + events, created ONCE at static init (before the harness's
// memory baseline). During capture we only record/wait events (capturable).
// ---------------------------------------------------------------------------
namespace {
struct SideCtx {
    cudaStream_t s = nullptr;
    cudaEvent_t eEntry = nullptr, eWo = nullptr, eP = nullptr, eJoin = nullptr;
    SideCtx() {
        cudaStreamCreateWithFlags(&s, cudaStreamNonBlocking);
        cudaEventCreateWithFlags(&eEntry, cudaEventDisableTiming);
        cudaEventCreateWithFlags(&eWo,    cudaEventDisableTiming);
        cudaEventCreateWithFlags(&eP,     cudaEventDisableTiming);
        cudaEventCreateWithFlags(&eJoin,  cudaEventDisableTiming);
    }
};
SideCtx g_side;   // constructed at load time
}

// ---------------------------------------------------------------------------
// PTX helpers (Ampere-compatible: ldmatrix / mma.sync / cp.async)
// ---------------------------------------------------------------------------
__device__ __forceinline__ uint32_t smem_u32(const void* p) {
    uint32_t a;
    asm("{ .reg .u64 t; cvta.to.shared.u64 t, %1; cvt.u32.u64 %0, t; }" : "=r"(a) : "l"(p));
    return a;
}
__device__ __forceinline__ void ldm_x4(uint32_t* r, uint32_t addr) {
    asm volatile("ldmatrix.sync.aligned.m8n8.x4.shared.b16 {%0,%1,%2,%3}, [%4];"
                 : "=r"(r[0]), "=r"(r[1]), "=r"(r[2]), "=r"(r[3]) : "r"(addr));
}
// fp16 MMA
__device__ __forceinline__ void mma16816h(float* c, const uint32_t* a,
                                          uint32_t b0, uint32_t b1) {
    asm volatile(
        "mma.sync.aligned.m16n8k16.row.col.f32.f16.f16.f32 "
        "{%0,%1,%2,%3}, {%4,%5,%6,%7}, {%8,%9}, {%0,%1,%2,%3};"
        : "+f"(c[0]), "+f"(c[1]), "+f"(c[2]), "+f"(c[3])
        : "r"(a[0]), "r"(a[1]), "r"(a[2]), "r"(a[3]), "r"(b0), "r"(b1));
}
__device__ __forceinline__ void cpa16(uint32_t saddr, const void* g) {
    asm volatile("cp.async.cg.shared.global [%0], [%1], 16;" :: "r"(saddr), "l"(g));
}
#define CP_COMMIT() asm volatile("cp.async.commit_group;" ::: "memory")
#define CP_WAIT(N)  asm volatile("cp.async.wait_group %0;" :: "n"(N) : "memory")

// ---------------------------------------------------------------------------
// Conversion kernels
// ---------------------------------------------------------------------------
__global__ void __launch_bounds__(256)
conv_h(const float* __restrict__ x, __half* __restrict__ o, int n4)
{
    int i = blockIdx.x * 256 + threadIdx.x;
    if (i >= n4) return;
    float4 v = reinterpret_cast<const float4*>(x)[i];
    __half2 a = __floats2half2_rn(v.x, v.y);
    __half2 b = __floats2half2_rn(v.z, v.w);
    reinterpret_cast<uint2*>(o)[i] =
        make_uint2(*reinterpret_cast<uint32_t*>(&a), *reinterpret_cast<uint32_t*>(&b));
}

// W [K,N] row-major -> W^T fp16 [N,K]
__global__ void __launch_bounds__(256)
convT_h(const float* __restrict__ W, __half* __restrict__ T, int K, int N)
{
    __shared__ float sm[32][33];
    int n0 = blockIdx.x * 32, k0 = blockIdx.y * 32;
    int tx = threadIdx.x, ty = threadIdx.y;       // (32, 8)
#pragma unroll
    for (int i = 0; i < 32; i += 8)
        sm[ty + i][tx] = W[(size_t)(k0 + ty + i) * N + n0 + tx];
    __syncthreads();
#pragma unroll
    for (int i = 0; i < 32; i += 8)
        T[(size_t)(n0 + ty + i) * K + k0 + tx] = __float2half_rn(sm[tx][ty + i]);
}

// ---------------------------------------------------------------------------
// fp16 GEMM via mma.sync:  D[m,n] = sum_k A[m,k] * B[n,k]   (1-term fp16)
// Block 128 x NT x 32, 512 threads, 16 warps (4M x 4N). 3-stage cp.async.
// STAGE keeps the proven 2A+2B geometry (unused regions are padding).
// Epilogue modes:
//   0: fp32 row-major (+bias,*scale)
//   1: head-split fp16 (+bias,*scale):  [b,h,t,d]
//   2: V^T fp16 (+bias):  [b, col, t]
// ---------------------------------------------------------------------------
#define APAD 80                 // 32 fp16 = 64B payload, padded to 80B
#define A_TERM (128 * APAD)     // 10240

template <int NT>
__global__ void __launch_bounds__(512)
gemm_fp16(const __half* __restrict__ Ap,
          size_t aBS, int lda,
          const __half* __restrict__ Bp,
          size_t bBS, int bDiv, int ldb,
          int K,
          const float* __restrict__ bias, float scale,
          float* __restrict__ outF, size_t outBS, int ldOut,
          __half* __restrict__ outH,
          int mode)
{
    constexpr int B_TERM = NT * APAD;
    constexpr int STAGE  = 2 * A_TERM + 2 * B_TERM;   // proven geometry (pad)
    constexpr int W      = NT / 4;
    constexpr int NTB    = W / 16;

    extern __shared__ __align__(16) char smem[];
    const uint32_t sbase = smem_u32(smem);
    const int tid  = threadIdx.x;
    const int lane = tid & 31;
    const int wid  = tid >> 5;
    const int wm   = wid & 3;
    const int wn   = wid >> 2;
    const int m0   = blockIdx.y * 128;
    const int n0   = blockIdx.x * NT;
    const int z    = blockIdx.z;

    const __half* Ah = Ap + (size_t)z * aBS;
    const __half* Bg = Bp + (size_t)(z / bDiv) * bBS;

    const int sRow = tid >> 2;
    const int slot = tid & 3;

    const uint32_t aLdmOff = (uint32_t)((wm * 32 + (lane & 15)) * APAD + (lane >> 4) * 16);
    const uint32_t bLdmOff = (uint32_t)((wn * W  + (lane & 15)) * APAD + (lane >> 4) * 16);

    float acc[2][NTB][2][4];
#pragma unroll
    for (int i = 0; i < 2; i++)
#pragma unroll
        for (int j = 0; j < NTB; j++)
#pragma unroll
            for (int k = 0; k < 2; k++)
#pragma unroll
                for (int l = 0; l < 4; l++) acc[i][j][k][l] = 0.0f;

    const int nc = K >> 5;

    auto stage_chunk = [&](int c) {
        const int k0 = c << 5;
        const uint32_t buf = sbase + (uint32_t)((c % 3) * STAGE);
        {
            size_t go = (size_t)(m0 + sRow) * lda + k0 + slot * 8;
            cpa16(buf + (uint32_t)(sRow * APAD + slot * 16), Ah + go);
        }
        for (int r = sRow; r < NT; r += 128) {
            size_t go = (size_t)(n0 + r) * ldb + k0 + slot * 8;
            cpa16(buf + 2 * A_TERM + (uint32_t)(r * APAD + slot * 16), Bg + go);
        }
        CP_COMMIT();
    };

    stage_chunk(0);
    if (nc > 1) stage_chunk(1);

    for (int c = 0; c < nc; c++) {
        if (c + 2 < nc) { stage_chunk(c + 2); CP_WAIT(2); }
        else if (c + 1 < nc) { CP_WAIT(1); }
        else { CP_WAIT(0); }
        __syncthreads();

        const uint32_t cbuf = sbase + (uint32_t)((c % 3) * STAGE);
        const uint32_t aHiB = cbuf + aLdmOff;
        const uint32_t bB   = cbuf + 2 * A_TERM + bLdmOff;

#pragma unroll
        for (int ks = 0; ks < 2; ks++) {
            const uint32_t ko = ks * 32;
            uint32_t ahi[2][4], bb[NTB][4];
            ldm_x4(ahi[0], aHiB + ko);
            ldm_x4(ahi[1], aHiB + ko + 16 * APAD);
#pragma unroll
            for (int nt = 0; nt < NTB; nt++)
                ldm_x4(bb[nt], bB + ko + nt * 16 * APAD);
#pragma unroll
            for (int mt = 0; mt < 2; mt++)
#pragma unroll
                for (int nt = 0; nt < NTB; nt++)
#pragma unroll
                    for (int nh = 0; nh < 2; nh++)
                        mma16816h(acc[mt][nt][nh], ahi[mt], bb[nt][nh], bb[nt][nh + 2]);
        }
        __syncthreads();
    }

    // ---- epilogue ----
    const int rr = lane >> 2;
    const int cc2 = (lane & 3) << 1;
#pragma unroll
    for (int mt = 0; mt < 2; mt++)
#pragma unroll
        for (int nt = 0; nt < NTB; nt++)
#pragma unroll
            for (int nh = 0; nh < 2; nh++) {
                const float* cv = acc[mt][nt][nh];
                int gc = n0 + wn * W + nt * 16 + nh * 8 + cc2;
                float b0 = 0.f, b1 = 0.f;
                if (bias) { b0 = bias[gc]; b1 = bias[gc + 1]; }
#pragma unroll
                for (int half = 0; half < 2; half++) {
                    int gr = m0 + wm * 32 + mt * 16 + rr + half * 8;
                    float v0 = (cv[half * 2 + 0] + b0) * scale;
                    float v1 = (cv[half * 2 + 1] + b1) * scale;
                    if (mode == 0) {
                        float* p = outF + (size_t)z * outBS + (size_t)gr * ldOut + gc;
                        *reinterpret_cast<float2*>(p) = make_float2(v0, v1);
                    } else if (mode == 1) {
                        int bb = gr >> 10, t = gr & 1023;
                        int h = gc >> 6, d = gc & 63;
                        size_t idx = ((size_t)((bb << 4) + h) << 16) + ((size_t)t << 6) + d;
                        *reinterpret_cast<__half2*>(outH + idx) = __floats2half2_rn(v0, v1);
                    } else { // mode 2: V^T fp16 [b, col, t]
                        int bb = gr >> 10, t = gr & 1023;
                        size_t i0 = ((size_t)bb << 16) + ((size_t)gc << 10) + t;
                        outH[i0] = __float2half_rn(v0);
                        outH[i0 + 1024] = __float2half_rn(v1);
                    }
                }
            }
}

#define SMEM64  (3 * (2 * A_TERM + 2 * 64 * APAD))    // 92160
#define SMEM128 (3 * (2 * A_TERM + 2 * 128 * APAD))   // 122880

// ---------------------------------------------------------------------------
// Fused attention, 512 threads (16 warps): per CTA = (bh, 32 q rows).
//   Phase 1: S strip via fp16 MMA, 2M x 8N warp grid (warp tile 16x16).
//   Phase 2: softmax, 2 rows/warp; P fp16 in place + gmem.
//   Phase 3: PV with K-dim split across warp halves + smem reduction.
// smem: S strip 32x4112, Q 32x144, 2 KV buffers 18432 each = 173056 B.
// ---------------------------------------------------------------------------
#define SROWB  4112
#define FA_Q   131584
#define FA_KV0 (FA_Q + 4608)
#define FA_KVSZ 18432
#define FA_KV1 (FA_KV0 + FA_KVSZ)
#define FA_SMEM (FA_KV1 + FA_KVSZ)   // 173056

__global__ void __launch_bounds__(512)
fused_attn(const __half* __restrict__ Q_, const __half* __restrict__ K_,
           const __half* __restrict__ V_,
           __half* __restrict__ Pout, __half* __restrict__ Cout)
{
    extern __shared__ __align__(16) char smem[];
    const uint32_t sb = smem_u32(smem);
    const int tid = threadIdx.x, lane = tid & 31, wid = tid >> 5;
    const int q0 = blockIdx.x * 32;
    const int bh = blockIdx.y;
    const int b = bh >> 4, h = bh & 15;

    const __half* Qg = Q_ + ((size_t)bh << 16) + ((size_t)q0 << 6);
    const __half* Kg = K_ + ((size_t)bh << 16);
    const __half* Vg = V_ + ((size_t)b << 16);

    auto stageK = [&](int kt, uint32_t buf) {
#pragma unroll
        for (int i = 0; i < 2; i++) {
            int idx = tid + i * 512;
            int row = idx >> 3, slot = idx & 7;
            size_t go = ((size_t)(kt * 128 + row) << 6) + slot * 8;
            cpa16(buf + (uint32_t)(row * 144 + slot * 16), Kg + go);
        }
        CP_COMMIT();
    };
    auto stageV = [&](int vt, uint32_t buf) {
#pragma unroll
        for (int i = 0; i < 2; i++) {
            int idx = tid + i * 512;
            int row = idx >> 4, slot = idx & 15;
            size_t go = ((size_t)row << 10) + vt * 128 + slot * 8;
            cpa16(buf + (uint32_t)(row * 272 + slot * 16), Vg + go);
        }
        CP_COMMIT();
    };

    // stage Q (32x64 fp16, 256 slots) + first K tile in one group
    if (tid < 256) {
        int row = tid >> 3, slot = tid & 7;
        size_t go = ((size_t)row << 6) + slot * 8;
        cpa16(sb + FA_Q + (uint32_t)(row * 144 + slot * 16), Qg + go);
    }
    stageK(0, sb + FA_KV0);

    // ---------------- phase 1: S = Q K^T  (2M x 8N, warp tile 16x16) -------
    const int wm = wid & 1, wn = wid >> 1;       // wn 0..7
    const uint32_t aQ = sb + FA_Q + (uint32_t)((wm * 16 + (lane & 15)) * 144 + (lane >> 4) * 16);

    for (int kt = 0; kt < 8; kt++) {
        uint32_t buf = sb + ((kt & 1) ? FA_KV1 : FA_KV0);
        if (kt < 7) { stageK(kt + 1, sb + ((kt & 1) ? FA_KV0 : FA_KV1)); CP_WAIT(1); }
        else { CP_WAIT(0); }
        __syncthreads();

        float acc[2][4];
#pragma unroll
        for (int j = 0; j < 2; j++)
#pragma unroll
            for (int l = 0; l < 4; l++) acc[j][l] = 0.0f;

        const uint32_t bK = buf + (uint32_t)((wn * 16 + (lane & 15)) * 144 + (lane >> 4) * 16);
#pragma unroll
        for (int ks = 0; ks < 4; ks++) {
            const uint32_t ko = ks * 32;
            uint32_t a[4], bb[4];
            ldm_x4(a, aQ + ko);
            ldm_x4(bb, bK + ko);
            mma16816h(acc[0], a, bb[0], bb[2]);
            mma16816h(acc[1], a, bb[1], bb[3]);
        }
        // write S tile to strip
        const int r0 = wm * 16 + (lane >> 2);
#pragma unroll
        for (int nh = 0; nh < 2; nh++) {
            int col = kt * 128 + wn * 16 + nh * 8 + ((lane & 3) << 1);
            *reinterpret_cast<float2*>(smem + r0 * SROWB + col * 4) =
                make_float2(acc[nh][0], acc[nh][1]);
            *reinterpret_cast<float2*>(smem + (r0 + 8) * SROWB + col * 4) =
                make_float2(acc[nh][2], acc[nh][3]);
        }
        __syncthreads();
    }

    // hoisted V0 stage: overlap fetch with softmax (KV0 free after kt=6)
    stageV(0, sb + FA_KV0);

    // ---------------- phase 2: softmax + P fp16 (2 rows/warp) --------------
#pragma unroll 1
    for (int rr = 0; rr < 2; rr++) {
        const int r = wid * 2 + rr;
        char* rowp = smem + r * SROWB;
        float2 v[16];
        float m = -1e30f;
#pragma unroll
        for (int i = 0; i < 16; i++) {
            v[i] = *reinterpret_cast<const float2*>(rowp + ((lane * 2 + 64 * i) << 2));
            m = fmaxf(m, fmaxf(v[i].x, v[i].y));
        }
#pragma unroll
        for (int o = 16; o; o >>= 1) m = fmaxf(m, __shfl_xor_sync(0xffffffffu, m, o));
        float s = 0.0f;
#pragma unroll
        for (int i = 0; i < 16; i++) {
            v[i].x = __expf(v[i].x - m);
            v[i].y = __expf(v[i].y - m);
            s += v[i].x + v[i].y;
        }
#pragma unroll
        for (int o = 16; o; o >>= 1) s += __shfl_xor_sync(0xffffffffu, s, o);
        const float inv = 1.0f / s;
        const size_t pbase = ((size_t)bh << 20) + ((size_t)(q0 + r) << 10);
        __syncwarp();
#pragma unroll
        for (int i = 0; i < 16; i++) {
            int c = lane * 2 + 64 * i;
            __half2 ph = __floats2half2_rn(v[i].x * inv, v[i].y * inv);
            *reinterpret_cast<__half2*>(Pout + pbase + c) = ph;
            *reinterpret_cast<__half2*>(rowp + c * 2) = ph;
        }
    }
    __syncthreads();

    // ---------------- phase 3: ctx = P V  (K-split across warp halves) -----
    const int kh  = wid >> 3;        // 0: ks 0-3, 1: ks 4-7
    const int w2  = wid & 7;
    const int wm2 = w2 & 1, wn2 = w2 >> 1;    // 2M x 4N, warp tile 16x16
    const uint32_t aP = sb + (uint32_t)((wm2 * 16 + (lane & 15)) * SROWB + (lane >> 4) * 16);

    float acc2[2][4];
#pragma unroll
    for (int j = 0; j < 2; j++)
#pragma unroll
        for (int l = 0; l < 4; l++) acc2[j][l] = 0.0f;

    for (int vt = 0; vt < 8; vt++) {
        uint32_t buf = sb + ((vt & 1) ? FA_KV1 : FA_KV0);
        if (vt < 7) { stageV(vt + 1, sb + ((vt & 1) ? FA_KV0 : FA_KV1)); CP_WAIT(1); }
        else { CP_WAIT(0); }
        __syncthreads();

        const uint32_t bV = buf + (uint32_t)((wn2 * 16 + (lane & 15)) * 272 + (lane >> 4) * 16);
#pragma unroll
        for (int ks = 0; ks < 4; ks++) {
            const uint32_t ko = (kh * 4 + ks) * 32;
            uint32_t a[4], bv[4];
            ldm_x4(a, aP + vt * 256 + ko);
            ldm_x4(bv, bV + ko);
            mma16816h(acc2[0], a, bv[0], bv[2]);
            mma16816h(acc2[1], a, bv[1], bv[3]);
        }
        __syncthreads();
    }

    // reduce kh=1 partials into kh=0 via smem scratch (S strip is done)
    if (kh == 1) {
        float4* sc = reinterpret_cast<float4*>(smem + (size_t)(w2 * 32 + lane) * 32);
        sc[0] = make_float4(acc2[0][0], acc2[0][1], acc2[0][2], acc2[0][3]);
        sc[1] = make_float4(acc2[1][0], acc2[1][1], acc2[1][2], acc2[1][3]);
    }
    __syncthreads();

    if (kh == 0) {
        const float4* sc = reinterpret_cast<const float4*>(smem + (size_t)(w2 * 32 + lane) * 32);
        float4 p0 = sc[0], p1 = sc[1];
        acc2[0][0] += p0.x; acc2[0][1] += p0.y; acc2[0][2] += p0.z; acc2[0][3] += p0.w;
        acc2[1][0] += p1.x; acc2[1][1] += p1.y; acc2[1][2] += p1.z; acc2[1][3] += p1.w;

        // epilogue: ctx fp16 [(b*1024 + q)*1024 + h*64 + d]
        const int r0 = wm2 * 16 + (lane >> 2);
#pragma unroll
        for (int nh = 0; nh < 2; nh++) {
            int gc = wn2 * 16 + nh * 8 + ((lane & 3) << 1);
#pragma unroll
            for (int half = 0; half < 2; half++) {
                int gr = q0 + r0 + half * 8;
                float v0 = acc2[nh][half * 2 + 0];
                float v1 = acc2[nh][half * 2 + 1];
                size_t idx = (((size_t)(b << 10) + gr) << 10) + (h << 6) + gc;
                *reinterpret_cast<__half2*>(Cout + idx) = __floats2half2_rn(v0, v1);
            }
        }
    }
}

// ---------------------------------------------------------------------------
// attn_mean[b,q,k] = (1/16) * sum_h P16
// ---------------------------------------------------------------------------
__global__ void __launch_bounds__(256)
attn_mean_kernel(const __half* __restrict__ P, float* __restrict__ out)
{
    size_t idx = (size_t)blockIdx.x * 256 + threadIdx.x;
    size_t e0 = idx << 2;
    int b = (int)(e0 >> 20);
    size_t rem = e0 & 1048575;
    float a0 = 0.f, a1 = 0.f, a2 = 0.f, a3 = 0.f;
#pragma unroll
    for (int h = 0; h < 16; h++) {
        const __half2* p = reinterpret_cast<const __half2*>(
            P + (((size_t)(b * 16 + h)) << 20) + rem);
        float2 x = __half22float2(p[0]);
        float2 y = __half22float2(p[1]);
        a0 += x.x; a1 += x.y; a2 += y.x; a3 += y.y;
    }
    const float s = 1.0f / 16.0f;
    *reinterpret_cast<float4*>(out + e0) = make_float4(a0 * s, a1 * s, a2 * s, a3 * s);
}

// ---------------------------------------------------------------------------
// kernel_launch. Inputs: x, Wq, bq, Wk, bk, Wv, bv, Wo, bo
// Output: out [4,1024,1024] fp32 then attn_mean [4,1024,1024] fp32
// DAG: side stream runs convT_Wo early and attn_mean parallel to out-proj.
// ---------------------------------------------------------------------------
extern "C" void kernel_launch(void* const* d_in, const int* in_sizes, int n_in,
                              void* d_out, int out_size)
{
    (void)in_sizes; (void)n_in; (void)out_size;
    const float* x  = (const float*)d_in[0];
    const float* Wq = (const float*)d_in[1];
    const float* bq = (const float*)d_in[2];
    const float* Wk = (const float*)d_in[3];
    const float* bk = (const float*)d_in[4];
    const float* Wv = (const float*)d_in[5];
    const float* bv = (const float*)d_in[6];
    const float* Wo = (const float*)d_in[7];
    const float* bo = (const float*)d_in[8];
    float* out     = (float*)d_out;
    float* outAttn = out + 4194304;

    char* hp = nullptr;
    cudaGetSymbolAddress((void**)&hp, g_heap);
    __half* X16   = (__half*)(hp + OFF_X16);
    __half* WqT16 = (__half*)(hp + OFF_WQT16);
    __half* WkT16 = (__half*)(hp + OFF_WKT16);
    __half* WoT16 = (__half*)(hp + OFF_WOT16);
    __half* WvT16 = (__half*)(hp + OFF_WVT16);
    __half* Q16   = (__half*)(hp + OFF_Q16);
    __half* K16   = (__half*)(hp + OFF_K16);
    __half* VT16  = (__half*)(hp + OFF_VT16);
    __half* C16   = (__half*)(hp + OFF_C16);
    __half* P16   = (__half*)(hp + OFF_P16);

    cudaFuncSetAttribute(gemm_fp16<64>,  cudaFuncAttributeMaxDynamicSharedMemorySize, SMEM64);
    cudaFuncSetAttribute(gemm_fp16<128>, cudaFuncAttributeMaxDynamicSharedMemorySize, SMEM128);
    cudaFuncSetAttribute(fused_attn, cudaFuncAttributeMaxDynamicSharedMemorySize, FA_SMEM);

    cudaStream_t ss = g_side.s;

    // ---- fork: side stream handles convT_Wo (needed only by out-proj) ----
    cudaEventRecord(g_side.eEntry, 0);
    cudaStreamWaitEvent(ss, g_side.eEntry, 0);
    convT_h<<<dim3(32, 32), dim3(32, 8), 0, ss>>>(Wo, WoT16, 1024, 1024);
    cudaEventRecord(g_side.eWo, ss);

    // ---- main chain ----
    conv_h<<<4096, 256>>>(x, X16, 1048576);
    convT_h<<<dim3(32, 32), dim3(32, 8)>>>(Wq, WqT16, 1024, 1024);
    convT_h<<<dim3(32, 32), dim3(32, 8)>>>(Wk, WkT16, 1024, 1024);
    convT_h<<<dim3(2, 32),  dim3(32, 8)>>>(Wv, WvT16, 1024, 64);

    // Q projection (scale 1/8 folded) -> head-split fp16
    gemm_fp16<128><<<dim3(8, 32, 1), 512, SMEM128>>>(
        X16, 0, 1024, WqT16, 0, 1, 1024, 1024,
        bq, 0.125f, nullptr, 0, 0, Q16, 1);
    // K projection -> head-split fp16
    gemm_fp16<128><<<dim3(8, 32, 1), 512, SMEM128>>>(
        X16, 0, 1024, WkT16, 0, 1, 1024, 1024,
        bk, 1.0f, nullptr, 0, 0, K16, 1);
    // V projection -> V^T fp16 [b,d,t]
    gemm_fp16<64><<<dim3(1, 32, 1), 512, SMEM64>>>(
        X16, 0, 1024, WvT16, 0, 1, 1024, 1024,
        bv, 1.0f, nullptr, 0, 0, VT16, 2);
    // fused attention: S + softmax + P fp16 + ctx fp16  (512 threads)
    fused_attn<<<dim3(32, 64), 512, FA_SMEM>>>(Q16, K16, VT16, P16, C16);

    // ---- fork after fused_attn: attn_mean on side stream (DRAM-bound),
    //      overlapping the out-projection (HMMA-bound) on the main stream ----
    cudaEventRecord(g_side.eP, 0);
    cudaStreamWaitEvent(ss, g_side.eP, 0);
    attn_mean_kernel<<<4096, 256, 0, ss>>>(P16, outAttn);
    cudaEventRecord(g_side.eJoin, ss);

    // out = ctx @ Wo + bo -> fp32 d_out  (waits for convT_Wo on side stream)
    cudaStreamWaitEvent(0, g_side.eWo, 0);
    gemm_fp16<128><<<dim3(8, 32, 1), 512, SMEM128>>>(
        C16, 0, 1024, WoT16, 0, 1, 1024, 1024,
        bo, 1.0f, out, 0, 1024, nullptr, 0);

    // ---- join side stream back into the main stream ----
    cudaStreamWaitEvent(0, g_side.eJoin, 0);
}

// round 16
// speedup vs baseline: 2.2122x; 1.0611x over previous
#include <cuda_runtime.h>
#include <cuda_bf16.h>
#include <cuda_fp16.h>
#include <cstdint>
#include <cstddef>

// Problem constants: B=4, T=1024, D=1024, H=16, DH=64
#define MB ((size_t)1 << 20)

// ---------------------------------------------------------------------------
// Static device heap (no runtime allocation). Offsets in bytes.
// NOTE: WqT/WkT adjacent (2 MB apart) and Q16/K16 adjacent (8 MB apart) so the
// combined QK projection can batch over z with simple strides.
// ---------------------------------------------------------------------------
#define OFF_X16    (0 * MB)           // x fp16 [4096,1024]      8 MB
#define OFF_WQT16  (8 * MB)           // Wq^T fp16 [1024,1024]   2 MB
#define OFF_WKT16  (10 * MB)
#define OFF_WOT16  (12 * MB)
#define OFF_WVT16  (14 * MB)          // Wv^T fp16 [64,1024]   128 KB
#define OFF_Q16    (15 * MB)          // Q fp16 head-split       8 MB
#define OFF_K16    (23 * MB)
#define OFF_VT16   (31 * MB)          // V^T fp16 [b,d,t]      512 KB
#define OFF_C16    (32 * MB)          // ctx fp16                8 MB
#define OFF_P16    (40 * MB)          // probs fp16 [bh,q,k]   128 MB
#define HEAP_BYTES (168 * MB)

__device__ char g_heap[HEAP_BYTES];

// ---------------------------------------------------------------------------
// Side streams + events, created ONCE at static init (before the harness's
// memory baseline). During capture we only record/wait events (capturable;
// all side work forks from and joins back to the capture-origin stream).
// ---------------------------------------------------------------------------
namespace {
struct SideCtx {
    cudaStream_t s1 = nullptr, s2 = nullptr;
    cudaEvent_t eEntry = nullptr, eQKw = nullptr, eX = nullptr, eWo = nullptr,
                eV = nullptr, eP = nullptr, eJoin = nullptr;
    SideCtx() {
        cudaStreamCreateWithFlags(&s1, cudaStreamNonBlocking);
        cudaStreamCreateWithFlags(&s2, cudaStreamNonBlocking);
        cudaEventCreateWithFlags(&eEntry, cudaEventDisableTiming);
        cudaEventCreateWithFlags(&eQKw,   cudaEventDisableTiming);
        cudaEventCreateWithFlags(&eX,     cudaEventDisableTiming);
        cudaEventCreateWithFlags(&eWo,    cudaEventDisableTiming);
        cudaEventCreateWithFlags(&eV,     cudaEventDisableTiming);
        cudaEventCreateWithFlags(&eP,     cudaEventDisableTiming);
        cudaEventCreateWithFlags(&eJoin,  cudaEventDisableTiming);
    }
};
SideCtx g_side;   // constructed at load time
}

// ---------------------------------------------------------------------------
// PTX helpers (Ampere-compatible: ldmatrix / mma.sync / cp.async)
// ---------------------------------------------------------------------------
__device__ __forceinline__ uint32_t smem_u32(const void* p) {
    uint32_t a;
    asm("{ .reg .u64 t; cvta.to.shared.u64 t, %1; cvt.u32.u64 %0, t; }" : "=r"(a) : "l"(p));
    return a;
}
__device__ __forceinline__ void ldm_x4(uint32_t* r, uint32_t addr) {
    asm volatile("ldmatrix.sync.aligned.m8n8.x4.shared.b16 {%0,%1,%2,%3}, [%4];"
                 : "=r"(r[0]), "=r"(r[1]), "=r"(r[2]), "=r"(r[3]) : "r"(addr));
}
// fp16 MMA
__device__ __forceinline__ void mma16816h(float* c, const uint32_t* a,
                                          uint32_t b0, uint32_t b1) {
    asm volatile(
        "mma.sync.aligned.m16n8k16.row.col.f32.f16.f16.f32 "
        "{%0,%1,%2,%3}, {%4,%5,%6,%7}, {%8,%9}, {%0,%1,%2,%3};"
        : "+f"(c[0]), "+f"(c[1]), "+f"(c[2]), "+f"(c[3])
        : "r"(a[0]), "r"(a[1]), "r"(a[2]), "r"(a[3]), "r"(b0), "r"(b1));
}
__device__ __forceinline__ void cpa16(uint32_t saddr, const void* g) {
    asm volatile("cp.async.cg.shared.global [%0], [%1], 16;" :: "r"(saddr), "l"(g));
}
#define CP_COMMIT() asm volatile("cp.async.commit_group;" ::: "memory")
#define CP_WAIT(N)  asm volatile("cp.async.wait_group %0;" :: "n"(N) : "memory")

// ---------------------------------------------------------------------------
// Conversion kernels
// ---------------------------------------------------------------------------
__global__ void __launch_bounds__(256)
conv_h(const float* __restrict__ x, __half* __restrict__ o, int n4)
{
    int i = blockIdx.x * 256 + threadIdx.x;
    if (i >= n4) return;
    float4 v = reinterpret_cast<const float4*>(x)[i];
    __half2 a = __floats2half2_rn(v.x, v.y);
    __half2 b = __floats2half2_rn(v.z, v.w);
    reinterpret_cast<uint2*>(o)[i] =
        make_uint2(*reinterpret_cast<uint32_t*>(&a), *reinterpret_cast<uint32_t*>(&b));
}

// W [K,N] row-major -> W^T fp16 [N,K]
__global__ void __launch_bounds__(256)
convT_h(const float* __restrict__ W, __half* __restrict__ T, int K, int N)
{
    __shared__ float sm[32][33];
    int n0 = blockIdx.x * 32, k0 = blockIdx.y * 32;
    int tx = threadIdx.x, ty = threadIdx.y;       // (32, 8)
#pragma unroll
    for (int i = 0; i < 32; i += 8)
        sm[ty + i][tx] = W[(size_t)(k0 + ty + i) * N + n0 + tx];
    __syncthreads();
#pragma unroll
    for (int i = 0; i < 32; i += 8)
        T[(size_t)(n0 + ty + i) * K + k0 + tx] = __float2half_rn(sm[tx][ty + i]);
}

// ---------------------------------------------------------------------------
// fp16 GEMM via mma.sync:  D[m,n] = sum_k A[m,k] * B[n,k]   (1-term fp16)
// Block 128 x NT x 32, 512 threads, 16 warps (4M x 4N). 3-stage cp.async.
// STAGE keeps the proven 2A+2B geometry (unused regions are padding).
// z-batched: A += z*aBS, B += (z/bDiv)*bBS, bias/scale selected by z,
// outH += z*outBS (modes 1/2).
// Epilogue modes:
//   0: fp32 row-major (+bias,*scale)
//   1: head-split fp16 (+bias,*scale):  [b,h,t,d]
//   2: V^T fp16 (+bias):  [b, col, t]
// ---------------------------------------------------------------------------
#define APAD 80                 // 32 fp16 = 64B payload, padded to 80B
#define A_TERM (128 * APAD)     // 10240

template <int NT>
__global__ void __launch_bounds__(512)
gemm_fp16(const __half* __restrict__ Ap,
          size_t aBS, int lda,
          const __half* __restrict__ Bp,
          size_t bBS, int bDiv, int ldb,
          int K,
          const float* __restrict__ bias, float scale,
          const float* __restrict__ biasB, float scaleB,
          float* __restrict__ outF, size_t outBS, int ldOut,
          __half* __restrict__ outH,
          int mode)
{
    constexpr int B_TERM = NT * APAD;
    constexpr int STAGE  = 2 * A_TERM + 2 * B_TERM;   // proven geometry (pad)
    constexpr int W      = NT / 4;
    constexpr int NTB    = W / 16;

    extern __shared__ __align__(16) char smem[];
    const uint32_t sbase = smem_u32(smem);
    const int tid  = threadIdx.x;
    const int lane = tid & 31;
    const int wid  = tid >> 5;
    const int wm   = wid & 3;
    const int wn   = wid >> 2;
    const int m0   = blockIdx.y * 128;
    const int n0   = blockIdx.x * NT;
    const int z    = blockIdx.z;

    const __half* Ah = Ap + (size_t)z * aBS;
    const __half* Bg = Bp + (size_t)(z / bDiv) * bBS;
    const float* biasZ = (z == 0) ? bias : biasB;
    const float scaleZ = (z == 0) ? scale : scaleB;
    __half* oH = outH + (size_t)z * outBS;

    const int sRow = tid >> 2;
    const int slot = tid & 3;

    const uint32_t aLdmOff = (uint32_t)((wm * 32 + (lane & 15)) * APAD + (lane >> 4) * 16);
    const uint32_t bLdmOff = (uint32_t)((wn * W  + (lane & 15)) * APAD + (lane >> 4) * 16);

    float acc[2][NTB][2][4];
#pragma unroll
    for (int i = 0; i < 2; i++)
#pragma unroll
        for (int j = 0; j < NTB; j++)
#pragma unroll
            for (int k = 0; k < 2; k++)
#pragma unroll
                for (int l = 0; l < 4; l++) acc[i][j][k][l] = 0.0f;

    const int nc = K >> 5;

    auto stage_chunk = [&](int c) {
        const int k0 = c << 5;
        const uint32_t buf = sbase + (uint32_t)((c % 3) * STAGE);
        {
            size_t go = (size_t)(m0 + sRow) * lda + k0 + slot * 8;
            cpa16(buf + (uint32_t)(sRow * APAD + slot * 16), Ah + go);
        }
        for (int r = sRow; r < NT; r += 128) {
            size_t go = (size_t)(n0 + r) * ldb + k0 + slot * 8;
            cpa16(buf + 2 * A_TERM + (uint32_t)(r * APAD + slot * 16), Bg + go);
        }
        CP_COMMIT();
    };

    stage_chunk(0);
    if (nc > 1) stage_chunk(1);

    for (int c = 0; c < nc; c++) {
        if (c + 2 < nc) { stage_chunk(c + 2); CP_WAIT(2); }
        else if (c + 1 < nc) { CP_WAIT(1); }
        else { CP_WAIT(0); }
        __syncthreads();

        const uint32_t cbuf = sbase + (uint32_t)((c % 3) * STAGE);
        const uint32_t aHiB = cbuf + aLdmOff;
        const uint32_t bB   = cbuf + 2 * A_TERM + bLdmOff;

#pragma unroll
        for (int ks = 0; ks < 2; ks++) {
            const uint32_t ko = ks * 32;
            uint32_t ahi[2][4], bb[NTB][4];
            ldm_x4(ahi[0], aHiB + ko);
            ldm_x4(ahi[1], aHiB + ko + 16 * APAD);
#pragma unroll
            for (int nt = 0; nt < NTB; nt++)
                ldm_x4(bb[nt], bB + ko + nt * 16 * APAD);
#pragma unroll
            for (int mt = 0; mt < 2; mt++)
#pragma unroll
                for (int nt = 0; nt < NTB; nt++)
#pragma unroll
                    for (int nh = 0; nh < 2; nh++)
                        mma16816h(acc[mt][nt][nh], ahi[mt], bb[nt][nh], bb[nt][nh + 2]);
        }
        __syncthreads();
    }

    // ---- epilogue ----
    const int rr = lane >> 2;
    const int cc2 = (lane & 3) << 1;
#pragma unroll
    for (int mt = 0; mt < 2; mt++)
#pragma unroll
        for (int nt = 0; nt < NTB; nt++)
#pragma unroll
            for (int nh = 0; nh < 2; nh++) {
                const float* cv = acc[mt][nt][nh];
                int gc = n0 + wn * W + nt * 16 + nh * 8 + cc2;
                float b0 = 0.f, b1 = 0.f;
                if (biasZ) { b0 = biasZ[gc]; b1 = biasZ[gc + 1]; }
#pragma unroll
                for (int half = 0; half < 2; half++) {
                    int gr = m0 + wm * 32 + mt * 16 + rr + half * 8;
                    float v0 = (cv[half * 2 + 0] + b0) * scaleZ;
                    float v1 = (cv[half * 2 + 1] + b1) * scaleZ;
                    if (mode == 0) {
                        float* p = outF + (size_t)gr * ldOut + gc;
                        *reinterpret_cast<float2*>(p) = make_float2(v0, v1);
                    } else if (mode == 1) {
                        int bb = gr >> 10, t = gr & 1023;
                        int h = gc >> 6, d = gc & 63;
                        size_t idx = ((size_t)((bb << 4) + h) << 16) + ((size_t)t << 6) + d;
                        *reinterpret_cast<__half2*>(oH + idx) = __floats2half2_rn(v0, v1);
                    } else { // mode 2: V^T fp16 [b, col, t]
                        int bb = gr >> 10, t = gr & 1023;
                        size_t i0 = ((size_t)bb << 16) + ((size_t)gc << 10) + t;
                        oH[i0] = __float2half_rn(v0);
                        oH[i0 + 1024] = __float2half_rn(v1);
                    }
                }
            }
}

#define SMEM64  (3 * (2 * A_TERM + 2 * 64 * APAD))    // 92160
#define SMEM128 (3 * (2 * A_TERM + 2 * 128 * APAD))   // 122880

// ---------------------------------------------------------------------------
// Fused attention, 512 threads (16 warps): per CTA = (bh, 32 q rows).
// (byte-identical to round 15)
// ---------------------------------------------------------------------------
#define SROWB  4112
#define FA_Q   131584
#define FA_KV0 (FA_Q + 4608)
#define FA_KVSZ 18432
#define FA_KV1 (FA_KV0 + FA_KVSZ)
#define FA_SMEM (FA_KV1 + FA_KVSZ)   // 173056

__global__ void __launch_bounds__(512)
fused_attn(const __half* __restrict__ Q_, const __half* __restrict__ K_,
           const __half* __restrict__ V_,
           __half* __restrict__ Pout, __half* __restrict__ Cout)
{
    extern __shared__ __align__(16) char smem[];
    const uint32_t sb = smem_u32(smem);
    const int tid = threadIdx.x, lane = tid & 31, wid = tid >> 5;
    const int q0 = blockIdx.x * 32;
    const int bh = blockIdx.y;
    const int b = bh >> 4, h = bh & 15;

    const __half* Qg = Q_ + ((size_t)bh << 16) + ((size_t)q0 << 6);
    const __half* Kg = K_ + ((size_t)bh << 16);
    const __half* Vg = V_ + ((size_t)b << 16);

    auto stageK = [&](int kt, uint32_t buf) {
#pragma unroll
        for (int i = 0; i < 2; i++) {
            int idx = tid + i * 512;
            int row = idx >> 3, slot = idx & 7;
            size_t go = ((size_t)(kt * 128 + row) << 6) + slot * 8;
            cpa16(buf + (uint32_t)(row * 144 + slot * 16), Kg + go);
        }
        CP_COMMIT();
    };
    auto stageV = [&](int vt, uint32_t buf) {
#pragma unroll
        for (int i = 0; i < 2; i++) {
            int idx = tid + i * 512;
            int row = idx >> 4, slot = idx & 15;
            size_t go = ((size_t)row << 10) + vt * 128 + slot * 8;
            cpa16(buf + (uint32_t)(row * 272 + slot * 16), Vg + go);
        }
        CP_COMMIT();
    };

    if (tid < 256) {
        int row = tid >> 3, slot = tid & 7;
        size_t go = ((size_t)row << 6) + slot * 8;
        cpa16(sb + FA_Q + (uint32_t)(row * 144 + slot * 16), Qg + go);
    }
    stageK(0, sb + FA_KV0);

    // ---------------- phase 1: S = Q K^T  (2M x 8N, warp tile 16x16) -------
    const int wm = wid & 1, wn = wid >> 1;
    const uint32_t aQ = sb + FA_Q + (uint32_t)((wm * 16 + (lane & 15)) * 144 + (lane >> 4) * 16);

    for (int kt = 0; kt < 8; kt++) {
        uint32_t buf = sb + ((kt & 1) ? FA_KV1 : FA_KV0);
        if (kt < 7) { stageK(kt + 1, sb + ((kt & 1) ? FA_KV0 : FA_KV1)); CP_WAIT(1); }
        else { CP_WAIT(0); }
        __syncthreads();

        float acc[2][4];
#pragma unroll
        for (int j = 0; j < 2; j++)
#pragma unroll
            for (int l = 0; l < 4; l++) acc[j][l] = 0.0f;

        const uint32_t bK = buf + (uint32_t)((wn * 16 + (lane & 15)) * 144 + (lane >> 4) * 16);
#pragma unroll
        for (int ks = 0; ks < 4; ks++) {
            const uint32_t ko = ks * 32;
            uint32_t a[4], bb[4];
            ldm_x4(a, aQ + ko);
            ldm_x4(bb, bK + ko);
            mma16816h(acc[0], a, bb[0], bb[2]);
            mma16816h(acc[1], a, bb[1], bb[3]);
        }
        const int r0 = wm * 16 + (lane >> 2);
#pragma unroll
        for (int nh = 0; nh < 2; nh++) {
            int col = kt * 128 + wn * 16 + nh * 8 + ((lane & 3) << 1);
            *reinterpret_cast<float2*>(smem + r0 * SROWB + col * 4) =
                make_float2(acc[nh][0], acc[nh][1]);
            *reinterpret_cast<float2*>(smem + (r0 + 8) * SROWB + col * 4) =
                make_float2(acc[nh][2], acc[nh][3]);
        }
        __syncthreads();
    }

    stageV(0, sb + FA_KV0);

    // ---------------- phase 2: softmax + P fp16 (2 rows/warp) --------------
#pragma unroll 1
    for (int rr = 0; rr < 2; rr++) {
        const int r = wid * 2 + rr;
        char* rowp = smem + r * SROWB;
        float2 v[16];
        float m = -1e30f;
#pragma unroll
        for (int i = 0; i < 16; i++) {
            v[i] = *reinterpret_cast<const float2*>(rowp + ((lane * 2 + 64 * i) << 2));
            m = fmaxf(m, fmaxf(v[i].x, v[i].y));
        }
#pragma unroll
        for (int o = 16; o; o >>= 1) m = fmaxf(m, __shfl_xor_sync(0xffffffffu, m, o));
        float s = 0.0f;
#pragma unroll
        for (int i = 0; i < 16; i++) {
            v[i].x = __expf(v[i].x - m);
            v[i].y = __expf(v[i].y - m);
            s += v[i].x + v[i].y;
        }
#pragma unroll
        for (int o = 16; o; o >>= 1) s += __shfl_xor_sync(0xffffffffu, s, o);
        const float inv = 1.0f / s;
        const size_t pbase = ((size_t)bh << 20) + ((size_t)(q0 + r) << 10);
        __syncwarp();
#pragma unroll
        for (int i = 0; i < 16; i++) {
            int c = lane * 2 + 64 * i;
            __half2 ph = __floats2half2_rn(v[i].x * inv, v[i].y * inv);
            *reinterpret_cast<__half2*>(Pout + pbase + c) = ph;
            *reinterpret_cast<__half2*>(rowp + c * 2) = ph;
        }
    }
    __syncthreads();

    // ---------------- phase 3: ctx = P V  (K-split across warp halves) -----
    const int kh  = wid >> 3;
    const int w2  = wid & 7;
    const int wm2 = w2 & 1, wn2 = w2 >> 1;
    const uint32_t aP = sb + (uint32_t)((wm2 * 16 + (lane & 15)) * SROWB + (lane >> 4) * 16);

    float acc2[2][4];
#pragma unroll
    for (int j = 0; j < 2; j++)
#pragma unroll
        for (int l = 0; l < 4; l++) acc2[j][l] = 0.0f;

    for (int vt = 0; vt < 8; vt++) {
        uint32_t buf = sb + ((vt & 1) ? FA_KV1 : FA_KV0);
        if (vt < 7) { stageV(vt + 1, sb + ((vt & 1) ? FA_KV0 : FA_KV1)); CP_WAIT(1); }
        else { CP_WAIT(0); }
        __syncthreads();

        const uint32_t bV = buf + (uint32_t)((wn2 * 16 + (lane & 15)) * 272 + (lane >> 4) * 16);
#pragma unroll
        for (int ks = 0; ks < 4; ks++) {
            const uint32_t ko = (kh * 4 + ks) * 32;
            uint32_t a[4], bv[4];
            ldm_x4(a, aP + vt * 256 + ko);
            ldm_x4(bv, bV + ko);
            mma16816h(acc2[0], a, bv[0], bv[2]);
            mma16816h(acc2[1], a, bv[1], bv[3]);
        }
        __syncthreads();
    }

    if (kh == 1) {
        float4* sc = reinterpret_cast<float4*>(smem + (size_t)(w2 * 32 + lane) * 32);
        sc[0] = make_float4(acc2[0][0], acc2[0][1], acc2[0][2], acc2[0][3]);
        sc[1] = make_float4(acc2[1][0], acc2[1][1], acc2[1][2], acc2[1][3]);
    }
    __syncthreads();

    if (kh == 0) {
        const float4* sc = reinterpret_cast<const float4*>(smem + (size_t)(w2 * 32 + lane) * 32);
        float4 p0 = sc[0], p1 = sc[1];
        acc2[0][0] += p0.x; acc2[0][1] += p0.y; acc2[0][2] += p0.z; acc2[0][3] += p0.w;
        acc2[1][0] += p1.x; acc2[1][1] += p1.y; acc2[1][2] += p1.z; acc2[1][3] += p1.w;

        const int r0 = wm2 * 16 + (lane >> 2);
#pragma unroll
        for (int nh = 0; nh < 2; nh++) {
            int gc = wn2 * 16 + nh * 8 + ((lane & 3) << 1);
#pragma unroll
            for (int half = 0; half < 2; half++) {
                int gr = q0 + r0 + half * 8;
                float v0 = acc2[nh][half * 2 + 0];
                float v1 = acc2[nh][half * 2 + 1];
                size_t idx = (((size_t)(b << 10) + gr) << 10) + (h << 6) + gc;
                *reinterpret_cast<__half2*>(Cout + idx) = __floats2half2_rn(v0, v1);
            }
        }
    }
}

// ---------------------------------------------------------------------------
// attn_mean[b,q,k] = (1/16) * sum_h P16
// ---------------------------------------------------------------------------
__global__ void __launch_bounds__(256)
attn_mean_kernel(const __half* __restrict__ P, float* __restrict__ out)
{
    size_t idx = (size_t)blockIdx.x * 256 + threadIdx.x;
    size_t e0 = idx << 2;
    int b = (int)(e0 >> 20);
    size_t rem = e0 & 1048575;
    float a0 = 0.f, a1 = 0.f, a2 = 0.f, a3 = 0.f;
#pragma unroll
    for (int h = 0; h < 16; h++) {
        const __half2* p = reinterpret_cast<const __half2*>(
            P + (((size_t)(b * 16 + h)) << 20) + rem);
        float2 x = __half22float2(p[0]);
        float2 y = __half22float2(p[1]);
        a0 += x.x; a1 += x.y; a2 += y.x; a3 += y.y;
    }
    const float s = 1.0f / 16.0f;
    *reinterpret_cast<float4*>(out + e0) = make_float4(a0 * s, a1 * s, a2 * s, a3 * s);
}

// ---------------------------------------------------------------------------
// kernel_launch. Inputs: x, Wq, bq, Wk, bk, Wv, bv, Wo, bo
// Output: out [4,1024,1024] fp32 then attn_mean [4,1024,1024] fp32
// DAG:
//   s1: convT_Wq, convT_Wk            (∥ conv_h)         -> eQKw
//   s2: convT_Wv, convT_Wo -> eWo; wait eX; V proj       -> eV
//   main: conv_h -> eX; wait eQKw; QK proj (z=2);
//         wait eV; fused_attn -> eP; wait eWo; out-proj; wait eJoin
//   s1: wait eP; attn_mean -> eJoin   (∥ out-proj)
// ---------------------------------------------------------------------------
extern "C" void kernel_launch(void* const* d_in, const int* in_sizes, int n_in,
                              void* d_out, int out_size)
{
    (void)in_sizes; (void)n_in; (void)out_size;
    const float* x  = (const float*)d_in[0];
    const float* Wq = (const float*)d_in[1];
    const float* bq = (const float*)d_in[2];
    const float* Wk = (const float*)d_in[3];
    const float* bk = (const float*)d_in[4];
    const float* Wv = (const float*)d_in[5];
    const float* bv = (const float*)d_in[6];
    const float* Wo = (const float*)d_in[7];
    const float* bo = (const float*)d_in[8];
    float* out     = (float*)d_out;
    float* outAttn = out + 4194304;

    char* hp = nullptr;
    cudaGetSymbolAddress((void**)&hp, g_heap);
    __half* X16   = (__half*)(hp + OFF_X16);
    __half* WqT16 = (__half*)(hp + OFF_WQT16);
    __half* WkT16 = (__half*)(hp + OFF_WKT16);
    __half* WoT16 = (__half*)(hp + OFF_WOT16);
    __half* WvT16 = (__half*)(hp + OFF_WVT16);
    __half* Q16   = (__half*)(hp + OFF_Q16);
    __half* K16   = (__half*)(hp + OFF_K16);
    __half* VT16  = (__half*)(hp + OFF_VT16);
    __half* C16   = (__half*)(hp + OFF_C16);
    __half* P16   = (__half*)(hp + OFF_P16);

    cudaFuncSetAttribute(gemm_fp16<64>,  cudaFuncAttributeMaxDynamicSharedMemorySize, SMEM64);
    cudaFuncSetAttribute(gemm_fp16<128>, cudaFuncAttributeMaxDynamicSharedMemorySize, SMEM128);
    cudaFuncSetAttribute(fused_attn, cudaFuncAttributeMaxDynamicSharedMemorySize, FA_SMEM);

    cudaStream_t s1 = g_side.s1, s2 = g_side.s2;

    // ---- fork ----
    cudaEventRecord(g_side.eEntry, 0);
    cudaStreamWaitEvent(s1, g_side.eEntry, 0);
    cudaStreamWaitEvent(s2, g_side.eEntry, 0);

    // s1: Wq/Wk transposes (needed by QK proj)
    convT_h<<<dim3(32, 32), dim3(32, 8), 0, s1>>>(Wq, WqT16, 1024, 1024);
    convT_h<<<dim3(32, 32), dim3(32, 8), 0, s1>>>(Wk, WkT16, 1024, 1024);
    cudaEventRecord(g_side.eQKw, s1);

    // s2: Wv/Wo transposes; Wo needed only by out-proj
    convT_h<<<dim3(2, 32),  dim3(32, 8), 0, s2>>>(Wv, WvT16, 1024, 64);
    convT_h<<<dim3(32, 32), dim3(32, 8), 0, s2>>>(Wo, WoT16, 1024, 1024);
    cudaEventRecord(g_side.eWo, s2);

    // main: x conversion
    conv_h<<<4096, 256>>>(x, X16, 1048576);
    cudaEventRecord(g_side.eX, 0);

    // s2: V projection (needs X16 + WvT16), overlaps QK proj on main
    cudaStreamWaitEvent(s2, g_side.eX, 0);
    gemm_fp16<64><<<dim3(1, 32, 1), 512, SMEM64, s2>>>(
        X16, 0, 1024, WvT16, 0, 1, 1024, 1024,
        bv, 1.0f, nullptr, 1.0f, nullptr, 0, 0, VT16, 2);
    cudaEventRecord(g_side.eV, s2);

    // main: combined Q+K projection (z=0 -> Q, scale 1/8; z=1 -> K)
    cudaStreamWaitEvent(0, g_side.eQKw, 0);
    gemm_fp16<128><<<dim3(8, 32, 2), 512, SMEM128>>>(
        X16, 0, 1024, WqT16, 1048576, 1, 1024, 1024,
        bq, 0.125f, bk, 1.0f, nullptr, 4194304, 0, Q16, 1);

    // main: fused attention (needs V from s2)
    cudaStreamWaitEvent(0, g_side.eV, 0);
    fused_attn<<<dim3(32, 64), 512, FA_SMEM>>>(Q16, K16, VT16, P16, C16);

    // fork after fused_attn: attn_mean on s1 ∥ out-proj on main
    cudaEventRecord(g_side.eP, 0);
    cudaStreamWaitEvent(s1, g_side.eP, 0);
    attn_mean_kernel<<<4096, 256, 0, s1>>>(P16, outAttn);
    cudaEventRecord(g_side.eJoin, s1);

    // main: out = ctx @ Wo + bo (needs WoT from s2)
    cudaStreamWaitEvent(0, g_side.eWo, 0);
    gemm_fp16<128><<<dim3(8, 32, 1), 512, SMEM128>>>(
        C16, 0, 1024, WoT16, 0, 1, 1024, 1024,
        bo, 1.0f, nullptr, 1.0f, out, 0, 1024, nullptr, 0);

    // ---- join ----
    cudaStreamWaitEvent(0, g_side.eJoin, 0);
}